// round 1
// baseline (speedup 1.0000x reference)
#include <cuda_runtime.h>
#include <math.h>

#define N_NODES 100000
#define N_EV    200000
#define D_MSGK  64
#define D_TIME  32
#define D_INF   96      /* effective GRU input dim (msg + time enc) */
#define D_MEMK  128
#define D_GNN   128
#define N_CLSK  64
#define N_SEDGE 1600000
#define N_TEDGE 1700000 /* static edges + N self loops */

/* ---------------- device scratch (no allocations allowed) ---------------- */
__device__ __align__(16) int      g_last[N_NODES];
__device__ __align__(16) float    g_mem [N_NODES * D_MEMK];
__device__ __align__(16) float    g_x   [N_NODES * D_GNN];
__device__ __align__(16) float    g_as  [N_NODES];
__device__ __align__(16) float    g_ad  [N_NODES];
__device__ __align__(16) unsigned g_menc[N_NODES];
__device__ __align__(16) float    g_den [N_NODES];
__device__ __align__(16) float    g_z   [N_NODES * D_GNN];
__device__ __align__(16) float    g_e   [N_TEDGE];

/* order-preserving float<->uint for atomicMax over arbitrary-sign floats */
__device__ __forceinline__ unsigned fenc(float f) {
    unsigned b = __float_as_uint(f);
    return (b & 0x80000000u) ? ~b : (b | 0x80000000u);
}
__device__ __forceinline__ float fdec(unsigned u) {
    return (u & 0x80000000u) ? __uint_as_float(u ^ 0x80000000u)
                             : __uint_as_float(~u);
}

/* ---------------- init ---------------- */
__global__ void k_init() {
    int i = blockIdx.x * blockDim.x + threadIdx.x;
    if (i < N_NODES * D_GNN) g_z[i] = 0.f;
    if (i < N_NODES) {
        g_last[i] = -1;
        g_menc[i] = 0x007FFFFFu;   /* fenc(-inf) */
        g_den[i]  = 0.f;
    }
}

/* ---------------- last event per node ---------------- */
__global__ void k_last(const int* __restrict__ src, const int* __restrict__ dst) {
    int i = blockIdx.x * blockDim.x + threadIdx.x;
    if (i >= N_EV) return;
    atomicMax(&g_last[src[i]], i);
    atomicMax(&g_last[dst[i]], i);
}

/* ---------------- fused GRU memory update ----------------
 * memory==0  =>  gi uses only W_ih[:,256:352], gh = b_hh, h = (1-z)*n.
 * W_sub (384x96) kept j-major in SMEM, persistent blocks, 8 nodes/block/iter.
 */
#define GRU_NB 8
__global__ void __launch_bounds__(256)
k_gru(const int* __restrict__ t, const float* __restrict__ msg,
      const float* __restrict__ w_ih, const float* __restrict__ b_ih,
      const float* __restrict__ b_hh,
      const float* __restrict__ time_w, const float* __restrict__ time_b) {
    extern __shared__ float sm[];
    float* Wsm = sm;                         /* [96][384], Wsm[j*384+k] */
    float* Vsm = sm + 96 * 384;              /* [GRU_NB][96] */
    int*   Fsm = (int*)(Vsm + GRU_NB * 96);  /* has-msg flags */
    const int tid = threadIdx.x;

    for (int idx = tid; idx < 384 * 96; idx += blockDim.x) {
        int k = idx / 96, j = idx - k * 96;
        Wsm[j * 384 + k] = w_ih[k * 352 + 256 + j];
    }
    const int k = tid & 127;
    const int g = tid >> 7;
    const float bi_r = b_ih[k],       bi_z = b_ih[128 + k], bi_n = b_ih[256 + k];
    const float bh_r = b_hh[k],       bh_z = b_hh[128 + k], bh_n = b_hh[256 + k];
    __syncthreads();

    const int nchunks = (N_NODES + GRU_NB - 1) / GRU_NB;
    for (int c = blockIdx.x; c < nchunks; c += gridDim.x) {
        const int base = c * GRU_NB;
        __syncthreads();
        for (int p = tid; p < GRU_NB * 96; p += blockDim.x) {
            int nb = p / 96, j = p - nb * 96;
            int node = base + nb;
            float v = 0.f;
            int le = (node < N_NODES) ? g_last[node] : -1;
            if (j == 0) Fsm[nb] = le;
            if (le >= 0) {
                if (j < 64) {
                    v = msg[(long)le * 64 + j];
                } else {
                    float tf = (float)t[le];
                    int jj = j - 64;
                    /* match JAX mul-then-add (no contraction); exact cos via fp64 */
                    float arg = __fadd_rn(__fmul_rn(tf, time_w[jj]), time_b[jj]);
                    v = (float)cos((double)arg);
                }
            }
            Vsm[nb * 96 + j] = v;
        }
        __syncthreads();

        float aR[4] = {0,0,0,0}, aZ[4] = {0,0,0,0}, aN[4] = {0,0,0,0};
#pragma unroll 8
        for (int j = 0; j < 96; j++) {
            float wr = Wsm[j * 384 + k];
            float wz = Wsm[j * 384 + 128 + k];
            float wn = Wsm[j * 384 + 256 + k];
#pragma unroll
            for (int u = 0; u < 4; u++) {
                float v = Vsm[(g * 4 + u) * 96 + j];
                aR[u] += wr * v; aZ[u] += wz * v; aN[u] += wn * v;
            }
        }
#pragma unroll
        for (int u = 0; u < 4; u++) {
            int nb = g * 4 + u;
            int node = base + nb;
            if (node >= N_NODES) continue;
            float h = 0.f;
            if (Fsm[nb] >= 0) {
                float r = 1.f / (1.f + expf(-(aR[u] + bi_r + bh_r)));
                float z = 1.f / (1.f + expf(-(aZ[u] + bi_z + bh_z)));
                float n = tanhf(aN[u] + bi_n + r * bh_n);
                h = (1.f - z) * n;
            }
            g_mem[(long)node * 128 + k] = h;
        }
    }
}

/* ---------------- GAT projection x = mem @ W^T ---------------- */
#define X_NB 4
__global__ void __launch_bounds__(256)
k_gatx(const float* __restrict__ gat_w) {
    extern __shared__ float sm[];
    float* Wsm = sm;              /* [128][128], Wsm[j*128+k] = W[k][j] */
    float* Vsm = sm + 128 * 128;  /* [X_NB][128] */
    const int tid = threadIdx.x;
    for (int idx = tid; idx < 128 * 128; idx += blockDim.x) {
        int kk = idx >> 7, j = idx & 127;
        Wsm[j * 128 + kk] = gat_w[kk * 128 + j];
    }
    const int k = tid & 127, g = tid >> 7;
    __syncthreads();

    const int nchunks = (N_NODES + X_NB - 1) / X_NB;
    for (int c = blockIdx.x; c < nchunks; c += gridDim.x) {
        const int base = c * X_NB;
        __syncthreads();
        for (int p = tid; p < X_NB * 128; p += blockDim.x) {
            int nb = p >> 7, j = p & 127;
            int node = base + nb;
            Vsm[p] = (node < N_NODES) ? g_mem[(long)node * 128 + j] : 0.f;
        }
        __syncthreads();
        float a0 = 0.f, a1 = 0.f;
#pragma unroll 8
        for (int j = 0; j < 128; j++) {
            float w = Wsm[j * 128 + k];
            a0 += w * Vsm[(g * 2) * 128 + j];
            a1 += w * Vsm[(g * 2 + 1) * 128 + j];
        }
        int n0 = base + g * 2, n1 = n0 + 1;
        if (n0 < N_NODES) g_x[(long)n0 * 128 + k] = a0;
        if (n1 < N_NODES) g_x[(long)n1 * 128 + k] = a1;
    }
}

/* ---------------- per-node attention scores ---------------- */
__global__ void k_attn(const float* __restrict__ att_src,
                       const float* __restrict__ att_dst) {
    int gt = blockIdx.x * blockDim.x + threadIdx.x;
    int node = gt >> 5, lane = gt & 31;
    if (node >= N_NODES) return;
    const float4 v  = ((const float4*)(g_x + (long)node * 128))[lane];
    const float4 ws = ((const float4*)att_src)[lane];
    const float4 wd = ((const float4*)att_dst)[lane];
    float s = v.x * ws.x + v.y * ws.y + v.z * ws.z + v.w * ws.w;
    float d = v.x * wd.x + v.y * wd.y + v.z * wd.z + v.w * wd.w;
#pragma unroll
    for (int o = 16; o; o >>= 1) {
        s += __shfl_xor_sync(0xFFFFFFFFu, s, o);
        d += __shfl_xor_sync(0xFFFFFFFFu, d, o);
    }
    if (lane == 0) { g_as[node] = s; g_ad[node] = d; }
}

/* ---------------- edge softmax: max ---------------- */
__global__ void k_emax(const int* __restrict__ es, const int* __restrict__ ed) {
    int i = blockIdx.x * blockDim.x + threadIdx.x;
    if (i >= N_TEDGE) return;
    int s, d;
    if (i < N_SEDGE) { s = es[i]; d = ed[i]; } else { s = d = i - N_SEDGE; }
    float e = g_as[s] + g_ad[d];
    e = (e > 0.f) ? e : 0.2f * e;      /* leaky_relu 0.2 */
    g_e[i] = e;
    atomicMax(&g_menc[d], fenc(e));
}

/* ---------------- edge softmax: exp + denominator ---------------- */
__global__ void k_eexp(const int* __restrict__ ed) {
    int i = blockIdx.x * blockDim.x + threadIdx.x;
    if (i >= N_TEDGE) return;
    int d = (i < N_SEDGE) ? ed[i] : i - N_SEDGE;
    float ex = expf(g_e[i] - fdec(g_menc[d]));
    g_e[i] = ex;
    atomicAdd(&g_den[d], ex);
}

/* ---------------- edge aggregation (warp/edge, float4 atomics) ---------------- */
__global__ void k_eagg(const int* __restrict__ es, const int* __restrict__ ed) {
    int gt = blockIdx.x * blockDim.x + threadIdx.x;
    int i = gt >> 5, lane = gt & 31;
    if (i >= N_TEDGE) return;
    int s, d;
    if (i < N_SEDGE) { s = es[i]; d = ed[i]; } else { s = d = i - N_SEDGE; }
    float alpha = g_e[i] / g_den[d];
    float4 v = ((const float4*)(g_x + (long)s * 128))[lane];
    float4 a = make_float4(alpha * v.x, alpha * v.y, alpha * v.z, alpha * v.w);
    atomicAdd(((float4*)(g_z + (long)d * 128)) + lane, a);  /* sm_90+ vector red */
}

/* ---------------- fused ReLU + classifier ---------------- */
#define C_NB 4
__global__ void __launch_bounds__(256)
k_cls(const float* __restrict__ cls_w, const float* __restrict__ cls_b,
      const float* __restrict__ gat_b, float* __restrict__ out) {
    extern __shared__ float sm[];
    float* Wsm = sm;             /* [128][64], Wsm[j*64+c] = W[c][j] */
    float* Vsm = sm + 128 * 64;  /* [C_NB][128] */
    const int tid = threadIdx.x;
    for (int idx = tid; idx < 64 * 128; idx += blockDim.x) {
        int cc = idx >> 7, j = idx & 127;
        Wsm[j * 64 + cc] = cls_w[idx];
    }
    const int c_ = tid & 63, g = tid >> 6;
    const float bias = cls_b[c_];
    __syncthreads();

    const int nchunks = (N_NODES + C_NB - 1) / C_NB;
    for (int ch = blockIdx.x; ch < nchunks; ch += gridDim.x) {
        const int base = ch * C_NB;
        __syncthreads();
        for (int p = tid; p < C_NB * 128; p += blockDim.x) {
            int nb = p >> 7, j = p & 127;
            int node = base + nb;
            float v = 0.f;
            if (node < N_NODES) {
                v = g_z[(long)node * 128 + j] + gat_b[j];
                v = (v > 0.f) ? v : 0.f;
            }
            Vsm[p] = v;
        }
        __syncthreads();
        float acc = bias;
#pragma unroll 8
        for (int j = 0; j < 128; j++)
            acc += Wsm[j * 64 + c_] * Vsm[g * 128 + j];
        int node = base + g;
        if (node < N_NODES) out[(long)node * 64 + c_] = acc;
    }
}

/* ---------------- launch ---------------- */
extern "C" void kernel_launch(void* const* d_in, const int* in_sizes, int n_in,
                              void* d_out, int out_size) {
    const int*   src    = (const int*)  d_in[0];
    const int*   dst    = (const int*)  d_in[1];
    const int*   t      = (const int*)  d_in[2];
    const float* msg    = (const float*)d_in[3];
    const int*   sei    = (const int*)  d_in[4];
    const float* time_w = (const float*)d_in[5];
    const float* time_b = (const float*)d_in[6];
    const float* w_ih   = (const float*)d_in[7];
    /* d_in[8] = gru_w_hh: provably unused (memory == 0 at update time) */
    const float* b_ih   = (const float*)d_in[9];
    const float* b_hh   = (const float*)d_in[10];
    const float* gat_w  = (const float*)d_in[11];
    const float* att_s  = (const float*)d_in[12];
    const float* att_d  = (const float*)d_in[13];
    const float* gat_b  = (const float*)d_in[14];
    const float* cls_w  = (const float*)d_in[15];
    const float* cls_b  = (const float*)d_in[16];
    float* out = (float*)d_out;
    const int* es = sei;
    const int* ed = sei + N_SEDGE;

    (void)in_sizes; (void)n_in; (void)out_size;

    k_init<<<(N_NODES * D_GNN + 255) / 256, 256>>>();
    k_last<<<(N_EV + 255) / 256, 256>>>(src, dst);

    {
        size_t smb = (size_t)(96 * 384 + GRU_NB * 96) * sizeof(float)
                   + GRU_NB * sizeof(int);
        cudaFuncSetAttribute(k_gru, cudaFuncAttributeMaxDynamicSharedMemorySize,
                             (int)smb);
        k_gru<<<148, 256, smb>>>(t, msg, w_ih, b_ih, b_hh, time_w, time_b);
    }
    {
        size_t smb = (size_t)(128 * 128 + X_NB * 128) * sizeof(float);
        cudaFuncSetAttribute(k_gatx, cudaFuncAttributeMaxDynamicSharedMemorySize,
                             (int)smb);
        k_gatx<<<444, 256, smb>>>(gat_w);
    }
    k_attn<<<(N_NODES * 32 + 255) / 256, 256>>>(att_s, att_d);
    k_emax<<<(N_TEDGE + 255) / 256, 256>>>(es, ed);
    k_eexp<<<(N_TEDGE + 255) / 256, 256>>>(ed);
    {
        long thr = (long)N_TEDGE * 32;
        k_eagg<<<(int)((thr + 255) / 256), 256>>>(es, ed);
    }
    {
        size_t smb = (size_t)(64 * 128 + C_NB * 128) * sizeof(float);
        k_cls<<<592, 256, smb>>>(cls_w, cls_b, gat_b, out);
    }
}

// round 3
// speedup vs baseline: 1.7040x; 1.7040x over previous
#include <cuda_runtime.h>
#include <math.h>

#define N_NODES 100000
#define N_EV    200000
#define N_SEDGE 1600000
#define SCHUNK  1024
#define SNBLK   ((N_NODES + SCHUNK - 1) / SCHUNK)

/* ---------------- device scratch (no allocations allowed) ---------------- */
__device__ __align__(16) int   g_last[N_NODES];
__device__ __align__(16) float g_mem [N_NODES * 128];
__device__ __align__(16) float g_x   [N_NODES * 128];
__device__ __align__(16) float g_as  [N_NODES];
__device__ __align__(16) float g_ad  [N_NODES];
__device__ __align__(16) float g_z   [N_NODES * 128];
__device__ __align__(16) int   g_cnt [N_NODES];
__device__ __align__(16) int   g_off [N_NODES];
__device__ __align__(16) int   g_pos [N_NODES];
__device__              int    g_part[SNBLK];
__device__ __align__(16) int   g_csrs[N_SEDGE];

typedef unsigned long long u64;
__device__ __forceinline__ u64 pk2(float a, float b) {
    u64 r; asm("mov.b64 %0,{%1,%2};" : "=l"(r) : "f"(a), "f"(b)); return r;
}
__device__ __forceinline__ void fma2(u64& d, u64 a, u64 b) {
    asm("fma.rn.f32x2 %0,%1,%2,%0;" : "+l"(d) : "l"(a), "l"(b));
}
__device__ __forceinline__ float2 up2(u64 v) {
    float2 r; asm("mov.b64 {%0,%1},%2;" : "=f"(r.x), "=f"(r.y) : "l"(v)); return r;
}

/* ---------------- init ---------------- */
__global__ void k_init() {
    int i = blockIdx.x * blockDim.x + threadIdx.x;
    if (i < N_NODES) { g_last[i] = -1; g_cnt[i] = 0; }
}

/* ---------------- last event per node ---------------- */
__global__ void k_last(const int* __restrict__ src, const int* __restrict__ dst) {
    int i = blockIdx.x * blockDim.x + threadIdx.x;
    if (i >= N_EV) return;
    atomicMax(&g_last[src[i]], i);
    atomicMax(&g_last[dst[i]], i);
}

/* ---------------- CSR build: count / scan / fill ---------------- */
__global__ void k_count(const int* __restrict__ ed) {
    int i = blockIdx.x * blockDim.x + threadIdx.x;
    if (i < N_SEDGE) atomicAdd(&g_cnt[ed[i]], 1);
}

__global__ void k_scanA() {  /* 256 thr, SNBLK blocks: per-chunk sums */
    int b = blockIdx.x, t = threadIdx.x;
    int base = b * SCHUNK + t * 4;
    int s = 0;
#pragma unroll
    for (int u = 0; u < 4; u++) { int i = base + u; if (i < N_NODES) s += g_cnt[i]; }
#pragma unroll
    for (int o = 16; o; o >>= 1) s += __shfl_xor_sync(0xFFFFFFFFu, s, o);
    __shared__ int ws[8];
    if ((t & 31) == 0) ws[t >> 5] = s;
    __syncthreads();
    if (t == 0) { int tot = 0; for (int w = 0; w < 8; w++) tot += ws[w]; g_part[b] = tot; }
}

__global__ void k_scanB() {  /* 1 block, 128 thr: exclusive scan of partials */
    int t = threadIdx.x;
    int v = (t < SNBLK) ? g_part[t] : 0;
    int lane = t & 31, wid = t >> 5;
    int inc = v;
#pragma unroll
    for (int o = 1; o < 32; o <<= 1) { int n = __shfl_up_sync(0xFFFFFFFFu, inc, o); if (lane >= o) inc += n; }
    __shared__ int ws[4];
    if (lane == 31) ws[wid] = inc;
    __syncthreads();
    if (t == 0) { int r = 0; for (int i = 0; i < 4; i++) { int x = ws[i]; ws[i] = r; r += x; } }
    __syncthreads();
    if (t < SNBLK) g_part[t] = inc - v + ws[wid];
}

__global__ void k_scanC() {  /* per-chunk exclusive scan + base -> g_off/g_pos */
    int b = blockIdx.x, t = threadIdx.x;
    int base = b * SCHUNK + t * 4;
    int c[4]; int s = 0;
#pragma unroll
    for (int u = 0; u < 4; u++) { int i = base + u; c[u] = (i < N_NODES) ? g_cnt[i] : 0; s += c[u]; }
    int lane = t & 31, wid = t >> 5;
    int inc = s;
#pragma unroll
    for (int o = 1; o < 32; o <<= 1) { int n = __shfl_up_sync(0xFFFFFFFFu, inc, o); if (lane >= o) inc += n; }
    __shared__ int ws[8];
    if (lane == 31) ws[wid] = inc;
    __syncthreads();
    if (t == 0) { int r = 0; for (int i = 0; i < 8; i++) { int x = ws[i]; ws[i] = r; r += x; } }
    __syncthreads();
    int off = g_part[b] + ws[wid] + inc - s;
#pragma unroll
    for (int u = 0; u < 4; u++) {
        int i = base + u;
        if (i < N_NODES) { g_off[i] = off; g_pos[i] = off; }
        off += c[u];
    }
}

__global__ void k_fill(const int* __restrict__ es, const int* __restrict__ ed) {
    int i = blockIdx.x * blockDim.x + threadIdx.x;
    if (i >= N_SEDGE) return;
    int pos = atomicAdd(&g_pos[ed[i]], 1);
    g_csrs[pos] = es[i];
}

/* ---------------- fused GRU memory update (FFMA2 register-tiled) ----------------
 * memory==0: gi uses only W_ih[:,256:352]; gh = b_hh; h = (1-z)*n.
 * Tile: 64 nodes. Block 256 = (tx 16) x (ty 16, 4 nodes each).
 * Thread: 3 gates x 2 halves x 4 k x 4 nodes, packed as f32x2 over k-pairs.
 */
#define GRU_WS 388
#define GRU_VS 68
__global__ void __launch_bounds__(256, 1)
k_gru(const int* __restrict__ t, const float* __restrict__ msg,
      const float* __restrict__ w_ih, const float* __restrict__ b_ih,
      const float* __restrict__ b_hh,
      const float* __restrict__ time_w, const float* __restrict__ time_b) {
    extern __shared__ float sm[];
    float* Wsm = sm;                      /* [96][388] j-major */
    float* Vsm = Wsm + 96 * GRU_WS;       /* [96][68]  j-major */
    float* Bsm = Vsm + 96 * GRU_VS;       /* br,bz,bin,bhn [4*128] */
    const int tid = threadIdx.x;

    for (int i = tid; i < 384 * 96; i += 256) {
        int k = i / 96, j = i - k * 96;
        Wsm[j * GRU_WS + k] = w_ih[k * 352 + 256 + j];
    }
    for (int k = tid; k < 128; k += 256) {
        Bsm[k]       = b_ih[k]       + b_hh[k];
        Bsm[128 + k] = b_ih[128 + k] + b_hh[128 + k];
        Bsm[256 + k] = b_ih[256 + k];
        Bsm[384 + k] = b_hh[256 + k];
    }
    const int tx = tid & 15, ty = tid >> 4;
    __syncthreads();

    const int nch = (N_NODES + 63) / 64;
    for (int c = blockIdx.x; c < nch; c += gridDim.x) {
        const int base = c * 64;
        __syncthreads();
        for (int p = tid; p < 64 * 96; p += 256) {
            int nl = p / 96, j = p - nl * 96;
            int node = base + nl;
            float v = 0.f;
            if (node < N_NODES) {
                int le = g_last[node];
                if (le >= 0) {
                    if (j < 64) v = msg[(long)le * 64 + j];
                    else {
                        int jj = j - 64;
                        float arg = __fadd_rn(__fmul_rn((float)t[le], time_w[jj]), time_b[jj]);
                        v = (float)cos((double)arg);
                    }
                }
            }
            Vsm[j * GRU_VS + nl] = v;
        }
        __syncthreads();

        u64 acc[3][2][2][4];
#pragma unroll
        for (int g = 0; g < 3; g++)
#pragma unroll
        for (int h = 0; h < 2; h++)
#pragma unroll
        for (int p = 0; p < 2; p++)
#pragma unroll
        for (int u = 0; u < 4; u++) acc[g][h][p][u] = 0ull;

#pragma unroll 2
        for (int j = 0; j < 96; j++) {
            float4 v4 = *(const float4*)&Vsm[j * GRU_VS + ty * 4];
            u64 vr[4] = { pk2(v4.x, v4.x), pk2(v4.y, v4.y),
                          pk2(v4.z, v4.z), pk2(v4.w, v4.w) };
#pragma unroll
            for (int g = 0; g < 3; g++)
#pragma unroll
            for (int h = 0; h < 2; h++) {
                ulonglong2 w = *(const ulonglong2*)&Wsm[j * GRU_WS + g * 128 + h * 64 + tx * 4];
#pragma unroll
                for (int u = 0; u < 4; u++) {
                    fma2(acc[g][h][0][u], w.x, vr[u]);
                    fma2(acc[g][h][1][u], w.y, vr[u]);
                }
            }
        }

#pragma unroll
        for (int u = 0; u < 4; u++) {
            int node = base + ty * 4 + u;
            if (node >= N_NODES) continue;
            bool has = (g_last[node] >= 0);
#pragma unroll
            for (int h = 0; h < 2; h++) {
                float o[4];
#pragma unroll
                for (int p = 0; p < 2; p++) {
                    float2 ar = up2(acc[0][h][p][u]);
                    float2 az = up2(acc[1][h][p][u]);
                    float2 an = up2(acc[2][h][p][u]);
#pragma unroll
                    for (int i = 0; i < 2; i++) {
                        int k = h * 64 + tx * 4 + p * 2 + i;
                        float aR = (i ? ar.y : ar.x) + Bsm[k];
                        float aZ = (i ? az.y : az.x) + Bsm[128 + k];
                        float aN = (i ? an.y : an.x);
                        float r = 1.f / (1.f + expf(-aR));
                        float z = 1.f / (1.f + expf(-aZ));
                        float n = tanhf(aN + Bsm[256 + k] + r * Bsm[384 + k]);
                        o[p * 2 + i] = has ? (1.f - z) * n : 0.f;
                    }
                }
                *(float4*)&g_mem[(long)node * 128 + h * 64 + tx * 4] =
                    make_float4(o[0], o[1], o[2], o[3]);
            }
        }
    }
}

/* ---------------- GAT projection x = mem @ W^T (FFMA2 register-tiled) ----------
 * Tile: 64 nodes. Block 128 = (tx 16: 8 k's) x (ty 8: 8 nodes).
 */
#define X_WS 132
#define X_VS 68
__global__ void __launch_bounds__(128)
k_gatx(const float* __restrict__ gat_w) {
    extern __shared__ float sm[];
    float* Wsm = sm;                  /* [128][132] j-major */
    float* Vsm = Wsm + 128 * X_WS;    /* [128][68]  j-major */
    const int tid = threadIdx.x;
    for (int i = tid; i < 128 * 128; i += 128) {
        int k = i >> 7, j = i & 127;
        Wsm[j * X_WS + k] = gat_w[k * 128 + j];
    }
    const int tx = tid & 15, ty = tid >> 4;
    __syncthreads();

    const int nch = (N_NODES + 63) / 64;
    for (int c = blockIdx.x; c < nch; c += gridDim.x) {
        const int base = c * 64;
        __syncthreads();
        for (int p = tid; p < 64 * 128; p += 128) {
            int nl = p >> 7, j = p & 127;
            int node = base + nl;
            Vsm[j * X_VS + nl] = (node < N_NODES) ? g_mem[(long)node * 128 + j] : 0.f;
        }
        __syncthreads();

        u64 acc[4][8];
#pragma unroll
        for (int q = 0; q < 4; q++)
#pragma unroll
        for (int u = 0; u < 8; u++) acc[q][u] = 0ull;

#pragma unroll 2
        for (int j = 0; j < 128; j++) {
            ulonglong2 w0 = *(const ulonglong2*)&Wsm[j * X_WS + tx * 4];
            ulonglong2 w1 = *(const ulonglong2*)&Wsm[j * X_WS + 64 + tx * 4];
            float4 va = *(const float4*)&Vsm[j * X_VS + ty * 8];
            float4 vb = *(const float4*)&Vsm[j * X_VS + ty * 8 + 4];
            u64 vr[8] = { pk2(va.x, va.x), pk2(va.y, va.y), pk2(va.z, va.z), pk2(va.w, va.w),
                          pk2(vb.x, vb.x), pk2(vb.y, vb.y), pk2(vb.z, vb.z), pk2(vb.w, vb.w) };
#pragma unroll
            for (int u = 0; u < 8; u++) {
                fma2(acc[0][u], w0.x, vr[u]);
                fma2(acc[1][u], w0.y, vr[u]);
                fma2(acc[2][u], w1.x, vr[u]);
                fma2(acc[3][u], w1.y, vr[u]);
            }
        }

#pragma unroll
        for (int u = 0; u < 8; u++) {
            int node = base + ty * 8 + u;
            if (node >= N_NODES) continue;
            float2 a = up2(acc[0][u]), b = up2(acc[1][u]);
            *(float4*)&g_x[(long)node * 128 + tx * 4] = make_float4(a.x, a.y, b.x, b.y);
            a = up2(acc[2][u]); b = up2(acc[3][u]);
            *(float4*)&g_x[(long)node * 128 + 64 + tx * 4] = make_float4(a.x, a.y, b.x, b.y);
        }
    }
}

/* ---------------- per-node attention scores ---------------- */
__global__ void k_attn(const float* __restrict__ att_src,
                       const float* __restrict__ att_dst) {
    int gt = blockIdx.x * blockDim.x + threadIdx.x;
    int node = gt >> 5, lane = gt & 31;
    if (node >= N_NODES) return;
    const float4 v  = ((const float4*)(g_x + (long)node * 128))[lane];
    const float4 ws = ((const float4*)att_src)[lane];
    const float4 wd = ((const float4*)att_dst)[lane];
    float s = v.x * ws.x + v.y * ws.y + v.z * ws.z + v.w * ws.w;
    float d = v.x * wd.x + v.y * wd.y + v.z * wd.z + v.w * wd.w;
#pragma unroll
    for (int o = 16; o; o >>= 1) {
        s += __shfl_xor_sync(0xFFFFFFFFu, s, o);
        d += __shfl_xor_sync(0xFFFFFFFFu, d, o);
    }
    if (lane == 0) { g_as[node] = s; g_ad[node] = d; }
}

/* ---------------- fused GAT softmax + aggregation: warp per node, no atomics */
__global__ void __launch_bounds__(256)
k_agg() {
    int gt = blockIdx.x * blockDim.x + threadIdx.x;
    int node = gt >> 5, lane = gt & 31;
    if (node >= N_NODES) return;
    const int start = g_off[node], end = g_pos[node];
    const float ad = g_ad[node];
    float e_self = g_as[node] + ad;
    e_self = (e_self > 0.f) ? e_self : 0.2f * e_self;

    /* pass 1: max (incl. self-loop) */
    float m = e_self;
    for (int i = start + lane; i < end; i += 32) {
        float e = g_as[g_csrs[i]] + ad;
        e = (e > 0.f) ? e : 0.2f * e;
        m = fmaxf(m, e);
    }
#pragma unroll
    for (int o = 16; o; o >>= 1) m = fmaxf(m, __shfl_xor_sync(0xFFFFFFFFu, m, o));

    /* self-loop contribution */
    const float w0 = expf(e_self - m);
    float4 xv = ((const float4*)(g_x + (long)node * 128))[lane];
    float4 acc = make_float4(w0 * xv.x, w0 * xv.y, w0 * xv.z, w0 * xv.w);
    float den_l = 0.f;

    /* pass 2: chunked exp + weighted gather */
    for (int b = start; b < end; b += 32) {
        int rem = end - b;
        int n = rem < 32 ? rem : 32;
        int  s_l = 0;
        float w_l = 0.f;
        if (lane < n) {
            s_l = g_csrs[b + lane];
            float e = g_as[s_l] + ad;
            e = (e > 0.f) ? e : 0.2f * e;
            w_l = expf(e - m);
            den_l += w_l;
        }
        for (int j = 0; j < n; j++) {
            int   s = __shfl_sync(0xFFFFFFFFu, s_l, j);
            float w = __shfl_sync(0xFFFFFFFFu, w_l, j);
            float4 v = ((const float4*)(g_x + (long)s * 128))[lane];
            acc.x += w * v.x; acc.y += w * v.y; acc.z += w * v.z; acc.w += w * v.w;
        }
    }
#pragma unroll
    for (int o = 16; o; o >>= 1) den_l += __shfl_xor_sync(0xFFFFFFFFu, den_l, o);
    float inv = 1.f / (den_l + w0);
    acc.x *= inv; acc.y *= inv; acc.z *= inv; acc.w *= inv;
    ((float4*)(g_z + (long)node * 128))[lane] = acc;
}

/* ---------------- fused ReLU + classifier (FFMA2, pack over node pairs) ------- */
#define C_WS 68
#define C_VS 68
__global__ void __launch_bounds__(128)
k_cls(const float* __restrict__ cls_w, const float* __restrict__ cls_b,
      const float* __restrict__ gat_b, float* __restrict__ out) {
    extern __shared__ float sm[];
    float* Wsm = sm;                  /* [128][68] j-major (64 outputs) */
    float* Vsm = Wsm + 128 * C_WS;    /* [128][68] j-major */
    const int tid = threadIdx.x;
    for (int i = tid; i < 64 * 128; i += 128) {
        int k = i >> 7, j = i & 127;
        Wsm[j * C_WS + k] = cls_w[k * 128 + j];
    }
    const int tx = tid & 15, ty = tid >> 4;
    const float4 bias = *(const float4*)&cls_b[tx * 4];
    __syncthreads();

    const int nch = (N_NODES + 63) / 64;
    for (int c = blockIdx.x; c < nch; c += gridDim.x) {
        const int base = c * 64;
        __syncthreads();
        for (int p = tid; p < 64 * 128; p += 128) {
            int nl = p >> 7, j = p & 127;
            int node = base + nl;
            float v = 0.f;
            if (node < N_NODES) {
                v = g_z[(long)node * 128 + j] + gat_b[j];
                v = (v > 0.f) ? v : 0.f;
            }
            Vsm[j * C_VS + nl] = v;
        }
        __syncthreads();

        u64 acc[4][4];
#pragma unroll
        for (int i = 0; i < 4; i++)
#pragma unroll
        for (int p = 0; p < 4; p++) acc[i][p] = 0ull;

#pragma unroll 2
        for (int j = 0; j < 128; j++) {
            float4 w = *(const float4*)&Wsm[j * C_WS + tx * 4];
            ulonglong2 va = *(const ulonglong2*)&Vsm[j * C_VS + ty * 8];
            ulonglong2 vb = *(const ulonglong2*)&Vsm[j * C_VS + ty * 8 + 4];
            u64 wr[4] = { pk2(w.x, w.x), pk2(w.y, w.y), pk2(w.z, w.z), pk2(w.w, w.w) };
#pragma unroll
            for (int i = 0; i < 4; i++) {
                fma2(acc[i][0], wr[i], va.x);
                fma2(acc[i][1], wr[i], va.y);
                fma2(acc[i][2], wr[i], vb.x);
                fma2(acc[i][3], wr[i], vb.y);
            }
        }

#pragma unroll
        for (int p = 0; p < 4; p++) {
            int n0 = base + ty * 8 + 2 * p, n1 = n0 + 1;
            float4 o0, o1;
            float2 f0 = up2(acc[0][p]), f1 = up2(acc[1][p]),
                   f2 = up2(acc[2][p]), f3 = up2(acc[3][p]);
            o0 = make_float4(f0.x + bias.x, f1.x + bias.y, f2.x + bias.z, f3.x + bias.w);
            o1 = make_float4(f0.y + bias.x, f1.y + bias.y, f2.y + bias.z, f3.y + bias.w);
            if (n0 < N_NODES) *(float4*)&out[(long)n0 * 64 + tx * 4] = o0;
            if (n1 < N_NODES) *(float4*)&out[(long)n1 * 64 + tx * 4] = o1;
        }
    }
}

/* ---------------- launch ---------------- */
extern "C" void kernel_launch(void* const* d_in, const int* in_sizes, int n_in,
                              void* d_out, int out_size) {
    const int*   src    = (const int*)  d_in[0];
    const int*   dst    = (const int*)  d_in[1];
    const int*   t      = (const int*)  d_in[2];
    const float* msg    = (const float*)d_in[3];
    const int*   sei    = (const int*)  d_in[4];
    const float* time_w = (const float*)d_in[5];
    const float* time_b = (const float*)d_in[6];
    const float* w_ih   = (const float*)d_in[7];
    /* d_in[8] = gru_w_hh: unused (memory == 0 at update time) */
    const float* b_ih   = (const float*)d_in[9];
    const float* b_hh   = (const float*)d_in[10];
    const float* gat_w  = (const float*)d_in[11];
    const float* att_s  = (const float*)d_in[12];
    const float* att_d  = (const float*)d_in[13];
    const float* gat_b  = (const float*)d_in[14];
    const float* cls_w  = (const float*)d_in[15];
    const float* cls_b  = (const float*)d_in[16];
    float* out = (float*)d_out;
    const int* es = sei;
    const int* ed = sei + N_SEDGE;
    (void)in_sizes; (void)n_in; (void)out_size;

    k_init <<<(N_NODES + 255) / 256, 256>>>();
    k_last <<<(N_EV + 255) / 256, 256>>>(src, dst);
    k_count<<<(N_SEDGE + 255) / 256, 256>>>(ed);
    k_scanA<<<SNBLK, 256>>>();
    k_scanB<<<1, 128>>>();
    k_scanC<<<SNBLK, 256>>>();
    k_fill <<<(N_SEDGE + 255) / 256, 256>>>(es, ed);

    {
        size_t smb = (size_t)(96 * GRU_WS + 96 * GRU_VS + 4 * 128) * sizeof(float);
        cudaFuncSetAttribute(k_gru, cudaFuncAttributeMaxDynamicSharedMemorySize, (int)smb);
        k_gru<<<148, 256, smb>>>(t, msg, w_ih, b_ih, b_hh, time_w, time_b);
    }
    {
        size_t smb = (size_t)(128 * X_WS + 128 * X_VS) * sizeof(float);
        cudaFuncSetAttribute(k_gatx, cudaFuncAttributeMaxDynamicSharedMemorySize, (int)smb);
        k_gatx<<<296, 128, smb>>>(gat_w);
    }
    k_attn<<<(N_NODES * 32 + 255) / 256, 256>>>(att_s, att_d);
    k_agg <<<(N_NODES * 32 + 255) / 256, 256>>>();
    {
        size_t smb = (size_t)(128 * C_WS + 128 * C_VS) * sizeof(float);
        cudaFuncSetAttribute(k_cls, cudaFuncAttributeMaxDynamicSharedMemorySize, (int)smb);
        k_cls<<<444, 128, smb>>>(cls_w, cls_b, gat_b, out);
    }
}

// round 5
// speedup vs baseline: 2.0990x; 1.2318x over previous
#include <cuda_runtime.h>
#include <math.h>

#define N_NODES 100000
#define N_EV    200000
#define N_SEDGE 1600000
#define SCHUNK  1024
#define SNBLK   ((N_NODES + SCHUNK - 1) / SCHUNK)

/* ---------------- device scratch (no allocations allowed) ---------------- */
__device__ __align__(16) int   g_last[N_NODES];
__device__ __align__(16) float g_mem [N_NODES * 128];
__device__ __align__(16) float g_x   [N_NODES * 128];
__device__ __align__(16) float g_as  [N_NODES];
__device__ __align__(16) float g_ad  [N_NODES];
__device__ __align__(16) float g_z   [N_NODES * 128];
__device__ __align__(16) int   g_cnt [N_NODES];
__device__ __align__(16) int   g_off [N_NODES];
__device__ __align__(16) int   g_pos [N_NODES];
__device__              int    g_part[SNBLK];
__device__ __align__(16) int   g_csrs[N_SEDGE];

/* ---------------- tf32 MMA helpers ---------------- */
__device__ __forceinline__ unsigned to_tf32(float f) {
    unsigned r; asm("cvt.rna.tf32.f32 %0,%1;" : "=r"(r) : "f"(f)); return r;
}
__device__ __forceinline__ void mma8(float (&c)[4], unsigned a0, unsigned a1,
                                     unsigned a2, unsigned a3,
                                     unsigned b0, unsigned b1) {
    asm("mma.sync.aligned.m16n8k8.row.col.f32.tf32.tf32.f32 "
        "{%0,%1,%2,%3},{%4,%5,%6,%7},{%8,%9},{%0,%1,%2,%3};"
        : "+f"(c[0]), "+f"(c[1]), "+f"(c[2]), "+f"(c[3])
        : "r"(a0), "r"(a1), "r"(a2), "r"(a3), "r"(b0), "r"(b1));
}

/* ---------------- init ---------------- */
__global__ void k_init() {
    int i = blockIdx.x * blockDim.x + threadIdx.x;
    if (i < N_NODES) { g_last[i] = -1; g_cnt[i] = 0; }
}

/* ---------------- last event per node ---------------- */
__global__ void k_last(const int* __restrict__ src, const int* __restrict__ dst) {
    int i = blockIdx.x * blockDim.x + threadIdx.x;
    if (i >= N_EV) return;
    atomicMax(&g_last[src[i]], i);
    atomicMax(&g_last[dst[i]], i);
}

/* ---------------- CSR build: count / scan / fill ---------------- */
__global__ void k_count(const int* __restrict__ ed) {
    int i = blockIdx.x * blockDim.x + threadIdx.x;
    if (i < N_SEDGE) atomicAdd(&g_cnt[ed[i]], 1);
}

__global__ void k_scanA() {
    int b = blockIdx.x, t = threadIdx.x;
    int base = b * SCHUNK + t * 4;
    int s = 0;
#pragma unroll
    for (int u = 0; u < 4; u++) { int i = base + u; if (i < N_NODES) s += g_cnt[i]; }
#pragma unroll
    for (int o = 16; o; o >>= 1) s += __shfl_xor_sync(0xFFFFFFFFu, s, o);
    __shared__ int ws[8];
    if ((t & 31) == 0) ws[t >> 5] = s;
    __syncthreads();
    if (t == 0) { int tot = 0; for (int w = 0; w < 8; w++) tot += ws[w]; g_part[b] = tot; }
}

__global__ void k_scanB() {
    int t = threadIdx.x;
    int v = (t < SNBLK) ? g_part[t] : 0;
    int lane = t & 31, wid = t >> 5;
    int inc = v;
#pragma unroll
    for (int o = 1; o < 32; o <<= 1) { int n = __shfl_up_sync(0xFFFFFFFFu, inc, o); if (lane >= o) inc += n; }
    __shared__ int ws[4];
    if (lane == 31) ws[wid] = inc;
    __syncthreads();
    if (t == 0) { int r = 0; for (int i = 0; i < 4; i++) { int x = ws[i]; ws[i] = r; r += x; } }
    __syncthreads();
    if (t < SNBLK) g_part[t] = inc - v + ws[wid];
}

__global__ void k_scanC() {
    int b = blockIdx.x, t = threadIdx.x;
    int base = b * SCHUNK + t * 4;
    int c[4]; int s = 0;
#pragma unroll
    for (int u = 0; u < 4; u++) { int i = base + u; c[u] = (i < N_NODES) ? g_cnt[i] : 0; s += c[u]; }
    int lane = t & 31, wid = t >> 5;
    int inc = s;
#pragma unroll
    for (int o = 1; o < 32; o <<= 1) { int n = __shfl_up_sync(0xFFFFFFFFu, inc, o); if (lane >= o) inc += n; }
    __shared__ int ws[8];
    if (lane == 31) ws[wid] = inc;
    __syncthreads();
    if (t == 0) { int r = 0; for (int i = 0; i < 8; i++) { int x = ws[i]; ws[i] = r; r += x; } }
    __syncthreads();
    int off = g_part[b] + ws[wid] + inc - s;
#pragma unroll
    for (int u = 0; u < 4; u++) {
        int i = base + u;
        if (i < N_NODES) { g_off[i] = off; g_pos[i] = off; }
        off += c[u];
    }
}

__global__ void k_fill(const int* __restrict__ es, const int* __restrict__ ed) {
    int i = blockIdx.x * blockDim.x + threadIdx.x;
    if (i >= N_SEDGE) return;
    int pos = atomicAdd(&g_pos[ed[i]], 1);
    g_csrs[pos] = es[i];
}

/* ---------------- fused GRU memory update (tf32 tensor-core) ----------------
 * memory==0: gi uses only W_ih[:,256:352]; gh = b_hh; h = (1-z)*n.
 * Tile 128 nodes. 8 warps x 16 rows. N=384 in 2 half-sweeps of 24 n8-tiles,
 * gate tiles interleaved so r/z/n stay in-thread for the epilogue.
 */
#define GRU_KS 100   /* 96 + 4 pad */
__global__ void __launch_bounds__(256, 1)
k_gru(const int* __restrict__ t, const float* __restrict__ msg,
      const float* __restrict__ w_ih, const float* __restrict__ b_ih,
      const float* __restrict__ b_hh,
      const float* __restrict__ time_w, const float* __restrict__ time_b) {
    extern __shared__ unsigned smu[];
    unsigned* Wsm = smu;                   /* [384][100] tf32 bits */
    unsigned* Vsm = smu + 384 * GRU_KS;    /* [128][100] tf32 bits */
    float*    Bsm = (float*)(smu + (384 + 128) * GRU_KS); /* 4*128 */
    const int tid = threadIdx.x;

    for (int i = tid; i < 384 * 96; i += 256) {
        int n = i / 96, k = i - n * 96;
        Wsm[n * GRU_KS + k] = to_tf32(w_ih[n * 352 + 256 + k]);
    }
    for (int k = tid; k < 128; k += 256) {
        Bsm[k]       = b_ih[k]       + b_hh[k];
        Bsm[128 + k] = b_ih[128 + k] + b_hh[128 + k];
        Bsm[256 + k] = b_ih[256 + k];
        Bsm[384 + k] = b_hh[256 + k];
    }
    const int warp = tid >> 5, lane = tid & 31;
    const int grp = lane >> 2, tg = lane & 3;
    __syncthreads();

    const int nch = (N_NODES + 127) / 128;
    for (int c = blockIdx.x; c < nch; c += gridDim.x) {
        const int base = c * 128;
        __syncthreads();
        for (int p = tid; p < 128 * 96; p += 256) {
            int nl = p / 96, j = p - nl * 96;
            int node = base + nl;
            float v = 0.f;
            if (node < N_NODES) {
                int le = g_last[node];
                if (le >= 0) {
                    if (j < 64) v = msg[(long)le * 64 + j];
                    else {
                        int jj = j - 64;
                        float arg = __fadd_rn(__fmul_rn((float)t[le], time_w[jj]), time_b[jj]);
                        v = (float)cos((double)arg);
                    }
                }
            }
            Vsm[nl * GRU_KS + j] = to_tf32(v);
        }
        __syncthreads();

        const int rlo = warp * 16 + grp;
#pragma unroll 1
        for (int half = 0; half < 2; half++) {
            float acc[24][4];
#pragma unroll
            for (int j = 0; j < 24; j++)
#pragma unroll
                for (int i = 0; i < 4; i++) acc[j][i] = 0.f;

#pragma unroll 1
            for (int k8 = 0; k8 < 12; k8++) {
                int k0 = k8 * 8 + tg;
                unsigned a0 = Vsm[rlo * GRU_KS + k0];
                unsigned a1 = Vsm[(rlo + 8) * GRU_KS + k0];
                unsigned a2 = Vsm[rlo * GRU_KS + k0 + 4];
                unsigned a3 = Vsm[(rlo + 8) * GRU_KS + k0 + 4];
#pragma unroll
                for (int j = 0; j < 24; j++) {
                    int n8 = (j >> 3) * 16 + half * 8 + (j & 7);
                    int n = n8 * 8 + grp;
                    unsigned b0 = Wsm[n * GRU_KS + k0];
                    unsigned b1 = Wsm[n * GRU_KS + k0 + 4];
                    mma8(acc[j], a0, a1, a2, a3, b0, b1);
                }
            }
            /* epilogue */
#pragma unroll
            for (int rw = 0; rw < 2; rw++) {
                int node = base + rlo + rw * 8;
                if (node >= N_NODES) continue;
                bool has = (g_last[node] >= 0);
#pragma unroll
                for (int jj = 0; jj < 8; jj++) {
                    float2 o;
#pragma unroll
                    for (int ii = 0; ii < 2; ii++) {
                        int k = (half * 8 + jj) * 8 + 2 * tg + ii;
                        int ai = rw * 2 + ii;
                        float r = 1.f / (1.f + expf(-(acc[jj][ai] + Bsm[k])));
                        float z = 1.f / (1.f + expf(-(acc[8 + jj][ai] + Bsm[128 + k])));
                        float nn = tanhf(acc[16 + jj][ai] + Bsm[256 + k] + r * Bsm[384 + k]);
                        float h = has ? (1.f - z) * nn : 0.f;
                        if (ii) o.y = h; else o.x = h;
                    }
                    *(float2*)&g_mem[(long)node * 128 + (half * 8 + jj) * 8 + 2 * tg] = o;
                }
            }
        }
    }
}

/* ---------------- GAT projection + attention scores (tf32 tensor-core) ------- */
#define X_KS 132
__global__ void __launch_bounds__(256, 1)
k_gatx(const float* __restrict__ gat_w, const float* __restrict__ att_src,
       const float* __restrict__ att_dst) {
    extern __shared__ unsigned smu[];
    unsigned* Wsm = smu;                 /* [128][132] tf32 */
    unsigned* Vsm = smu + 128 * X_KS;    /* [128][132] tf32 */
    float*    Asm = (float*)(smu + 2 * 128 * X_KS);  /* att_src[128], att_dst[128] */
    const int tid = threadIdx.x;
    for (int i = tid; i < 128 * 128; i += 256) {
        int n = i >> 7, k = i & 127;
        Wsm[n * X_KS + k] = to_tf32(gat_w[n * 128 + k]);
    }
    if (tid < 128) { Asm[tid] = att_src[tid]; Asm[128 + tid] = att_dst[tid]; }
    const int warp = tid >> 5, lane = tid & 31;
    const int grp = lane >> 2, tg = lane & 3;
    __syncthreads();

    const int nch = (N_NODES + 127) / 128;
    for (int c = blockIdx.x; c < nch; c += gridDim.x) {
        const int base = c * 128;
        __syncthreads();
        for (int p = tid; p < 128 * 128; p += 256) {
            int nl = p >> 7, j = p & 127;
            int node = base + nl;
            Vsm[nl * X_KS + j] = to_tf32(node < N_NODES ? g_mem[(long)node * 128 + j] : 0.f);
        }
        __syncthreads();

        float acc[16][4];
#pragma unroll
        for (int j = 0; j < 16; j++)
#pragma unroll
            for (int i = 0; i < 4; i++) acc[j][i] = 0.f;

        const int rlo = warp * 16 + grp;
#pragma unroll 1
        for (int k8 = 0; k8 < 16; k8++) {
            int k0 = k8 * 8 + tg;
            unsigned a0 = Vsm[rlo * X_KS + k0];
            unsigned a1 = Vsm[(rlo + 8) * X_KS + k0];
            unsigned a2 = Vsm[rlo * X_KS + k0 + 4];
            unsigned a3 = Vsm[(rlo + 8) * X_KS + k0 + 4];
#pragma unroll
            for (int n8 = 0; n8 < 16; n8++) {
                int n = n8 * 8 + grp;
                mma8(acc[n8], a0, a1, a2, a3,
                     Wsm[n * X_KS + k0], Wsm[n * X_KS + k0 + 4]);
            }
        }
        /* epilogue: store x + fused attention scores */
        float ps0 = 0.f, pd0 = 0.f, ps1 = 0.f, pd1 = 0.f;
        int node0 = base + rlo, node1 = node0 + 8;
#pragma unroll
        for (int n8 = 0; n8 < 16; n8++) {
            int col = n8 * 8 + 2 * tg;
            float s0 = Asm[col], s1 = Asm[col + 1];
            float d0 = Asm[128 + col], d1 = Asm[128 + col + 1];
            ps0 += acc[n8][0] * s0 + acc[n8][1] * s1;
            pd0 += acc[n8][0] * d0 + acc[n8][1] * d1;
            ps1 += acc[n8][2] * s0 + acc[n8][3] * s1;
            pd1 += acc[n8][2] * d0 + acc[n8][3] * d1;
            if (node0 < N_NODES)
                *(float2*)&g_x[(long)node0 * 128 + col] = make_float2(acc[n8][0], acc[n8][1]);
            if (node1 < N_NODES)
                *(float2*)&g_x[(long)node1 * 128 + col] = make_float2(acc[n8][2], acc[n8][3]);
        }
#pragma unroll
        for (int o = 1; o <= 2; o <<= 1) {
            ps0 += __shfl_xor_sync(0xFFFFFFFFu, ps0, o);
            pd0 += __shfl_xor_sync(0xFFFFFFFFu, pd0, o);
            ps1 += __shfl_xor_sync(0xFFFFFFFFu, ps1, o);
            pd1 += __shfl_xor_sync(0xFFFFFFFFu, pd1, o);
        }
        if (tg == 0) {
            if (node0 < N_NODES) { g_as[node0] = ps0; g_ad[node0] = pd0; }
            if (node1 < N_NODES) { g_as[node1] = ps1; g_ad[node1] = pd1; }
        }
    }
}

/* ---------------- fused GAT softmax + aggregation: warp per node, no atomics */
__global__ void __launch_bounds__(256)
k_agg() {
    int gt = blockIdx.x * blockDim.x + threadIdx.x;
    int node = gt >> 5, lane = gt & 31;
    if (node >= N_NODES) return;
    const int start = g_off[node], end = g_pos[node];
    const float ad = g_ad[node];
    float e_self = g_as[node] + ad;
    e_self = (e_self > 0.f) ? e_self : 0.2f * e_self;

    float m = e_self;
    for (int i = start + lane; i < end; i += 32) {
        float e = g_as[g_csrs[i]] + ad;
        e = (e > 0.f) ? e : 0.2f * e;
        m = fmaxf(m, e);
    }
#pragma unroll
    for (int o = 16; o; o >>= 1) m = fmaxf(m, __shfl_xor_sync(0xFFFFFFFFu, m, o));

    const float w0 = expf(e_self - m);
    float4 xv = ((const float4*)(g_x + (long)node * 128))[lane];
    float4 acc = make_float4(w0 * xv.x, w0 * xv.y, w0 * xv.z, w0 * xv.w);
    float den_l = 0.f;

    for (int b = start; b < end; b += 32) {
        int rem = end - b;
        int n = rem < 32 ? rem : 32;
        int  s_l = 0;
        float w_l = 0.f;
        if (lane < n) {
            s_l = g_csrs[b + lane];
            float e = g_as[s_l] + ad;
            e = (e > 0.f) ? e : 0.2f * e;
            w_l = expf(e - m);
            den_l += w_l;
        }
        for (int j = 0; j < n; j++) {
            int   s = __shfl_sync(0xFFFFFFFFu, s_l, j);
            float w = __shfl_sync(0xFFFFFFFFu, w_l, j);
            float4 v = ((const float4*)(g_x + (long)s * 128))[lane];
            acc.x += w * v.x; acc.y += w * v.y; acc.z += w * v.z; acc.w += w * v.w;
        }
    }
#pragma unroll
    for (int o = 16; o; o >>= 1) den_l += __shfl_xor_sync(0xFFFFFFFFu, den_l, o);
    float inv = 1.f / (den_l + w0);
    acc.x *= inv; acc.y *= inv; acc.z *= inv; acc.w *= inv;
    ((float4*)(g_z + (long)node * 128))[lane] = acc;
}

/* ---------------- fused ReLU + classifier (tf32 tensor-core) ---------------- */
#define C_KS 132
__global__ void __launch_bounds__(256, 2)
k_cls(const float* __restrict__ cls_w, const float* __restrict__ cls_b,
      const float* __restrict__ gat_b, float* __restrict__ out) {
    extern __shared__ unsigned smu[];
    unsigned* Wsm = smu;                /* [64][132] tf32 */
    unsigned* Vsm = smu + 64 * C_KS;    /* [128][132] tf32 */
    float*    Cb  = (float*)(smu + (64 + 128) * C_KS);  /* cls_b[64] */
    const int tid = threadIdx.x;
    for (int i = tid; i < 64 * 128; i += 256) {
        int n = i >> 7, k = i & 127;
        Wsm[n * C_KS + k] = to_tf32(cls_w[n * 128 + k]);
    }
    if (tid < 64) Cb[tid] = cls_b[tid];
    const int warp = tid >> 5, lane = tid & 31;
    const int grp = lane >> 2, tg = lane & 3;
    __syncthreads();

    const int nch = (N_NODES + 127) / 128;
    for (int c = blockIdx.x; c < nch; c += gridDim.x) {
        const int base = c * 128;
        __syncthreads();
        for (int p = tid; p < 128 * 128; p += 256) {
            int nl = p >> 7, j = p & 127;
            int node = base + nl;
            float v = 0.f;
            if (node < N_NODES) {
                v = g_z[(long)node * 128 + j] + gat_b[j];
                v = (v > 0.f) ? v : 0.f;
            }
            Vsm[nl * C_KS + j] = to_tf32(v);
        }
        __syncthreads();

        float acc[8][4];
#pragma unroll
        for (int j = 0; j < 8; j++)
#pragma unroll
            for (int i = 0; i < 4; i++) acc[j][i] = 0.f;

        const int rlo = warp * 16 + grp;
#pragma unroll 1
        for (int k8 = 0; k8 < 16; k8++) {
            int k0 = k8 * 8 + tg;
            unsigned a0 = Vsm[rlo * C_KS + k0];
            unsigned a1 = Vsm[(rlo + 8) * C_KS + k0];
            unsigned a2 = Vsm[rlo * C_KS + k0 + 4];
            unsigned a3 = Vsm[(rlo + 8) * C_KS + k0 + 4];
#pragma unroll
            for (int n8 = 0; n8 < 8; n8++) {
                int n = n8 * 8 + grp;
                mma8(acc[n8], a0, a1, a2, a3,
                     Wsm[n * C_KS + k0], Wsm[n * C_KS + k0 + 4]);
            }
        }
        int node0 = base + rlo, node1 = node0 + 8;
#pragma unroll
        for (int n8 = 0; n8 < 8; n8++) {
            int col = n8 * 8 + 2 * tg;
            float b0 = Cb[col], b1 = Cb[col + 1];
            if (node0 < N_NODES)
                *(float2*)&out[(long)node0 * 64 + col] =
                    make_float2(acc[n8][0] + b0, acc[n8][1] + b1);
            if (node1 < N_NODES)
                *(float2*)&out[(long)node1 * 64 + col] =
                    make_float2(acc[n8][2] + b0, acc[n8][3] + b1);
        }
    }
}

/* ---------------- launch ---------------- */
extern "C" void kernel_launch(void* const* d_in, const int* in_sizes, int n_in,
                              void* d_out, int out_size) {
    const int*   src    = (const int*)  d_in[0];
    const int*   dst    = (const int*)  d_in[1];
    const int*   t      = (const int*)  d_in[2];
    const float* msg    = (const float*)d_in[3];
    const int*   sei    = (const int*)  d_in[4];
    const float* time_w = (const float*)d_in[5];
    const float* time_b = (const float*)d_in[6];
    const float* w_ih   = (const float*)d_in[7];
    /* d_in[8] = gru_w_hh: unused (memory == 0 at update time) */
    const float* b_ih   = (const float*)d_in[9];
    const float* b_hh   = (const float*)d_in[10];
    const float* gat_w  = (const float*)d_in[11];
    const float* att_s  = (const float*)d_in[12];
    const float* att_d  = (const float*)d_in[13];
    const float* gat_b  = (const float*)d_in[14];
    const float* cls_w  = (const float*)d_in[15];
    const float* cls_b  = (const float*)d_in[16];
    float* out = (float*)d_out;
    const int* es = sei;
    const int* ed = sei + N_SEDGE;
    (void)in_sizes; (void)n_in; (void)out_size;

    k_init <<<(N_NODES + 255) / 256, 256>>>();
    k_last <<<(N_EV + 255) / 256, 256>>>(src, dst);
    k_count<<<(N_SEDGE + 255) / 256, 256>>>(ed);
    k_scanA<<<SNBLK, 256>>>();
    k_scanB<<<1, 128>>>();
    k_scanC<<<SNBLK, 256>>>();
    k_fill <<<(N_SEDGE + 255) / 256, 256>>>(es, ed);

    {
        size_t smb = (size_t)((384 + 128) * GRU_KS) * 4 + 512 * 4;
        cudaFuncSetAttribute(k_gru, cudaFuncAttributeMaxDynamicSharedMemorySize, (int)smb);
        k_gru<<<148, 256, smb>>>(t, msg, w_ih, b_ih, b_hh, time_w, time_b);
    }
    {
        size_t smb = (size_t)(2 * 128 * X_KS) * 4 + 256 * 4;
        cudaFuncSetAttribute(k_gatx, cudaFuncAttributeMaxDynamicSharedMemorySize, (int)smb);
        k_gatx<<<148, 256, smb>>>(gat_w, att_s, att_d);
    }
    k_agg <<<(N_NODES * 32 + 255) / 256, 256>>>();
    {
        size_t smb = (size_t)((64 + 128) * C_KS) * 4 + 64 * 4;
        cudaFuncSetAttribute(k_cls, cudaFuncAttributeMaxDynamicSharedMemorySize, (int)smb);
        k_cls<<<296, 256, smb>>>(cls_w, cls_b, gat_b, out);
    }
}

// round 10
// speedup vs baseline: 2.4075x; 1.1470x over previous
#include <cuda_runtime.h>
#include <math.h>

#define N_NODES 100000
#define N_EV    200000
#define N_SEDGE 1600000
#define SCHUNK  1024
#define SNBLK   ((N_NODES + SCHUNK - 1) / SCHUNK)

/* ---------------- device scratch (no allocations allowed) ---------------- */
__device__ __align__(16) int   g_last[N_NODES];
__device__ __align__(16) float g_mem [N_NODES * 128];
__device__ __align__(16) float g_x   [N_NODES * 128];
__device__ __align__(16) float g_as  [N_NODES];
__device__ __align__(16) float g_ad  [N_NODES];
__device__ __align__(16) float g_z   [N_NODES * 128];
__device__ __align__(16) int   g_cnt [N_NODES];
__device__ __align__(16) int   g_off [N_NODES];
__device__ __align__(16) int   g_pos [N_NODES];
__device__              int    g_part[SNBLK];
__device__ __align__(16) int   g_csrs[N_SEDGE];

/* ---------------- tf32 MMA helpers ---------------- */
__device__ __forceinline__ unsigned to_tf32(float f) {
    unsigned r; asm("cvt.rna.tf32.f32 %0,%1;" : "=r"(r) : "f"(f)); return r;
}
__device__ __forceinline__ void mma8(float (&c)[4], unsigned a0, unsigned a1,
                                     unsigned a2, unsigned a3,
                                     unsigned b0, unsigned b1) {
    asm("mma.sync.aligned.m16n8k8.row.col.f32.tf32.tf32.f32 "
        "{%0,%1,%2,%3},{%4,%5,%6,%7},{%8,%9},{%0,%1,%2,%3};"
        : "+f"(c[0]), "+f"(c[1]), "+f"(c[2]), "+f"(c[3])
        : "r"(a0), "r"(a1), "r"(a2), "r"(a3), "r"(b0), "r"(b1));
}

/* ---------------- init ---------------- */
__global__ void k_init() {
    int i = blockIdx.x * blockDim.x + threadIdx.x;
    if (i < N_NODES) { g_last[i] = -1; g_cnt[i] = 0; }
}

/* ---------------- last event per node ---------------- */
__global__ void k_last(const int* __restrict__ src, const int* __restrict__ dst) {
    int i = blockIdx.x * blockDim.x + threadIdx.x;
    if (i >= N_EV) return;
    atomicMax(&g_last[src[i]], i);
    atomicMax(&g_last[dst[i]], i);
}

/* ---------------- CSR build: count / scan / fill ---------------- */
__global__ void k_count(const int* __restrict__ ed) {
    int i = blockIdx.x * blockDim.x + threadIdx.x;
    if (i < N_SEDGE) atomicAdd(&g_cnt[ed[i]], 1);
}

__global__ void k_scanA() {
    int b = blockIdx.x, t = threadIdx.x;
    int base = b * SCHUNK + t * 4;
    int s = 0;
#pragma unroll
    for (int u = 0; u < 4; u++) { int i = base + u; if (i < N_NODES) s += g_cnt[i]; }
#pragma unroll
    for (int o = 16; o; o >>= 1) s += __shfl_xor_sync(0xFFFFFFFFu, s, o);
    __shared__ int ws[8];
    if ((t & 31) == 0) ws[t >> 5] = s;
    __syncthreads();
    if (t == 0) { int tot = 0; for (int w = 0; w < 8; w++) tot += ws[w]; g_part[b] = tot; }
}

__global__ void k_scanB() {
    int t = threadIdx.x;
    int v = (t < SNBLK) ? g_part[t] : 0;
    int lane = t & 31, wid = t >> 5;
    int inc = v;
#pragma unroll
    for (int o = 1; o < 32; o <<= 1) { int n = __shfl_up_sync(0xFFFFFFFFu, inc, o); if (lane >= o) inc += n; }
    __shared__ int ws[4];
    if (lane == 31) ws[wid] = inc;
    __syncthreads();
    if (t == 0) { int r = 0; for (int i = 0; i < 4; i++) { int x = ws[i]; ws[i] = r; r += x; } }
    __syncthreads();
    if (t < SNBLK) g_part[t] = inc - v + ws[wid];
}

__global__ void k_scanC() {
    int b = blockIdx.x, t = threadIdx.x;
    int base = b * SCHUNK + t * 4;
    int c[4]; int s = 0;
#pragma unroll
    for (int u = 0; u < 4; u++) { int i = base + u; c[u] = (i < N_NODES) ? g_cnt[i] : 0; s += c[u]; }
    int lane = t & 31, wid = t >> 5;
    int inc = s;
#pragma unroll
    for (int o = 1; o < 32; o <<= 1) { int n = __shfl_up_sync(0xFFFFFFFFu, inc, o); if (lane >= o) inc += n; }
    __shared__ int ws[8];
    if (lane == 31) ws[wid] = inc;
    __syncthreads();
    if (t == 0) { int r = 0; for (int i = 0; i < 8; i++) { int x = ws[i]; ws[i] = r; r += x; } }
    __syncthreads();
    int off = g_part[b] + ws[wid] + inc - s;
#pragma unroll
    for (int u = 0; u < 4; u++) {
        int i = base + u;
        if (i < N_NODES) { g_off[i] = off; g_pos[i] = off; }
        off += c[u];
    }
}

__global__ void k_fill(const int* __restrict__ es, const int* __restrict__ ed) {
    int i = blockIdx.x * blockDim.x + threadIdx.x;
    if (i >= N_SEDGE) return;
    int pos = atomicAdd(&g_pos[ed[i]], 1);
    g_csrs[pos] = es[i];
}

/* ---------------- fused GRU memory update (tf32 tensor-core) ----------------
 * memory==0: gi uses only W_ih[:,256:352]; gh = b_hh; h = (1-z)*n.
 * Tile 128 nodes. 8 warps x 16 rows. N=384 in 2 half-sweeps of 24 n8-tiles.
 */
#define GRU_KS 100   /* 96 + 4 pad */
__global__ void __launch_bounds__(256, 1)
k_gru(const int* __restrict__ t, const float* __restrict__ msg,
      const float* __restrict__ w_ih, const float* __restrict__ b_ih,
      const float* __restrict__ b_hh,
      const float* __restrict__ time_w, const float* __restrict__ time_b) {
    extern __shared__ unsigned smu[];
    unsigned* Wsm = smu;                   /* [384][100] tf32 bits */
    unsigned* Vsm = smu + 384 * GRU_KS;    /* [128][100] tf32 bits */
    float*    Bsm = (float*)(smu + (384 + 128) * GRU_KS); /* 4*128 */
    const int tid = threadIdx.x;

    for (int i = tid; i < 384 * 96; i += 256) {
        int n = i / 96, k = i - n * 96;
        Wsm[n * GRU_KS + k] = to_tf32(w_ih[n * 352 + 256 + k]);
    }
    for (int k = tid; k < 128; k += 256) {
        Bsm[k]       = b_ih[k]       + b_hh[k];
        Bsm[128 + k] = b_ih[128 + k] + b_hh[128 + k];
        Bsm[256 + k] = b_ih[256 + k];
        Bsm[384 + k] = b_hh[256 + k];
    }
    const int warp = tid >> 5, lane = tid & 31;
    const int grp = lane >> 2, tg = lane & 3;
    __syncthreads();

    const int nch = (N_NODES + 127) / 128;
    for (int c = blockIdx.x; c < nch; c += gridDim.x) {
        const int base = c * 128;
        __syncthreads();
        for (int p = tid; p < 128 * 96; p += 256) {
            int nl = p / 96, j = p - nl * 96;
            int node = base + nl;
            float v = 0.f;
            if (node < N_NODES) {
                int le = g_last[node];
                if (le >= 0) {
                    if (j < 64) v = msg[(long)le * 64 + j];
                    else {
                        int jj = j - 64;
                        /* arg matches JAX bitwise (fp32 mul then add, no FMA);
                           cosf of that arg agrees with XLA's f32 cos to ~2 ulp */
                        float arg = __fadd_rn(__fmul_rn((float)t[le], time_w[jj]), time_b[jj]);
                        v = cosf(arg);
                    }
                }
            }
            Vsm[nl * GRU_KS + j] = to_tf32(v);
        }
        __syncthreads();

        const int rlo = warp * 16 + grp;
#pragma unroll 1
        for (int half = 0; half < 2; half++) {
            float acc[24][4];
#pragma unroll
            for (int j = 0; j < 24; j++)
#pragma unroll
                for (int i = 0; i < 4; i++) acc[j][i] = 0.f;

#pragma unroll 1
            for (int k8 = 0; k8 < 12; k8++) {
                int k0 = k8 * 8 + tg;
                unsigned a0 = Vsm[rlo * GRU_KS + k0];
                unsigned a1 = Vsm[(rlo + 8) * GRU_KS + k0];
                unsigned a2 = Vsm[rlo * GRU_KS + k0 + 4];
                unsigned a3 = Vsm[(rlo + 8) * GRU_KS + k0 + 4];
#pragma unroll
                for (int j = 0; j < 24; j++) {
                    int n8 = (j >> 3) * 16 + half * 8 + (j & 7);
                    int n = n8 * 8 + grp;
                    unsigned b0 = Wsm[n * GRU_KS + k0];
                    unsigned b1 = Wsm[n * GRU_KS + k0 + 4];
                    mma8(acc[j], a0, a1, a2, a3, b0, b1);
                }
            }
            /* epilogue */
#pragma unroll
            for (int rw = 0; rw < 2; rw++) {
                int node = base + rlo + rw * 8;
                if (node >= N_NODES) continue;
                bool has = (g_last[node] >= 0);
#pragma unroll
                for (int jj = 0; jj < 8; jj++) {
                    float2 o;
#pragma unroll
                    for (int ii = 0; ii < 2; ii++) {
                        int k = (half * 8 + jj) * 8 + 2 * tg + ii;
                        int ai = rw * 2 + ii;
                        float r = 1.f / (1.f + expf(-(acc[jj][ai] + Bsm[k])));
                        float z = 1.f / (1.f + expf(-(acc[8 + jj][ai] + Bsm[128 + k])));
                        float nn = tanhf(acc[16 + jj][ai] + Bsm[256 + k] + r * Bsm[384 + k]);
                        float h = has ? (1.f - z) * nn : 0.f;
                        if (ii) o.y = h; else o.x = h;
                    }
                    *(float2*)&g_mem[(long)node * 128 + (half * 8 + jj) * 8 + 2 * tg] = o;
                }
            }
        }
    }
}

/* ---------------- GAT projection + attention scores (tf32 tensor-core) ------- */
#define X_KS 132
__global__ void __launch_bounds__(256, 1)
k_gatx(const float* __restrict__ gat_w, const float* __restrict__ att_src,
       const float* __restrict__ att_dst) {
    extern __shared__ unsigned smu[];
    unsigned* Wsm = smu;                 /* [128][132] tf32 */
    unsigned* Vsm = smu + 128 * X_KS;    /* [128][132] tf32 */
    float*    Asm = (float*)(smu + 2 * 128 * X_KS);  /* att_src[128], att_dst[128] */
    const int tid = threadIdx.x;
    for (int i = tid; i < 128 * 128; i += 256) {
        int n = i >> 7, k = i & 127;
        Wsm[n * X_KS + k] = to_tf32(gat_w[n * 128 + k]);
    }
    if (tid < 128) { Asm[tid] = att_src[tid]; Asm[128 + tid] = att_dst[tid]; }
    const int warp = tid >> 5, lane = tid & 31;
    const int grp = lane >> 2, tg = lane & 3;
    __syncthreads();

    const int nch = (N_NODES + 127) / 128;
    for (int c = blockIdx.x; c < nch; c += gridDim.x) {
        const int base = c * 128;
        __syncthreads();
        for (int p = tid; p < 128 * 128; p += 256) {
            int nl = p >> 7, j = p & 127;
            int node = base + nl;
            Vsm[nl * X_KS + j] = to_tf32(node < N_NODES ? g_mem[(long)node * 128 + j] : 0.f);
        }
        __syncthreads();

        float acc[16][4];
#pragma unroll
        for (int j = 0; j < 16; j++)
#pragma unroll
            for (int i = 0; i < 4; i++) acc[j][i] = 0.f;

        const int rlo = warp * 16 + grp;
#pragma unroll 1
        for (int k8 = 0; k8 < 16; k8++) {
            int k0 = k8 * 8 + tg;
            unsigned a0 = Vsm[rlo * X_KS + k0];
            unsigned a1 = Vsm[(rlo + 8) * X_KS + k0];
            unsigned a2 = Vsm[rlo * X_KS + k0 + 4];
            unsigned a3 = Vsm[(rlo + 8) * X_KS + k0 + 4];
#pragma unroll
            for (int n8 = 0; n8 < 16; n8++) {
                int n = n8 * 8 + grp;
                mma8(acc[n8], a0, a1, a2, a3,
                     Wsm[n * X_KS + k0], Wsm[n * X_KS + k0 + 4]);
            }
        }
        /* epilogue: store x + fused attention scores */
        float ps0 = 0.f, pd0 = 0.f, ps1 = 0.f, pd1 = 0.f;
        int node0 = base + rlo, node1 = node0 + 8;
#pragma unroll
        for (int n8 = 0; n8 < 16; n8++) {
            int col = n8 * 8 + 2 * tg;
            float s0 = Asm[col], s1 = Asm[col + 1];
            float d0 = Asm[128 + col], d1 = Asm[128 + col + 1];
            ps0 += acc[n8][0] * s0 + acc[n8][1] * s1;
            pd0 += acc[n8][0] * d0 + acc[n8][1] * d1;
            ps1 += acc[n8][2] * s0 + acc[n8][3] * s1;
            pd1 += acc[n8][2] * d0 + acc[n8][3] * d1;
            if (node0 < N_NODES)
                *(float2*)&g_x[(long)node0 * 128 + col] = make_float2(acc[n8][0], acc[n8][1]);
            if (node1 < N_NODES)
                *(float2*)&g_x[(long)node1 * 128 + col] = make_float2(acc[n8][2], acc[n8][3]);
        }
#pragma unroll
        for (int o = 1; o <= 2; o <<= 1) {
            ps0 += __shfl_xor_sync(0xFFFFFFFFu, ps0, o);
            pd0 += __shfl_xor_sync(0xFFFFFFFFu, pd0, o);
            ps1 += __shfl_xor_sync(0xFFFFFFFFu, ps1, o);
            pd1 += __shfl_xor_sync(0xFFFFFFFFu, pd1, o);
        }
        if (tg == 0) {
            if (node0 < N_NODES) { g_as[node0] = ps0; g_ad[node0] = pd0; }
            if (node1 < N_NODES) { g_as[node1] = ps1; g_ad[node1] = pd1; }
        }
    }
}

/* ---------------- fused GAT softmax + aggregation: warp per node --------------
 * Single pass, no max-shift: score magnitudes are provably tiny (|e| << 80),
 * alpha = exp(e)/sum(exp(e)) is mathematically identical to the shifted form.
 */
__global__ void __launch_bounds__(256)
k_agg() {
    int gt = blockIdx.x * blockDim.x + threadIdx.x;
    int node = gt >> 5, lane = gt & 31;
    if (node >= N_NODES) return;
    const int start = g_off[node], end = g_pos[node];
    const float ad = g_ad[node];
    float e_self = g_as[node] + ad;
    e_self = (e_self > 0.f) ? e_self : 0.2f * e_self;

    const float w0 = expf(e_self);
    float4 xv = __ldg((const float4*)(g_x + (long)node * 128) + lane);
    float4 acc = make_float4(w0 * xv.x, w0 * xv.y, w0 * xv.z, w0 * xv.w);
    float den_l = 0.f;

    for (int b = start; b < end; b += 32) {
        int rem = end - b;
        int n = rem < 32 ? rem : 32;
        int  s_l = 0;
        float w_l = 0.f;
        if (lane < n) {
            s_l = __ldg(&g_csrs[b + lane]);
            float e = __ldg(&g_as[s_l]) + ad;
            e = (e > 0.f) ? e : 0.2f * e;
            w_l = expf(e);
            den_l += w_l;
        }
        for (int j = 0; j < n; j++) {
            int   s = __shfl_sync(0xFFFFFFFFu, s_l, j);
            float w = __shfl_sync(0xFFFFFFFFu, w_l, j);
            float4 v = __ldg((const float4*)(g_x + (long)s * 128) + lane);
            acc.x += w * v.x; acc.y += w * v.y; acc.z += w * v.z; acc.w += w * v.w;
        }
    }
#pragma unroll
    for (int o = 16; o; o >>= 1) den_l += __shfl_xor_sync(0xFFFFFFFFu, den_l, o);
    float inv = 1.f / (den_l + w0);
    acc.x *= inv; acc.y *= inv; acc.z *= inv; acc.w *= inv;
    ((float4*)(g_z + (long)node * 128))[lane] = acc;
}

/* ---------------- fused ReLU + classifier (tf32 tensor-core) ---------------- */
#define C_KS 132
__global__ void __launch_bounds__(256, 2)
k_cls(const float* __restrict__ cls_w, const float* __restrict__ cls_b,
      const float* __restrict__ gat_b, float* __restrict__ out) {
    extern __shared__ unsigned smu[];
    unsigned* Wsm = smu;                /* [64][132] tf32 */
    unsigned* Vsm = smu + 64 * C_KS;    /* [128][132] tf32 */
    float*    Cb  = (float*)(smu + (64 + 128) * C_KS);  /* cls_b[64] */
    const int tid = threadIdx.x;
    for (int i = tid; i < 64 * 128; i += 256) {
        int n = i >> 7, k = i & 127;
        Wsm[n * C_KS + k] = to_tf32(cls_w[n * 128 + k]);
    }
    if (tid < 64) Cb[tid] = cls_b[tid];
    const int warp = tid >> 5, lane = tid & 31;
    const int grp = lane >> 2, tg = lane & 3;
    __syncthreads();

    const int nch = (N_NODES + 127) / 128;
    for (int c = blockIdx.x; c < nch; c += gridDim.x) {
        const int base = c * 128;
        __syncthreads();
        for (int p = tid; p < 128 * 128; p += 256) {
            int nl = p >> 7, j = p & 127;
            int node = base + nl;
            float v = 0.f;
            if (node < N_NODES) {
                v = g_z[(long)node * 128 + j] + gat_b[j];
                v = (v > 0.f) ? v : 0.f;
            }
            Vsm[nl * C_KS + j] = to_tf32(v);
        }
        __syncthreads();

        float acc[8][4];
#pragma unroll
        for (int j = 0; j < 8; j++)
#pragma unroll
            for (int i = 0; i < 4; i++) acc[j][i] = 0.f;

        const int rlo = warp * 16 + grp;
#pragma unroll 1
        for (int k8 = 0; k8 < 16; k8++) {
            int k0 = k8 * 8 + tg;
            unsigned a0 = Vsm[rlo * C_KS + k0];
            unsigned a1 = Vsm[(rlo + 8) * C_KS + k0];
            unsigned a2 = Vsm[rlo * C_KS + k0 + 4];
            unsigned a3 = Vsm[(rlo + 8) * C_KS + k0 + 4];
#pragma unroll
            for (int n8 = 0; n8 < 8; n8++) {
                int n = n8 * 8 + grp;
                mma8(acc[n8], a0, a1, a2, a3,
                     Wsm[n * C_KS + k0], Wsm[n * C_KS + k0 + 4]);
            }
        }
        int node0 = base + rlo, node1 = node0 + 8;
#pragma unroll
        for (int n8 = 0; n8 < 8; n8++) {
            int col = n8 * 8 + 2 * tg;
            float b0 = Cb[col], b1 = Cb[col + 1];
            if (node0 < N_NODES)
                *(float2*)&out[(long)node0 * 64 + col] =
                    make_float2(acc[n8][0] + b0, acc[n8][1] + b1);
            if (node1 < N_NODES)
                *(float2*)&out[(long)node1 * 64 + col] =
                    make_float2(acc[n8][2] + b0, acc[n8][3] + b1);
        }
    }
}

/* ---------------- launch ----------------
 * Order puts k_gru at launch #4 so the fixed ncu window profiles it.
 * (CSR build is independent of the GEMM chain; k_agg needs both.)
 */
extern "C" void kernel_launch(void* const* d_in, const int* in_sizes, int n_in,
                              void* d_out, int out_size) {
    const int*   src    = (const int*)  d_in[0];
    const int*   dst    = (const int*)  d_in[1];
    const int*   t      = (const int*)  d_in[2];
    const float* msg    = (const float*)d_in[3];
    const int*   sei    = (const int*)  d_in[4];
    const float* time_w = (const float*)d_in[5];
    const float* time_b = (const float*)d_in[6];
    const float* w_ih   = (const float*)d_in[7];
    /* d_in[8] = gru_w_hh: unused (memory == 0 at update time) */
    const float* b_ih   = (const float*)d_in[9];
    const float* b_hh   = (const float*)d_in[10];
    const float* gat_w  = (const float*)d_in[11];
    const float* att_s  = (const float*)d_in[12];
    const float* att_d  = (const float*)d_in[13];
    const float* gat_b  = (const float*)d_in[14];
    const float* cls_w  = (const float*)d_in[15];
    const float* cls_b  = (const float*)d_in[16];
    float* out = (float*)d_out;
    const int* es = sei;
    const int* ed = sei + N_SEDGE;
    (void)in_sizes; (void)n_in; (void)out_size;

    k_init <<<(N_NODES + 255) / 256, 256>>>();
    k_last <<<(N_EV + 255) / 256, 256>>>(src, dst);
    k_count<<<(N_SEDGE + 255) / 256, 256>>>(ed);

    {
        size_t smb = (size_t)((384 + 128) * GRU_KS) * 4 + 512 * 4;
        cudaFuncSetAttribute(k_gru, cudaFuncAttributeMaxDynamicSharedMemorySize, (int)smb);
        k_gru<<<148, 256, smb>>>(t, msg, w_ih, b_ih, b_hh, time_w, time_b);
    }
    {
        size_t smb = (size_t)(2 * 128 * X_KS) * 4 + 256 * 4;
        cudaFuncSetAttribute(k_gatx, cudaFuncAttributeMaxDynamicSharedMemorySize, (int)smb);
        k_gatx<<<148, 256, smb>>>(gat_w, att_s, att_d);
    }

    k_scanA<<<SNBLK, 256>>>();
    k_scanB<<<1, 128>>>();
    k_scanC<<<SNBLK, 256>>>();
    k_fill <<<(N_SEDGE + 255) / 256, 256>>>(es, ed);

    k_agg <<<(N_NODES * 32 + 255) / 256, 256>>>();
    {
        size_t smb = (size_t)((64 + 128) * C_KS) * 4 + 64 * 4;
        cudaFuncSetAttribute(k_cls, cudaFuncAttributeMaxDynamicSharedMemorySize, (int)smb);
        k_cls<<<296, 256, smb>>>(cls_w, cls_b, gat_b, out);
    }
}

// round 11
// speedup vs baseline: 3.6907x; 1.5330x over previous
#include <cuda_runtime.h>
#include <math.h>

#define N_NODES 100000
#define N_EV    200000
#define N_SEDGE 1600000
#define SCHUNK  1024
#define SNBLK   ((N_NODES + SCHUNK - 1) / SCHUNK)

/* ---------------- device scratch (no allocations allowed) ---------------- */
__device__ __align__(16) int   g_last[N_NODES];
__device__ __align__(16) float g_mem [N_NODES * 128];
__device__ __align__(16) float g_x   [N_NODES * 128];
__device__ __align__(16) float g_as  [N_NODES];
__device__ __align__(16) float g_ad  [N_NODES];
__device__ __align__(16) float g_z   [N_NODES * 128];
__device__ __align__(16) int   g_cnt [N_NODES];
__device__ __align__(16) int   g_off [N_NODES];
__device__ __align__(16) int   g_pos [N_NODES];
__device__              int    g_part[SNBLK];
__device__ __align__(16) int   g_csrs[N_SEDGE];

/* ---------------- tf32 MMA helpers ---------------- */
__device__ __forceinline__ unsigned to_tf32(float f) {
    unsigned r; asm("cvt.rna.tf32.f32 %0,%1;" : "=r"(r) : "f"(f)); return r;
}
__device__ __forceinline__ void mma8(float (&c)[4], unsigned a0, unsigned a1,
                                     unsigned a2, unsigned a3,
                                     unsigned b0, unsigned b1) {
    asm("mma.sync.aligned.m16n8k8.row.col.f32.tf32.tf32.f32 "
        "{%0,%1,%2,%3},{%4,%5,%6,%7},{%8,%9},{%0,%1,%2,%3};"
        : "+f"(c[0]), "+f"(c[1]), "+f"(c[2]), "+f"(c[3])
        : "r"(a0), "r"(a1), "r"(a2), "r"(a3), "r"(b0), "r"(b1));
}
__device__ __forceinline__ float sigmoidf_(float x) {
    return 1.f / (1.f + expf(-x));
}

/* ---------------- init ---------------- */
__global__ void k_init() {
    int i = blockIdx.x * blockDim.x + threadIdx.x;
    if (i < N_NODES) { g_last[i] = -1; g_cnt[i] = 0; }
}

/* ---------------- last event per node ---------------- */
__global__ void k_last(const int* __restrict__ src, const int* __restrict__ dst) {
    int i = blockIdx.x * blockDim.x + threadIdx.x;
    if (i >= N_EV) return;
    atomicMax(&g_last[src[i]], i);
    atomicMax(&g_last[dst[i]], i);
}

/* ---------------- CSR build: count / scan / fill ---------------- */
__global__ void k_count(const int* __restrict__ ed) {
    int i = blockIdx.x * blockDim.x + threadIdx.x;
    if (i < N_SEDGE) atomicAdd(&g_cnt[ed[i]], 1);
}

__global__ void k_scanA() {
    int b = blockIdx.x, t = threadIdx.x;
    int base = b * SCHUNK + t * 4;
    int s = 0;
#pragma unroll
    for (int u = 0; u < 4; u++) { int i = base + u; if (i < N_NODES) s += g_cnt[i]; }
#pragma unroll
    for (int o = 16; o; o >>= 1) s += __shfl_xor_sync(0xFFFFFFFFu, s, o);
    __shared__ int ws[8];
    if ((t & 31) == 0) ws[t >> 5] = s;
    __syncthreads();
    if (t == 0) { int tot = 0; for (int w = 0; w < 8; w++) tot += ws[w]; g_part[b] = tot; }
}

__global__ void k_scanB() {
    int t = threadIdx.x;
    int v = (t < SNBLK) ? g_part[t] : 0;
    int lane = t & 31, wid = t >> 5;
    int inc = v;
#pragma unroll
    for (int o = 1; o < 32; o <<= 1) { int n = __shfl_up_sync(0xFFFFFFFFu, inc, o); if (lane >= o) inc += n; }
    __shared__ int ws[4];
    if (lane == 31) ws[wid] = inc;
    __syncthreads();
    if (t == 0) { int r = 0; for (int i = 0; i < 4; i++) { int x = ws[i]; ws[i] = r; r += x; } }
    __syncthreads();
    if (t < SNBLK) g_part[t] = inc - v + ws[wid];
}

__global__ void k_scanC() {
    int b = blockIdx.x, t = threadIdx.x;
    int base = b * SCHUNK + t * 4;
    int c[4]; int s = 0;
#pragma unroll
    for (int u = 0; u < 4; u++) { int i = base + u; c[u] = (i < N_NODES) ? g_cnt[i] : 0; s += c[u]; }
    int lane = t & 31, wid = t >> 5;
    int inc = s;
#pragma unroll
    for (int o = 1; o < 32; o <<= 1) { int n = __shfl_up_sync(0xFFFFFFFFu, inc, o); if (lane >= o) inc += n; }
    __shared__ int ws[8];
    if (lane == 31) ws[wid] = inc;
    __syncthreads();
    if (t == 0) { int r = 0; for (int i = 0; i < 8; i++) { int x = ws[i]; ws[i] = r; r += x; } }
    __syncthreads();
    int off = g_part[b] + ws[wid] + inc - s;
#pragma unroll
    for (int u = 0; u < 4; u++) {
        int i = base + u;
        if (i < N_NODES) { g_off[i] = off; g_pos[i] = off; }
        off += c[u];
    }
}

__global__ void k_fill(const int* __restrict__ es, const int* __restrict__ ed) {
    int i = blockIdx.x * blockDim.x + threadIdx.x;
    if (i >= N_SEDGE) return;
    int pos = atomicAdd(&g_pos[ed[i]], 1);
    g_csrs[pos] = es[i];
}

/* ---------------- fused GRU memory update (tf32 MMA, reg-resident A) ---------
 * memory==0: gi uses only W_ih[:,256:352]; gh = b_hh; h = (1-z)*n.
 * 512 thr/block, warp-per-16-rows grid-stride (100000 = 6250*16, exact).
 * A fragments (msg gather + cosf) computed straight into registers: no V smem,
 * no __syncthreads in the loop. W pre-packed in MMA fragment layout (uint2
 * per lane per (pass,k8,tile)); mainloop B-load = one conflict-free LDS.64.
 * N=384 in 8 passes x 6 tiles (2 per gate -> r/z/n in-thread for epilogue).
 */
#define GRU_WFRAGS (8 * 12 * 6 * 32)   /* uint2 entries = 147456 B */
__global__ void __launch_bounds__(512, 1)
k_gru(const int* __restrict__ t, const float* __restrict__ msg,
      const float* __restrict__ w_ih, const float* __restrict__ b_ih,
      const float* __restrict__ b_hh,
      const float* __restrict__ time_w, const float* __restrict__ time_b) {
    extern __shared__ unsigned smu[];
    uint2* Wf  = (uint2*)smu;                 /* [pass][k8][tile6][lane] */
    float* Bsm = (float*)(Wf + GRU_WFRAGS);   /* r,z,n_in,n_hh biases 4*128 */
    float* Tw  = Bsm + 512;                   /* time_w[32] */
    float* Tb  = Tw + 32;                     /* time_b[32] */
    const int tid = threadIdx.x;

    /* one-time W fragment packing: tile6 = g*2+jj; n8 = g*16 + p*2 + jj */
    for (int i = tid; i < GRU_WFRAGS; i += 512) {
        int lane = i & 31, rest = i >> 5;
        int t6 = rest % 6; rest /= 6;
        int k8 = rest % 12;
        int p  = rest / 12;
        int g = t6 >> 1, jj = t6 & 1;
        int n8 = g * 16 + p * 2 + jj;
        int n = n8 * 8 + (lane >> 2);
        int k = k8 * 8 + (lane & 3);
        const float* wr = w_ih + n * 352 + 256 + k;
        Wf[i] = make_uint2(to_tf32(wr[0]), to_tf32(wr[4]));
    }
    for (int k = tid; k < 128; k += 512) {
        Bsm[k]       = b_ih[k]       + b_hh[k];
        Bsm[128 + k] = b_ih[128 + k] + b_hh[128 + k];
        Bsm[256 + k] = b_ih[256 + k];
        Bsm[384 + k] = b_hh[256 + k];
    }
    if (tid < 32) { Tw[tid] = time_w[tid]; Tb[tid] = time_b[tid]; }
    __syncthreads();

    const int warp = tid >> 5, lane = tid & 31;
    const int grp = lane >> 2, tg = lane & 3;
    const int nwarps = gridDim.x * 16;

    for (int rg = blockIdx.x * 16 + warp; rg < N_NODES / 16; rg += nwarps) {
        const int node0 = rg * 16 + grp, node1 = node0 + 8;
        const int le0 = g_last[node0], le1 = g_last[node1];
        const bool h0 = le0 >= 0, h1 = le1 >= 0;
        const float tf0 = h0 ? (float)t[le0] : 0.f;
        const float tf1 = h1 ? (float)t[le1] : 0.f;
        const float* m0 = msg + (long)(h0 ? le0 : 0) * 64;
        const float* m1 = msg + (long)(h1 ? le1 : 0) * 64;

        /* A fragments: a[k8] = {V(r0,c0), V(r1,c0), V(r0,c1), V(r1,c1)} */
        unsigned a[12][4];
#pragma unroll
        for (int k8 = 0; k8 < 8; k8++) {
            int c0 = k8 * 8 + tg, c1 = c0 + 4;
            a[k8][0] = h0 ? to_tf32(__ldg(&m0[c0])) : 0u;
            a[k8][1] = h1 ? to_tf32(__ldg(&m1[c0])) : 0u;
            a[k8][2] = h0 ? to_tf32(__ldg(&m0[c1])) : 0u;
            a[k8][3] = h1 ? to_tf32(__ldg(&m1[c1])) : 0u;
        }
#pragma unroll
        for (int k8 = 8; k8 < 12; k8++) {
            int j0 = k8 * 8 + tg - 64, j1 = j0 + 4;
            float w0 = Tw[j0], bb0 = Tb[j0], w1 = Tw[j1], bb1 = Tb[j1];
            a[k8][0] = h0 ? to_tf32(cosf(__fadd_rn(__fmul_rn(tf0, w0), bb0))) : 0u;
            a[k8][1] = h1 ? to_tf32(cosf(__fadd_rn(__fmul_rn(tf1, w0), bb0))) : 0u;
            a[k8][2] = h0 ? to_tf32(cosf(__fadd_rn(__fmul_rn(tf0, w1), bb1))) : 0u;
            a[k8][3] = h1 ? to_tf32(cosf(__fadd_rn(__fmul_rn(tf1, w1), bb1))) : 0u;
        }

#pragma unroll 1
        for (int p = 0; p < 8; p++) {
            float acc[6][4];
#pragma unroll
            for (int q = 0; q < 6; q++)
#pragma unroll
                for (int i = 0; i < 4; i++) acc[q][i] = 0.f;

#pragma unroll
            for (int k8 = 0; k8 < 12; k8++) {
                const uint2* wp = Wf + ((p * 12 + k8) * 6) * 32 + lane;
#pragma unroll
                for (int t6 = 0; t6 < 6; t6++) {
                    uint2 b = wp[t6 * 32];
                    mma8(acc[t6], a[k8][0], a[k8][1], a[k8][2], a[k8][3], b.x, b.y);
                }
            }
            /* epilogue: tiles jj (r), 2+jj (z), 4+jj (n); cols (p*2+jj)*8+2tg+ii */
#pragma unroll
            for (int jj = 0; jj < 2; jj++) {
                int kbase = (p * 2 + jj) * 8 + 2 * tg;
                float o0[2], o1[2];
#pragma unroll
                for (int ii = 0; ii < 2; ii++) {
                    int kk = kbase + ii;
                    float br = Bsm[kk], bz = Bsm[128 + kk];
                    float bin = Bsm[256 + kk], bhn = Bsm[384 + kk];
                    {
                        float r = sigmoidf_(acc[jj][ii] + br);
                        float z = sigmoidf_(acc[2 + jj][ii] + bz);
                        float nn = tanhf(acc[4 + jj][ii] + bin + r * bhn);
                        o0[ii] = h0 ? (1.f - z) * nn : 0.f;
                    }
                    {
                        float r = sigmoidf_(acc[jj][2 + ii] + br);
                        float z = sigmoidf_(acc[2 + jj][2 + ii] + bz);
                        float nn = tanhf(acc[4 + jj][2 + ii] + bin + r * bhn);
                        o1[ii] = h1 ? (1.f - z) * nn : 0.f;
                    }
                }
                *(float2*)&g_mem[(long)node0 * 128 + kbase] = make_float2(o0[0], o0[1]);
                *(float2*)&g_mem[(long)node1 * 128 + kbase] = make_float2(o1[0], o1[1]);
            }
        }
    }
}

/* ---------------- GAT projection + attention scores (tf32 tensor-core) ------- */
#define X_KS 132
__global__ void __launch_bounds__(256, 1)
k_gatx(const float* __restrict__ gat_w, const float* __restrict__ att_src,
       const float* __restrict__ att_dst) {
    extern __shared__ unsigned smu[];
    unsigned* Wsm = smu;                 /* [128][132] tf32 */
    unsigned* Vsm = smu + 128 * X_KS;    /* [128][132] tf32 */
    float*    Asm = (float*)(smu + 2 * 128 * X_KS);  /* att_src[128], att_dst[128] */
    const int tid = threadIdx.x;
    for (int i = tid; i < 128 * 128; i += 256) {
        int n = i >> 7, k = i & 127;
        Wsm[n * X_KS + k] = to_tf32(gat_w[n * 128 + k]);
    }
    if (tid < 128) { Asm[tid] = att_src[tid]; Asm[128 + tid] = att_dst[tid]; }
    const int warp = tid >> 5, lane = tid & 31;
    const int grp = lane >> 2, tg = lane & 3;
    __syncthreads();

    const int nch = (N_NODES + 127) / 128;
    for (int c = blockIdx.x; c < nch; c += gridDim.x) {
        const int base = c * 128;
        __syncthreads();
        for (int p = tid; p < 128 * 128; p += 256) {
            int nl = p >> 7, j = p & 127;
            int node = base + nl;
            Vsm[nl * X_KS + j] = to_tf32(node < N_NODES ? g_mem[(long)node * 128 + j] : 0.f);
        }
        __syncthreads();

        float acc[16][4];
#pragma unroll
        for (int j = 0; j < 16; j++)
#pragma unroll
            for (int i = 0; i < 4; i++) acc[j][i] = 0.f;

        const int rlo = warp * 16 + grp;
#pragma unroll 1
        for (int k8 = 0; k8 < 16; k8++) {
            int k0 = k8 * 8 + tg;
            unsigned a0 = Vsm[rlo * X_KS + k0];
            unsigned a1 = Vsm[(rlo + 8) * X_KS + k0];
            unsigned a2 = Vsm[rlo * X_KS + k0 + 4];
            unsigned a3 = Vsm[(rlo + 8) * X_KS + k0 + 4];
#pragma unroll
            for (int n8 = 0; n8 < 16; n8++) {
                int n = n8 * 8 + grp;
                mma8(acc[n8], a0, a1, a2, a3,
                     Wsm[n * X_KS + k0], Wsm[n * X_KS + k0 + 4]);
            }
        }
        /* epilogue: store x + fused attention scores */
        float ps0 = 0.f, pd0 = 0.f, ps1 = 0.f, pd1 = 0.f;
        int node0 = base + rlo, node1 = node0 + 8;
#pragma unroll
        for (int n8 = 0; n8 < 16; n8++) {
            int col = n8 * 8 + 2 * tg;
            float s0 = Asm[col], s1 = Asm[col + 1];
            float d0 = Asm[128 + col], d1 = Asm[128 + col + 1];
            ps0 += acc[n8][0] * s0 + acc[n8][1] * s1;
            pd0 += acc[n8][0] * d0 + acc[n8][1] * d1;
            ps1 += acc[n8][2] * s0 + acc[n8][3] * s1;
            pd1 += acc[n8][2] * d0 + acc[n8][3] * d1;
            if (node0 < N_NODES)
                *(float2*)&g_x[(long)node0 * 128 + col] = make_float2(acc[n8][0], acc[n8][1]);
            if (node1 < N_NODES)
                *(float2*)&g_x[(long)node1 * 128 + col] = make_float2(acc[n8][2], acc[n8][3]);
        }
#pragma unroll
        for (int o = 1; o <= 2; o <<= 1) {
            ps0 += __shfl_xor_sync(0xFFFFFFFFu, ps0, o);
            pd0 += __shfl_xor_sync(0xFFFFFFFFu, pd0, o);
            ps1 += __shfl_xor_sync(0xFFFFFFFFu, ps1, o);
            pd1 += __shfl_xor_sync(0xFFFFFFFFu, pd1, o);
        }
        if (tg == 0) {
            if (node0 < N_NODES) { g_as[node0] = ps0; g_ad[node0] = pd0; }
            if (node1 < N_NODES) { g_as[node1] = ps1; g_ad[node1] = pd1; }
        }
    }
}

/* ---------------- fused GAT softmax + aggregation: warp per node --------------
 * Single pass, no max-shift: score magnitudes are provably tiny (|e| << 80),
 * alpha = exp(e)/sum(exp(e)) is mathematically identical to the shifted form.
 */
__global__ void __launch_bounds__(256)
k_agg() {
    int gt = blockIdx.x * blockDim.x + threadIdx.x;
    int node = gt >> 5, lane = gt & 31;
    if (node >= N_NODES) return;
    const int start = g_off[node], end = g_pos[node];
    const float ad = g_ad[node];
    float e_self = g_as[node] + ad;
    e_self = (e_self > 0.f) ? e_self : 0.2f * e_self;

    const float w0 = expf(e_self);
    float4 xv = __ldg((const float4*)(g_x + (long)node * 128) + lane);
    float4 acc = make_float4(w0 * xv.x, w0 * xv.y, w0 * xv.z, w0 * xv.w);
    float den_l = 0.f;

    for (int b = start; b < end; b += 32) {
        int rem = end - b;
        int n = rem < 32 ? rem : 32;
        int  s_l = 0;
        float w_l = 0.f;
        if (lane < n) {
            s_l = __ldg(&g_csrs[b + lane]);
            float e = __ldg(&g_as[s_l]) + ad;
            e = (e > 0.f) ? e : 0.2f * e;
            w_l = expf(e);
            den_l += w_l;
        }
        for (int j = 0; j < n; j++) {
            int   s = __shfl_sync(0xFFFFFFFFu, s_l, j);
            float w = __shfl_sync(0xFFFFFFFFu, w_l, j);
            float4 v = __ldg((const float4*)(g_x + (long)s * 128) + lane);
            acc.x += w * v.x; acc.y += w * v.y; acc.z += w * v.z; acc.w += w * v.w;
        }
    }
#pragma unroll
    for (int o = 16; o; o >>= 1) den_l += __shfl_xor_sync(0xFFFFFFFFu, den_l, o);
    float inv = 1.f / (den_l + w0);
    acc.x *= inv; acc.y *= inv; acc.z *= inv; acc.w *= inv;
    ((float4*)(g_z + (long)node * 128))[lane] = acc;
}

/* ---------------- fused ReLU + classifier (tf32 tensor-core) ---------------- */
#define C_KS 132
__global__ void __launch_bounds__(256, 2)
k_cls(const float* __restrict__ cls_w, const float* __restrict__ cls_b,
      const float* __restrict__ gat_b, float* __restrict__ out) {
    extern __shared__ unsigned smu[];
    unsigned* Wsm = smu;                /* [64][132] tf32 */
    unsigned* Vsm = smu + 64 * C_KS;    /* [128][132] tf32 */
    float*    Cb  = (float*)(smu + (64 + 128) * C_KS);  /* cls_b[64] */
    const int tid = threadIdx.x;
    for (int i = tid; i < 64 * 128; i += 256) {
        int n = i >> 7, k = i & 127;
        Wsm[n * C_KS + k] = to_tf32(cls_w[n * 128 + k]);
    }
    if (tid < 64) Cb[tid] = cls_b[tid];
    const int warp = tid >> 5, lane = tid & 31;
    const int grp = lane >> 2, tg = lane & 3;
    __syncthreads();

    const int nch = (N_NODES + 127) / 128;
    for (int c = blockIdx.x; c < nch; c += gridDim.x) {
        const int base = c * 128;
        __syncthreads();
        for (int p = tid; p < 128 * 128; p += 256) {
            int nl = p >> 7, j = p & 127;
            int node = base + nl;
            float v = 0.f;
            if (node < N_NODES) {
                v = g_z[(long)node * 128 + j] + gat_b[j];
                v = (v > 0.f) ? v : 0.f;
            }
            Vsm[nl * C_KS + j] = to_tf32(v);
        }
        __syncthreads();

        float acc[8][4];
#pragma unroll
        for (int j = 0; j < 8; j++)
#pragma unroll
            for (int i = 0; i < 4; i++) acc[j][i] = 0.f;

        const int rlo = warp * 16 + grp;
#pragma unroll 1
        for (int k8 = 0; k8 < 16; k8++) {
            int k0 = k8 * 8 + tg;
            unsigned a0 = Vsm[rlo * C_KS + k0];
            unsigned a1 = Vsm[(rlo + 8) * C_KS + k0];
            unsigned a2 = Vsm[rlo * C_KS + k0 + 4];
            unsigned a3 = Vsm[(rlo + 8) * C_KS + k0 + 4];
#pragma unroll
            for (int n8 = 0; n8 < 8; n8++) {
                int n = n8 * 8 + grp;
                mma8(acc[n8], a0, a1, a2, a3,
                     Wsm[n * C_KS + k0], Wsm[n * C_KS + k0 + 4]);
            }
        }
        int node0 = base + rlo, node1 = node0 + 8;
#pragma unroll
        for (int n8 = 0; n8 < 8; n8++) {
            int col = n8 * 8 + 2 * tg;
            float b0 = Cb[col], b1 = Cb[col + 1];
            if (node0 < N_NODES)
                *(float2*)&out[(long)node0 * 64 + col] =
                    make_float2(acc[n8][0] + b0, acc[n8][1] + b1);
            if (node1 < N_NODES)
                *(float2*)&out[(long)node1 * 64 + col] =
                    make_float2(acc[n8][2] + b0, acc[n8][3] + b1);
        }
    }
}

/* ---------------- launch ----------------
 * Order keeps k_gru at launch #4 so the fixed ncu window profiles it.
 */
extern "C" void kernel_launch(void* const* d_in, const int* in_sizes, int n_in,
                              void* d_out, int out_size) {
    const int*   src    = (const int*)  d_in[0];
    const int*   dst    = (const int*)  d_in[1];
    const int*   t      = (const int*)  d_in[2];
    const float* msg    = (const float*)d_in[3];
    const int*   sei    = (const int*)  d_in[4];
    const float* time_w = (const float*)d_in[5];
    const float* time_b = (const float*)d_in[6];
    const float* w_ih   = (const float*)d_in[7];
    /* d_in[8] = gru_w_hh: unused (memory == 0 at update time) */
    const float* b_ih   = (const float*)d_in[9];
    const float* b_hh   = (const float*)d_in[10];
    const float* gat_w  = (const float*)d_in[11];
    const float* att_s  = (const float*)d_in[12];
    const float* att_d  = (const float*)d_in[13];
    const float* gat_b  = (const float*)d_in[14];
    const float* cls_w  = (const float*)d_in[15];
    const float* cls_b  = (const float*)d_in[16];
    float* out = (float*)d_out;
    const int* es = sei;
    const int* ed = sei + N_SEDGE;
    (void)in_sizes; (void)n_in; (void)out_size;

    k_init <<<(N_NODES + 255) / 256, 256>>>();
    k_last <<<(N_EV + 255) / 256, 256>>>(src, dst);
    k_count<<<(N_SEDGE + 255) / 256, 256>>>(ed);

    {
        size_t smb = (size_t)GRU_WFRAGS * 8 + (512 + 64) * 4;
        cudaFuncSetAttribute(k_gru, cudaFuncAttributeMaxDynamicSharedMemorySize, (int)smb);
        k_gru<<<148, 512, smb>>>(t, msg, w_ih, b_ih, b_hh, time_w, time_b);
    }
    {
        size_t smb = (size_t)(2 * 128 * X_KS) * 4 + 256 * 4;
        cudaFuncSetAttribute(k_gatx, cudaFuncAttributeMaxDynamicSharedMemorySize, (int)smb);
        k_gatx<<<148, 256, smb>>>(gat_w, att_s, att_d);
    }

    k_scanA<<<SNBLK, 256>>>();
    k_scanB<<<1, 128>>>();
    k_scanC<<<SNBLK, 256>>>();
    k_fill <<<(N_SEDGE + 255) / 256, 256>>>(es, ed);

    k_agg <<<(N_NODES * 32 + 255) / 256, 256>>>();
    {
        size_t smb = (size_t)((64 + 128) * C_KS) * 4 + 64 * 4;
        cudaFuncSetAttribute(k_cls, cudaFuncAttributeMaxDynamicSharedMemorySize, (int)smb);
        k_cls<<<296, 256, smb>>>(cls_w, cls_b, gat_b, out);
    }
}

// round 12
// speedup vs baseline: 4.4875x; 1.2159x over previous
#include <cuda_runtime.h>
#include <cuda_fp16.h>
#include <math.h>

#define N_NODES 100000
#define N_EV    200000
#define N_SEDGE 1600000
#define SCHUNK  1024
#define SNBLK   ((N_NODES + SCHUNK - 1) / SCHUNK)

/* ---------------- device scratch (no allocations allowed) ---------------- */
__device__ __align__(16) int    g_last[N_NODES];
__device__ __align__(16) float  g_mem [N_NODES * 128];
__device__ __align__(16) __half g_xh  [N_NODES * 128];
__device__ __align__(16) float  g_as  [N_NODES];
__device__ __align__(16) float  g_ad  [N_NODES];
__device__ __align__(16) float  g_z   [N_NODES * 128];
__device__ __align__(16) int    g_cnt [N_NODES];
__device__ __align__(16) int    g_off [N_NODES];
__device__ __align__(16) int    g_pos [N_NODES];
__device__               int    g_part[SNBLK];
__device__ __align__(16) int    g_csrs[N_SEDGE];

/* ---------------- tf32 MMA helpers ---------------- */
__device__ __forceinline__ unsigned to_tf32(float f) {
    unsigned r; asm("cvt.rna.tf32.f32 %0,%1;" : "=r"(r) : "f"(f)); return r;
}
__device__ __forceinline__ void mma8(float (&c)[4], unsigned a0, unsigned a1,
                                     unsigned a2, unsigned a3,
                                     unsigned b0, unsigned b1) {
    asm("mma.sync.aligned.m16n8k8.row.col.f32.tf32.tf32.f32 "
        "{%0,%1,%2,%3},{%4,%5,%6,%7},{%8,%9},{%0,%1,%2,%3};"
        : "+f"(c[0]), "+f"(c[1]), "+f"(c[2]), "+f"(c[3])
        : "r"(a0), "r"(a1), "r"(a2), "r"(a3), "r"(b0), "r"(b1));
}
__device__ __forceinline__ float sigmoidf_(float x) {
    return 1.f / (1.f + expf(-x));
}

/* ---------------- init ---------------- */
__global__ void k_init() {
    int i = blockIdx.x * blockDim.x + threadIdx.x;
    if (i < N_NODES) { g_last[i] = -1; g_cnt[i] = 0; }
}

/* ---------------- last event per node ---------------- */
__global__ void k_last(const int* __restrict__ src, const int* __restrict__ dst) {
    int i = blockIdx.x * blockDim.x + threadIdx.x;
    if (i >= N_EV) return;
    atomicMax(&g_last[src[i]], i);
    atomicMax(&g_last[dst[i]], i);
}

/* ---------------- CSR build: count / scan / fill ---------------- */
__global__ void k_count(const int* __restrict__ ed) {
    int i = blockIdx.x * blockDim.x + threadIdx.x;
    if (i < N_SEDGE) atomicAdd(&g_cnt[ed[i]], 1);
}

__global__ void k_scanA() {
    int b = blockIdx.x, t = threadIdx.x;
    int base = b * SCHUNK + t * 4;
    int s = 0;
#pragma unroll
    for (int u = 0; u < 4; u++) { int i = base + u; if (i < N_NODES) s += g_cnt[i]; }
#pragma unroll
    for (int o = 16; o; o >>= 1) s += __shfl_xor_sync(0xFFFFFFFFu, s, o);
    __shared__ int ws[8];
    if ((t & 31) == 0) ws[t >> 5] = s;
    __syncthreads();
    if (t == 0) { int tot = 0; for (int w = 0; w < 8; w++) tot += ws[w]; g_part[b] = tot; }
}

__global__ void k_scanB() {
    int t = threadIdx.x;
    int v = (t < SNBLK) ? g_part[t] : 0;
    int lane = t & 31, wid = t >> 5;
    int inc = v;
#pragma unroll
    for (int o = 1; o < 32; o <<= 1) { int n = __shfl_up_sync(0xFFFFFFFFu, inc, o); if (lane >= o) inc += n; }
    __shared__ int ws[4];
    if (lane == 31) ws[wid] = inc;
    __syncthreads();
    if (t == 0) { int r = 0; for (int i = 0; i < 4; i++) { int x = ws[i]; ws[i] = r; r += x; } }
    __syncthreads();
    if (t < SNBLK) g_part[t] = inc - v + ws[wid];
}

__global__ void k_scanC() {
    int b = blockIdx.x, t = threadIdx.x;
    int base = b * SCHUNK + t * 4;
    int c[4]; int s = 0;
#pragma unroll
    for (int u = 0; u < 4; u++) { int i = base + u; c[u] = (i < N_NODES) ? g_cnt[i] : 0; s += c[u]; }
    int lane = t & 31, wid = t >> 5;
    int inc = s;
#pragma unroll
    for (int o = 1; o < 32; o <<= 1) { int n = __shfl_up_sync(0xFFFFFFFFu, inc, o); if (lane >= o) inc += n; }
    __shared__ int ws[8];
    if (lane == 31) ws[wid] = inc;
    __syncthreads();
    if (t == 0) { int r = 0; for (int i = 0; i < 8; i++) { int x = ws[i]; ws[i] = r; r += x; } }
    __syncthreads();
    int off = g_part[b] + ws[wid] + inc - s;
#pragma unroll
    for (int u = 0; u < 4; u++) {
        int i = base + u;
        if (i < N_NODES) { g_off[i] = off; g_pos[i] = off; }
        off += c[u];
    }
}

__global__ void k_fill(const int* __restrict__ es, const int* __restrict__ ed) {
    int i = blockIdx.x * blockDim.x + threadIdx.x;
    if (i >= N_SEDGE) return;
    int pos = atomicAdd(&g_pos[ed[i]], 1);
    g_csrs[pos] = es[i];
}

/* ---------------- fused GRU memory update (tf32 MMA, reg-resident A) ---------
 * memory==0: gi uses only W_ih[:,256:352]; gh = b_hh; h = (1-z)*n.
 * 512 thr/block, warp-per-16-rows grid-stride (100000 = 6250*16, exact).
 */
#define GRU_WFRAGS (8 * 12 * 6 * 32)   /* uint2 entries = 147456 B */
__global__ void __launch_bounds__(512, 1)
k_gru(const int* __restrict__ t, const float* __restrict__ msg,
      const float* __restrict__ w_ih, const float* __restrict__ b_ih,
      const float* __restrict__ b_hh,
      const float* __restrict__ time_w, const float* __restrict__ time_b) {
    extern __shared__ unsigned smu[];
    uint2* Wf  = (uint2*)smu;                 /* [pass][k8][tile6][lane] */
    float* Bsm = (float*)(Wf + GRU_WFRAGS);   /* r,z,n_in,n_hh biases 4*128 */
    float* Tw  = Bsm + 512;
    float* Tb  = Tw + 32;
    const int tid = threadIdx.x;

    for (int i = tid; i < GRU_WFRAGS; i += 512) {
        int lane = i & 31, rest = i >> 5;
        int t6 = rest % 6; rest /= 6;
        int k8 = rest % 12;
        int p  = rest / 12;
        int g = t6 >> 1, jj = t6 & 1;
        int n8 = g * 16 + p * 2 + jj;
        int n = n8 * 8 + (lane >> 2);
        int k = k8 * 8 + (lane & 3);
        const float* wr = w_ih + n * 352 + 256 + k;
        Wf[i] = make_uint2(to_tf32(wr[0]), to_tf32(wr[4]));
    }
    for (int k = tid; k < 128; k += 512) {
        Bsm[k]       = b_ih[k]       + b_hh[k];
        Bsm[128 + k] = b_ih[128 + k] + b_hh[128 + k];
        Bsm[256 + k] = b_ih[256 + k];
        Bsm[384 + k] = b_hh[256 + k];
    }
    if (tid < 32) { Tw[tid] = time_w[tid]; Tb[tid] = time_b[tid]; }
    __syncthreads();

    const int warp = tid >> 5, lane = tid & 31;
    const int grp = lane >> 2, tg = lane & 3;
    const int nwarps = gridDim.x * 16;

    for (int rg = blockIdx.x * 16 + warp; rg < N_NODES / 16; rg += nwarps) {
        const int node0 = rg * 16 + grp, node1 = node0 + 8;
        const int le0 = g_last[node0], le1 = g_last[node1];
        const bool h0 = le0 >= 0, h1 = le1 >= 0;
        const float tf0 = h0 ? (float)t[le0] : 0.f;
        const float tf1 = h1 ? (float)t[le1] : 0.f;
        const float* m0 = msg + (long)(h0 ? le0 : 0) * 64;
        const float* m1 = msg + (long)(h1 ? le1 : 0) * 64;

        unsigned a[12][4];
#pragma unroll
        for (int k8 = 0; k8 < 8; k8++) {
            int c0 = k8 * 8 + tg, c1 = c0 + 4;
            a[k8][0] = h0 ? to_tf32(__ldg(&m0[c0])) : 0u;
            a[k8][1] = h1 ? to_tf32(__ldg(&m1[c0])) : 0u;
            a[k8][2] = h0 ? to_tf32(__ldg(&m0[c1])) : 0u;
            a[k8][3] = h1 ? to_tf32(__ldg(&m1[c1])) : 0u;
        }
#pragma unroll
        for (int k8 = 8; k8 < 12; k8++) {
            int j0 = k8 * 8 + tg - 64, j1 = j0 + 4;
            float w0 = Tw[j0], bb0 = Tb[j0], w1 = Tw[j1], bb1 = Tb[j1];
            a[k8][0] = h0 ? to_tf32(cosf(__fadd_rn(__fmul_rn(tf0, w0), bb0))) : 0u;
            a[k8][1] = h1 ? to_tf32(cosf(__fadd_rn(__fmul_rn(tf1, w0), bb0))) : 0u;
            a[k8][2] = h0 ? to_tf32(cosf(__fadd_rn(__fmul_rn(tf0, w1), bb1))) : 0u;
            a[k8][3] = h1 ? to_tf32(cosf(__fadd_rn(__fmul_rn(tf1, w1), bb1))) : 0u;
        }

#pragma unroll 1
        for (int p = 0; p < 8; p++) {
            float acc[6][4];
#pragma unroll
            for (int q = 0; q < 6; q++)
#pragma unroll
                for (int i = 0; i < 4; i++) acc[q][i] = 0.f;

#pragma unroll
            for (int k8 = 0; k8 < 12; k8++) {
                const uint2* wp = Wf + ((p * 12 + k8) * 6) * 32 + lane;
#pragma unroll
                for (int t6 = 0; t6 < 6; t6++) {
                    uint2 b = wp[t6 * 32];
                    mma8(acc[t6], a[k8][0], a[k8][1], a[k8][2], a[k8][3], b.x, b.y);
                }
            }
#pragma unroll
            for (int jj = 0; jj < 2; jj++) {
                int kbase = (p * 2 + jj) * 8 + 2 * tg;
                float o0[2], o1[2];
#pragma unroll
                for (int ii = 0; ii < 2; ii++) {
                    int kk = kbase + ii;
                    float br = Bsm[kk], bz = Bsm[128 + kk];
                    float bin = Bsm[256 + kk], bhn = Bsm[384 + kk];
                    {
                        float r = sigmoidf_(acc[jj][ii] + br);
                        float z = sigmoidf_(acc[2 + jj][ii] + bz);
                        float nn = tanhf(acc[4 + jj][ii] + bin + r * bhn);
                        o0[ii] = h0 ? (1.f - z) * nn : 0.f;
                    }
                    {
                        float r = sigmoidf_(acc[jj][2 + ii] + br);
                        float z = sigmoidf_(acc[2 + jj][2 + ii] + bz);
                        float nn = tanhf(acc[4 + jj][2 + ii] + bin + r * bhn);
                        o1[ii] = h1 ? (1.f - z) * nn : 0.f;
                    }
                }
                *(float2*)&g_mem[(long)node0 * 128 + kbase] = make_float2(o0[0], o0[1]);
                *(float2*)&g_mem[(long)node1 * 128 + kbase] = make_float2(o1[0], o1[1]);
            }
        }
    }
}

/* ---------------- GAT projection + attention scores (reg-resident A) ---------
 * x = mem @ W^T emitted as fp16 (g_xh, consumed only by k_agg gather);
 * attention scores a_s/a_d computed in fp32 from the accumulators.
 */
#define XW_FRAGS (16 * 16 * 32)   /* uint2 = 64 KB */
__global__ void __launch_bounds__(512, 1)
k_gatx(const float* __restrict__ gat_w, const float* __restrict__ att_src,
       const float* __restrict__ att_dst) {
    extern __shared__ unsigned smu[];
    uint2* Wf  = (uint2*)smu;                /* [k8][n8][lane] */
    float* Asm = (float*)(Wf + XW_FRAGS);    /* att_src[128], att_dst[128] */
    const int tid = threadIdx.x;

    for (int i = tid; i < XW_FRAGS; i += 512) {
        int lane = i & 31, rest = i >> 5;
        int n8 = rest & 15, k8 = rest >> 4;
        int n = n8 * 8 + (lane >> 2);
        int k = k8 * 8 + (lane & 3);
        Wf[i] = make_uint2(to_tf32(gat_w[n * 128 + k]), to_tf32(gat_w[n * 128 + k + 4]));
    }
    if (tid < 256) Asm[tid] = (tid < 128) ? att_src[tid] : att_dst[tid - 128];
    __syncthreads();

    const int warp = tid >> 5, lane = tid & 31;
    const int grp = lane >> 2, tg = lane & 3;
    const int nwarps = gridDim.x * 16;

    for (int rg = blockIdx.x * 16 + warp; rg < N_NODES / 16; rg += nwarps) {
        const int node0 = rg * 16 + grp, node1 = node0 + 8;
        const float* r0 = g_mem + (long)node0 * 128;
        const float* r1 = g_mem + (long)node1 * 128;

        unsigned a[16][4];
#pragma unroll
        for (int k8 = 0; k8 < 16; k8++) {
            int c0 = k8 * 8 + tg;
            a[k8][0] = to_tf32(__ldg(r0 + c0));
            a[k8][1] = to_tf32(__ldg(r1 + c0));
            a[k8][2] = to_tf32(__ldg(r0 + c0 + 4));
            a[k8][3] = to_tf32(__ldg(r1 + c0 + 4));
        }

        float ps0 = 0.f, pd0 = 0.f, ps1 = 0.f, pd1 = 0.f;
#pragma unroll 1
        for (int h = 0; h < 2; h++) {
            float acc[8][4];
#pragma unroll
            for (int q = 0; q < 8; q++)
#pragma unroll
                for (int i = 0; i < 4; i++) acc[q][i] = 0.f;

#pragma unroll
            for (int k8 = 0; k8 < 16; k8++) {
                const uint2* wp = Wf + (k8 * 16 + h * 8) * 32 + lane;
#pragma unroll
                for (int n8 = 0; n8 < 8; n8++) {
                    uint2 b = wp[n8 * 32];
                    mma8(acc[n8], a[k8][0], a[k8][1], a[k8][2], a[k8][3], b.x, b.y);
                }
            }
#pragma unroll
            for (int n8 = 0; n8 < 8; n8++) {
                int col = (h * 8 + n8) * 8 + 2 * tg;
                float s0 = Asm[col], s1 = Asm[col + 1];
                float d0 = Asm[128 + col], d1 = Asm[128 + col + 1];
                ps0 += acc[n8][0] * s0 + acc[n8][1] * s1;
                pd0 += acc[n8][0] * d0 + acc[n8][1] * d1;
                ps1 += acc[n8][2] * s0 + acc[n8][3] * s1;
                pd1 += acc[n8][2] * d0 + acc[n8][3] * d1;
                *(__half2*)&g_xh[(long)node0 * 128 + col] =
                    __floats2half2_rn(acc[n8][0], acc[n8][1]);
                *(__half2*)&g_xh[(long)node1 * 128 + col] =
                    __floats2half2_rn(acc[n8][2], acc[n8][3]);
            }
        }
#pragma unroll
        for (int o = 1; o <= 2; o <<= 1) {
            ps0 += __shfl_xor_sync(0xFFFFFFFFu, ps0, o);
            pd0 += __shfl_xor_sync(0xFFFFFFFFu, pd0, o);
            ps1 += __shfl_xor_sync(0xFFFFFFFFu, ps1, o);
            pd1 += __shfl_xor_sync(0xFFFFFFFFu, pd1, o);
        }
        if (tg == 0) {
            g_as[node0] = ps0; g_ad[node0] = pd0;
            g_as[node1] = ps1; g_ad[node1] = pd1;
        }
    }
}

/* ---------------- fused GAT softmax + aggregation: warp per node --------------
 * Single pass, no max-shift (scores provably tiny). x gathered as fp16
 * (halves L2 traffic); alpha/den stay fp32. Lane owns cols lane*4..lane*4+3.
 */
__global__ void __launch_bounds__(256)
k_agg() {
    int gt = blockIdx.x * blockDim.x + threadIdx.x;
    int node = gt >> 5, lane = gt & 31;
    if (node >= N_NODES) return;
    const int start = g_off[node], end = g_pos[node];
    const float ad = g_ad[node];
    float e_self = g_as[node] + ad;
    e_self = (e_self > 0.f) ? e_self : 0.2f * e_self;

    const float w0 = expf(e_self);
    uint2 raw = __ldg((const uint2*)(g_xh + (long)node * 128) + lane);
    float2 lo = __half22float2(*(__half2*)&raw.x);
    float2 hi = __half22float2(*(__half2*)&raw.y);
    float4 acc = make_float4(w0 * lo.x, w0 * lo.y, w0 * hi.x, w0 * hi.y);
    float den_l = 0.f;

    for (int b = start; b < end; b += 32) {
        int rem = end - b;
        int n = rem < 32 ? rem : 32;
        int  s_l = 0;
        float w_l = 0.f;
        if (lane < n) {
            s_l = __ldg(&g_csrs[b + lane]);
            float e = __ldg(&g_as[s_l]) + ad;
            e = (e > 0.f) ? e : 0.2f * e;
            w_l = expf(e);
            den_l += w_l;
        }
        for (int j = 0; j < n; j++) {
            int   s = __shfl_sync(0xFFFFFFFFu, s_l, j);
            float w = __shfl_sync(0xFFFFFFFFu, w_l, j);
            uint2 r = __ldg((const uint2*)(g_xh + (long)s * 128) + lane);
            float2 l2 = __half22float2(*(__half2*)&r.x);
            float2 h2 = __half22float2(*(__half2*)&r.y);
            acc.x += w * l2.x; acc.y += w * l2.y;
            acc.z += w * h2.x; acc.w += w * h2.y;
        }
    }
#pragma unroll
    for (int o = 16; o; o >>= 1) den_l += __shfl_xor_sync(0xFFFFFFFFu, den_l, o);
    float inv = 1.f / (den_l + w0);
    acc.x *= inv; acc.y *= inv; acc.z *= inv; acc.w *= inv;
    ((float4*)(g_z + (long)node * 128))[lane] = acc;
}

/* ---------------- fused ReLU + classifier (reg-resident A) ---------------- */
#define CW_FRAGS (16 * 8 * 32)   /* uint2 = 32 KB */
__global__ void __launch_bounds__(512, 1)
k_cls(const float* __restrict__ cls_w, const float* __restrict__ cls_b,
      const float* __restrict__ gat_b, float* __restrict__ out) {
    extern __shared__ unsigned smu[];
    uint2* Wf = (uint2*)smu;               /* [k8][n8][lane] */
    float* Cb = (float*)(Wf + CW_FRAGS);   /* cls_b[64] */
    float* Gb = Cb + 64;                   /* gat_b[128] */
    const int tid = threadIdx.x;

    for (int i = tid; i < CW_FRAGS; i += 512) {
        int lane = i & 31, rest = i >> 5;
        int n8 = rest & 7, k8 = rest >> 3;
        int n = n8 * 8 + (lane >> 2);
        int k = k8 * 8 + (lane & 3);
        Wf[i] = make_uint2(to_tf32(cls_w[n * 128 + k]), to_tf32(cls_w[n * 128 + k + 4]));
    }
    if (tid < 64) Cb[tid] = cls_b[tid];
    if (tid < 128) Gb[tid] = gat_b[tid];
    __syncthreads();

    const int warp = tid >> 5, lane = tid & 31;
    const int grp = lane >> 2, tg = lane & 3;
    const int nwarps = gridDim.x * 16;

    for (int rg = blockIdx.x * 16 + warp; rg < N_NODES / 16; rg += nwarps) {
        const int node0 = rg * 16 + grp, node1 = node0 + 8;
        const float* r0 = g_z + (long)node0 * 128;
        const float* r1 = g_z + (long)node1 * 128;

        unsigned a[16][4];
#pragma unroll
        for (int k8 = 0; k8 < 16; k8++) {
            int c0 = k8 * 8 + tg, c1 = c0 + 4;
            float b0 = Gb[c0], b1 = Gb[c1];
            float v;
            v = __ldg(r0 + c0) + b0; a[k8][0] = to_tf32(v > 0.f ? v : 0.f);
            v = __ldg(r1 + c0) + b0; a[k8][1] = to_tf32(v > 0.f ? v : 0.f);
            v = __ldg(r0 + c1) + b1; a[k8][2] = to_tf32(v > 0.f ? v : 0.f);
            v = __ldg(r1 + c1) + b1; a[k8][3] = to_tf32(v > 0.f ? v : 0.f);
        }

        float acc[8][4];
#pragma unroll
        for (int q = 0; q < 8; q++)
#pragma unroll
            for (int i = 0; i < 4; i++) acc[q][i] = 0.f;

#pragma unroll
        for (int k8 = 0; k8 < 16; k8++) {
            const uint2* wp = Wf + (k8 * 8) * 32 + lane;
#pragma unroll
            for (int n8 = 0; n8 < 8; n8++) {
                uint2 b = wp[n8 * 32];
                mma8(acc[n8], a[k8][0], a[k8][1], a[k8][2], a[k8][3], b.x, b.y);
            }
        }
#pragma unroll
        for (int n8 = 0; n8 < 8; n8++) {
            int col = n8 * 8 + 2 * tg;
            float b0 = Cb[col], b1 = Cb[col + 1];
            *(float2*)&out[(long)node0 * 64 + col] =
                make_float2(acc[n8][0] + b0, acc[n8][1] + b1);
            *(float2*)&out[(long)node1 * 64 + col] =
                make_float2(acc[n8][2] + b0, acc[n8][3] + b1);
        }
    }
}

/* ---------------- launch ----------------
 * Order puts k_gatx at launch #4 so the fixed ncu window profiles it.
 * (CSR build is independent of the GEMM chain; k_agg needs both.)
 */
extern "C" void kernel_launch(void* const* d_in, const int* in_sizes, int n_in,
                              void* d_out, int out_size) {
    const int*   src    = (const int*)  d_in[0];
    const int*   dst    = (const int*)  d_in[1];
    const int*   t      = (const int*)  d_in[2];
    const float* msg    = (const float*)d_in[3];
    const int*   sei    = (const int*)  d_in[4];
    const float* time_w = (const float*)d_in[5];
    const float* time_b = (const float*)d_in[6];
    const float* w_ih   = (const float*)d_in[7];
    /* d_in[8] = gru_w_hh: unused (memory == 0 at update time) */
    const float* b_ih   = (const float*)d_in[9];
    const float* b_hh   = (const float*)d_in[10];
    const float* gat_w  = (const float*)d_in[11];
    const float* att_s  = (const float*)d_in[12];
    const float* att_d  = (const float*)d_in[13];
    const float* gat_b  = (const float*)d_in[14];
    const float* cls_w  = (const float*)d_in[15];
    const float* cls_b  = (const float*)d_in[16];
    float* out = (float*)d_out;
    const int* es = sei;
    const int* ed = sei + N_SEDGE;
    (void)in_sizes; (void)n_in; (void)out_size;

    k_init <<<(N_NODES + 255) / 256, 256>>>();
    k_last <<<(N_EV + 255) / 256, 256>>>(src, dst);

    {
        size_t smb = (size_t)GRU_WFRAGS * 8 + (512 + 64) * 4;
        cudaFuncSetAttribute(k_gru, cudaFuncAttributeMaxDynamicSharedMemorySize, (int)smb);
        k_gru<<<148, 512, smb>>>(t, msg, w_ih, b_ih, b_hh, time_w, time_b);
    }
    {
        size_t smb = (size_t)XW_FRAGS * 8 + 256 * 4;
        cudaFuncSetAttribute(k_gatx, cudaFuncAttributeMaxDynamicSharedMemorySize, (int)smb);
        k_gatx<<<148, 512, smb>>>(gat_w, att_s, att_d);
    }

    k_count<<<(N_SEDGE + 255) / 256, 256>>>(ed);
    k_scanA<<<SNBLK, 256>>>();
    k_scanB<<<1, 128>>>();
    k_scanC<<<SNBLK, 256>>>();
    k_fill <<<(N_SEDGE + 255) / 256, 256>>>(es, ed);

    k_agg <<<(N_NODES * 32 + 255) / 256, 256>>>();
    {
        size_t smb = (size_t)CW_FRAGS * 8 + 192 * 4;
        cudaFuncSetAttribute(k_cls, cudaFuncAttributeMaxDynamicSharedMemorySize, (int)smb);
        k_cls<<<148, 512, smb>>>(cls_w, cls_b, gat_b, out);
    }
}

// round 13
// speedup vs baseline: 5.1495x; 1.1475x over previous
#include <cuda_runtime.h>
#include <cuda_fp16.h>
#include <math.h>

#define N_NODES 100000
#define N_EV    200000
#define N_SEDGE 1600000
#define SCHUNK  1024
#define SNBLK   ((N_NODES + SCHUNK - 1) / SCHUNK)

/* ---------------- device scratch (no allocations allowed) ---------------- */
__device__ __align__(16) int    g_last[N_NODES];
__device__ __align__(16) float  g_mem [N_NODES * 128];
__device__ __align__(16) __half g_xh  [N_NODES * 128];
__device__ __align__(16) float  g_as  [N_NODES];
__device__ __align__(16) float  g_ad  [N_NODES];
__device__ __align__(16) float  g_z   [N_NODES * 128];
__device__ __align__(16) int    g_cnt [N_NODES];
__device__ __align__(16) int    g_off [N_NODES];
__device__ __align__(16) int    g_pos [N_NODES];
__device__               int    g_part[SNBLK];
__device__ __align__(16) int    g_csrs[N_SEDGE];

/* ---------------- tf32 MMA helpers ---------------- */
__device__ __forceinline__ unsigned to_tf32(float f) {
    unsigned r; asm("cvt.rna.tf32.f32 %0,%1;" : "=r"(r) : "f"(f)); return r;
}
__device__ __forceinline__ void mma8(float (&c)[4], unsigned a0, unsigned a1,
                                     unsigned a2, unsigned a3,
                                     unsigned b0, unsigned b1) {
    asm("mma.sync.aligned.m16n8k8.row.col.f32.tf32.tf32.f32 "
        "{%0,%1,%2,%3},{%4,%5,%6,%7},{%8,%9},{%0,%1,%2,%3};"
        : "+f"(c[0]), "+f"(c[1]), "+f"(c[2]), "+f"(c[3])
        : "r"(a0), "r"(a1), "r"(a2), "r"(a3), "r"(b0), "r"(b1));
}
/* fast transcendentals: rel err ~1e-6, saturate correctly at +-inf */
__device__ __forceinline__ float fsig(float x) {
    return __fdividef(1.f, 1.f + __expf(-x));
}
__device__ __forceinline__ float ftanh_(float x) {
    return 1.f - __fdividef(2.f, __expf(2.f * x) + 1.f);
}

/* ---------------- init ---------------- */
__global__ void k_init_last() {
    int i = blockIdx.x * blockDim.x + threadIdx.x;
    if (i < N_NODES) g_last[i] = -1;
}
__global__ void k_init_cnt() {
    int i = blockIdx.x * blockDim.x + threadIdx.x;
    if (i < N_NODES) g_cnt[i] = 0;
}

/* ---------------- last event per node ---------------- */
__global__ void k_last(const int* __restrict__ src, const int* __restrict__ dst) {
    int i = blockIdx.x * blockDim.x + threadIdx.x;
    if (i >= N_EV) return;
    atomicMax(&g_last[src[i]], i);
    atomicMax(&g_last[dst[i]], i);
}

/* ---------------- CSR build: count / scan / fill ---------------- */
__global__ void k_count(const int* __restrict__ ed) {
    int i = blockIdx.x * blockDim.x + threadIdx.x;
    if (i < N_SEDGE) atomicAdd(&g_cnt[ed[i]], 1);
}

__global__ void k_scanA() {
    int b = blockIdx.x, t = threadIdx.x;
    int base = b * SCHUNK + t * 4;
    int s = 0;
#pragma unroll
    for (int u = 0; u < 4; u++) { int i = base + u; if (i < N_NODES) s += g_cnt[i]; }
#pragma unroll
    for (int o = 16; o; o >>= 1) s += __shfl_xor_sync(0xFFFFFFFFu, s, o);
    __shared__ int ws[8];
    if ((t & 31) == 0) ws[t >> 5] = s;
    __syncthreads();
    if (t == 0) { int tot = 0; for (int w = 0; w < 8; w++) tot += ws[w]; g_part[b] = tot; }
}

__global__ void k_scanB() {
    int t = threadIdx.x;
    int v = (t < SNBLK) ? g_part[t] : 0;
    int lane = t & 31, wid = t >> 5;
    int inc = v;
#pragma unroll
    for (int o = 1; o < 32; o <<= 1) { int n = __shfl_up_sync(0xFFFFFFFFu, inc, o); if (lane >= o) inc += n; }
    __shared__ int ws[4];
    if (lane == 31) ws[wid] = inc;
    __syncthreads();
    if (t == 0) { int r = 0; for (int i = 0; i < 4; i++) { int x = ws[i]; ws[i] = r; r += x; } }
    __syncthreads();
    if (t < SNBLK) g_part[t] = inc - v + ws[wid];
}

__global__ void k_scanC() {
    int b = blockIdx.x, t = threadIdx.x;
    int base = b * SCHUNK + t * 4;
    int c[4]; int s = 0;
#pragma unroll
    for (int u = 0; u < 4; u++) { int i = base + u; c[u] = (i < N_NODES) ? g_cnt[i] : 0; s += c[u]; }
    int lane = t & 31, wid = t >> 5;
    int inc = s;
#pragma unroll
    for (int o = 1; o < 32; o <<= 1) { int n = __shfl_up_sync(0xFFFFFFFFu, inc, o); if (lane >= o) inc += n; }
    __shared__ int ws[8];
    if (lane == 31) ws[wid] = inc;
    __syncthreads();
    if (t == 0) { int r = 0; for (int i = 0; i < 8; i++) { int x = ws[i]; ws[i] = r; r += x; } }
    __syncthreads();
    int off = g_part[b] + ws[wid] + inc - s;
#pragma unroll
    for (int u = 0; u < 4; u++) {
        int i = base + u;
        if (i < N_NODES) { g_off[i] = off; g_pos[i] = off; }
        off += c[u];
    }
}

__global__ void k_fill(const int* __restrict__ es, const int* __restrict__ ed) {
    int i = blockIdx.x * blockDim.x + threadIdx.x;
    if (i >= N_SEDGE) return;
    int pos = atomicAdd(&g_pos[ed[i]], 1);
    g_csrs[pos] = es[i];
}

/* ---------------- fused GRU memory update (tf32 MMA, reg-resident A) ---------
 * W fragments packed per-lane-contiguous: 48 B/lane per (p,k8) -> 3x LDS.128.
 * (lane stride 48 B = 12 words: 8-lane phase hits distinct banks.)
 */
#define GRU_WENT (8 * 12 * 32 * 6)   /* uint2 entries = 147456 B */
__global__ void __launch_bounds__(512, 1)
k_gru(const int* __restrict__ t, const float* __restrict__ msg,
      const float* __restrict__ w_ih, const float* __restrict__ b_ih,
      const float* __restrict__ b_hh,
      const float* __restrict__ time_w, const float* __restrict__ time_b) {
    extern __shared__ unsigned smu[];
    uint2* Wf  = (uint2*)smu;                 /* [p][k8][lane][t6] */
    float* Bsm = (float*)(Wf + GRU_WENT);
    float* Tw  = Bsm + 512;
    float* Tb  = Tw + 32;
    const int tid = threadIdx.x;

    for (int i = tid; i < GRU_WENT; i += 512) {
        int t6 = i % 6;
        int lane = (i / 6) & 31;
        int k8 = (i / 192) % 12;
        int p  = i / 2304;
        int g = t6 >> 1, jj = t6 & 1;
        int n8 = g * 16 + p * 2 + jj;
        int n = n8 * 8 + (lane >> 2);
        int k = k8 * 8 + (lane & 3);
        const float* wr = w_ih + n * 352 + 256 + k;
        Wf[i] = make_uint2(to_tf32(wr[0]), to_tf32(wr[4]));
    }
    for (int k = tid; k < 128; k += 512) {
        Bsm[k]       = b_ih[k]       + b_hh[k];
        Bsm[128 + k] = b_ih[128 + k] + b_hh[128 + k];
        Bsm[256 + k] = b_ih[256 + k];
        Bsm[384 + k] = b_hh[256 + k];
    }
    if (tid < 32) { Tw[tid] = time_w[tid]; Tb[tid] = time_b[tid]; }
    __syncthreads();

    const int warp = tid >> 5, lane = tid & 31;
    const int grp = lane >> 2, tg = lane & 3;
    const int nwarps = gridDim.x * 16;

    for (int rg = blockIdx.x * 16 + warp; rg < N_NODES / 16; rg += nwarps) {
        const int node0 = rg * 16 + grp, node1 = node0 + 8;
        const int le0 = g_last[node0], le1 = g_last[node1];
        const bool h0 = le0 >= 0, h1 = le1 >= 0;
        const float tf0 = h0 ? (float)t[le0] : 0.f;
        const float tf1 = h1 ? (float)t[le1] : 0.f;
        const float* m0 = msg + (long)(h0 ? le0 : 0) * 64;
        const float* m1 = msg + (long)(h1 ? le1 : 0) * 64;

        unsigned a[12][4];
#pragma unroll
        for (int k8 = 0; k8 < 8; k8++) {
            int c0 = k8 * 8 + tg, c1 = c0 + 4;
            a[k8][0] = h0 ? to_tf32(__ldg(&m0[c0])) : 0u;
            a[k8][1] = h1 ? to_tf32(__ldg(&m1[c0])) : 0u;
            a[k8][2] = h0 ? to_tf32(__ldg(&m0[c1])) : 0u;
            a[k8][3] = h1 ? to_tf32(__ldg(&m1[c1])) : 0u;
        }
#pragma unroll
        for (int k8 = 8; k8 < 12; k8++) {
            int j0 = k8 * 8 + tg - 64, j1 = j0 + 4;
            float w0 = Tw[j0], bb0 = Tb[j0], w1 = Tw[j1], bb1 = Tb[j1];
            a[k8][0] = h0 ? to_tf32(cosf(__fadd_rn(__fmul_rn(tf0, w0), bb0))) : 0u;
            a[k8][1] = h1 ? to_tf32(cosf(__fadd_rn(__fmul_rn(tf1, w0), bb0))) : 0u;
            a[k8][2] = h0 ? to_tf32(cosf(__fadd_rn(__fmul_rn(tf0, w1), bb1))) : 0u;
            a[k8][3] = h1 ? to_tf32(cosf(__fadd_rn(__fmul_rn(tf1, w1), bb1))) : 0u;
        }

#pragma unroll 1
        for (int p = 0; p < 8; p++) {
            float acc[6][4];
#pragma unroll
            for (int q = 0; q < 6; q++)
#pragma unroll
                for (int i = 0; i < 4; i++) acc[q][i] = 0.f;

#pragma unroll
            for (int k8 = 0; k8 < 12; k8++) {
                const uint4* wp = (const uint4*)(Wf + ((p * 12 + k8) * 32 + lane) * 6);
                uint4 w0 = wp[0], w1 = wp[1], w2 = wp[2];
                mma8(acc[0], a[k8][0], a[k8][1], a[k8][2], a[k8][3], w0.x, w0.y);
                mma8(acc[1], a[k8][0], a[k8][1], a[k8][2], a[k8][3], w0.z, w0.w);
                mma8(acc[2], a[k8][0], a[k8][1], a[k8][2], a[k8][3], w1.x, w1.y);
                mma8(acc[3], a[k8][0], a[k8][1], a[k8][2], a[k8][3], w1.z, w1.w);
                mma8(acc[4], a[k8][0], a[k8][1], a[k8][2], a[k8][3], w2.x, w2.y);
                mma8(acc[5], a[k8][0], a[k8][1], a[k8][2], a[k8][3], w2.z, w2.w);
            }
#pragma unroll
            for (int jj = 0; jj < 2; jj++) {
                int kbase = (p * 2 + jj) * 8 + 2 * tg;
                float o0[2], o1[2];
#pragma unroll
                for (int ii = 0; ii < 2; ii++) {
                    int kk = kbase + ii;
                    float br = Bsm[kk], bz = Bsm[128 + kk];
                    float bin = Bsm[256 + kk], bhn = Bsm[384 + kk];
                    {
                        float r = fsig(acc[jj][ii] + br);
                        float z = fsig(acc[2 + jj][ii] + bz);
                        float nn = ftanh_(acc[4 + jj][ii] + bin + r * bhn);
                        o0[ii] = h0 ? (1.f - z) * nn : 0.f;
                    }
                    {
                        float r = fsig(acc[jj][2 + ii] + br);
                        float z = fsig(acc[2 + jj][2 + ii] + bz);
                        float nn = ftanh_(acc[4 + jj][2 + ii] + bin + r * bhn);
                        o1[ii] = h1 ? (1.f - z) * nn : 0.f;
                    }
                }
                *(float2*)&g_mem[(long)node0 * 128 + kbase] = make_float2(o0[0], o0[1]);
                *(float2*)&g_mem[(long)node1 * 128 + kbase] = make_float2(o1[0], o1[1]);
            }
        }
    }
}

/* ---------------- GAT projection + attention scores (reg-resident A) ---------
 * W fragments per-lane-contiguous, 80 B/lane (8 tiles + 16 B pad) -> 4x LDS.128.
 */
#define XW_ENT (16 * 2 * 32 * 10)   /* uint2 = 81920 B */
__global__ void __launch_bounds__(512, 1)
k_gatx(const float* __restrict__ gat_w, const float* __restrict__ att_src,
       const float* __restrict__ att_dst) {
    extern __shared__ unsigned smu[];
    uint2* Wf  = (uint2*)smu;              /* [k8][h][lane][n8(+pad)] */
    float* Asm = (float*)(Wf + XW_ENT);
    const int tid = threadIdx.x;

    for (int i = tid; i < XW_ENT; i += 512) {
        int n8 = i % 10;
        int lane = (i / 10) & 31;
        int h = (i / 320) & 1;
        int k8 = i / 640;
        uint2 v = make_uint2(0u, 0u);
        if (n8 < 8) {
            int n = (h * 8 + n8) * 8 + (lane >> 2);
            int k = k8 * 8 + (lane & 3);
            v = make_uint2(to_tf32(gat_w[n * 128 + k]), to_tf32(gat_w[n * 128 + k + 4]));
        }
        Wf[i] = v;
    }
    if (tid < 256) Asm[tid] = (tid < 128) ? att_src[tid] : att_dst[tid - 128];
    __syncthreads();

    const int warp = tid >> 5, lane = tid & 31;
    const int grp = lane >> 2, tg = lane & 3;
    const int nwarps = gridDim.x * 16;

    for (int rg = blockIdx.x * 16 + warp; rg < N_NODES / 16; rg += nwarps) {
        const int node0 = rg * 16 + grp, node1 = node0 + 8;
        const float* r0 = g_mem + (long)node0 * 128;
        const float* r1 = g_mem + (long)node1 * 128;

        unsigned a[16][4];
#pragma unroll
        for (int k8 = 0; k8 < 16; k8++) {
            int c0 = k8 * 8 + tg;
            a[k8][0] = to_tf32(__ldg(r0 + c0));
            a[k8][1] = to_tf32(__ldg(r1 + c0));
            a[k8][2] = to_tf32(__ldg(r0 + c0 + 4));
            a[k8][3] = to_tf32(__ldg(r1 + c0 + 4));
        }

        float ps0 = 0.f, pd0 = 0.f, ps1 = 0.f, pd1 = 0.f;
#pragma unroll 1
        for (int h = 0; h < 2; h++) {
            float acc[8][4];
#pragma unroll
            for (int q = 0; q < 8; q++)
#pragma unroll
                for (int i = 0; i < 4; i++) acc[q][i] = 0.f;

#pragma unroll
            for (int k8 = 0; k8 < 16; k8++) {
                const uint4* wp = (const uint4*)(Wf + ((k8 * 2 + h) * 32 + lane) * 10);
                uint4 wa = wp[0], wb = wp[1], wc = wp[2], wd = wp[3];
                mma8(acc[0], a[k8][0], a[k8][1], a[k8][2], a[k8][3], wa.x, wa.y);
                mma8(acc[1], a[k8][0], a[k8][1], a[k8][2], a[k8][3], wa.z, wa.w);
                mma8(acc[2], a[k8][0], a[k8][1], a[k8][2], a[k8][3], wb.x, wb.y);
                mma8(acc[3], a[k8][0], a[k8][1], a[k8][2], a[k8][3], wb.z, wb.w);
                mma8(acc[4], a[k8][0], a[k8][1], a[k8][2], a[k8][3], wc.x, wc.y);
                mma8(acc[5], a[k8][0], a[k8][1], a[k8][2], a[k8][3], wc.z, wc.w);
                mma8(acc[6], a[k8][0], a[k8][1], a[k8][2], a[k8][3], wd.x, wd.y);
                mma8(acc[7], a[k8][0], a[k8][1], a[k8][2], a[k8][3], wd.z, wd.w);
            }
#pragma unroll
            for (int n8 = 0; n8 < 8; n8++) {
                int col = (h * 8 + n8) * 8 + 2 * tg;
                float s0 = Asm[col], s1 = Asm[col + 1];
                float d0 = Asm[128 + col], d1 = Asm[128 + col + 1];
                ps0 += acc[n8][0] * s0 + acc[n8][1] * s1;
                pd0 += acc[n8][0] * d0 + acc[n8][1] * d1;
                ps1 += acc[n8][2] * s0 + acc[n8][3] * s1;
                pd1 += acc[n8][2] * d0 + acc[n8][3] * d1;
                *(__half2*)&g_xh[(long)node0 * 128 + col] =
                    __floats2half2_rn(acc[n8][0], acc[n8][1]);
                *(__half2*)&g_xh[(long)node1 * 128 + col] =
                    __floats2half2_rn(acc[n8][2], acc[n8][3]);
            }
        }
#pragma unroll
        for (int o = 1; o <= 2; o <<= 1) {
            ps0 += __shfl_xor_sync(0xFFFFFFFFu, ps0, o);
            pd0 += __shfl_xor_sync(0xFFFFFFFFu, pd0, o);
            ps1 += __shfl_xor_sync(0xFFFFFFFFu, ps1, o);
            pd1 += __shfl_xor_sync(0xFFFFFFFFu, pd1, o);
        }
        if (tg == 0) {
            g_as[node0] = ps0; g_ad[node0] = pd0;
            g_as[node1] = ps1; g_ad[node1] = pd1;
        }
    }
}

/* ---------------- fused GAT softmax + aggregation: warp per node ------------- */
__global__ void __launch_bounds__(256)
k_agg() {
    int gt = blockIdx.x * blockDim.x + threadIdx.x;
    int node = gt >> 5, lane = gt & 31;
    if (node >= N_NODES) return;
    const int start = g_off[node], end = g_pos[node];
    const float ad = g_ad[node];
    float e_self = g_as[node] + ad;
    e_self = (e_self > 0.f) ? e_self : 0.2f * e_self;

    const float w0 = __expf(e_self);
    uint2 raw = __ldg((const uint2*)(g_xh + (long)node * 128) + lane);
    float2 lo = __half22float2(*(__half2*)&raw.x);
    float2 hi = __half22float2(*(__half2*)&raw.y);
    float4 acc = make_float4(w0 * lo.x, w0 * lo.y, w0 * hi.x, w0 * hi.y);
    float den_l = 0.f;

    for (int b = start; b < end; b += 32) {
        int rem = end - b;
        int n = rem < 32 ? rem : 32;
        int  s_l = 0;
        float w_l = 0.f;
        if (lane < n) {
            s_l = __ldg(&g_csrs[b + lane]);
            float e = __ldg(&g_as[s_l]) + ad;
            e = (e > 0.f) ? e : 0.2f * e;
            w_l = __expf(e);
            den_l += w_l;
        }
        for (int j = 0; j < n; j++) {
            int   s = __shfl_sync(0xFFFFFFFFu, s_l, j);
            float w = __shfl_sync(0xFFFFFFFFu, w_l, j);
            uint2 r = __ldg((const uint2*)(g_xh + (long)s * 128) + lane);
            float2 l2 = __half22float2(*(__half2*)&r.x);
            float2 h2 = __half22float2(*(__half2*)&r.y);
            acc.x += w * l2.x; acc.y += w * l2.y;
            acc.z += w * h2.x; acc.w += w * h2.y;
        }
    }
#pragma unroll
    for (int o = 16; o; o >>= 1) den_l += __shfl_xor_sync(0xFFFFFFFFu, den_l, o);
    float inv = 1.f / (den_l + w0);
    acc.x *= inv; acc.y *= inv; acc.z *= inv; acc.w *= inv;
    ((float4*)(g_z + (long)node * 128))[lane] = acc;
}

/* ---------------- fused ReLU + classifier (reg-resident A) ---------------- */
#define CW_ENT (16 * 32 * 10)   /* uint2 = 40960 B */
__global__ void __launch_bounds__(512, 1)
k_cls(const float* __restrict__ cls_w, const float* __restrict__ cls_b,
      const float* __restrict__ gat_b, float* __restrict__ out) {
    extern __shared__ unsigned smu[];
    uint2* Wf = (uint2*)smu;              /* [k8][lane][n8(+pad)] */
    float* Cb = (float*)(Wf + CW_ENT);
    float* Gb = Cb + 64;
    const int tid = threadIdx.x;

    for (int i = tid; i < CW_ENT; i += 512) {
        int n8 = i % 10;
        int lane = (i / 10) & 31;
        int k8 = i / 320;
        uint2 v = make_uint2(0u, 0u);
        if (n8 < 8) {
            int n = n8 * 8 + (lane >> 2);
            int k = k8 * 8 + (lane & 3);
            v = make_uint2(to_tf32(cls_w[n * 128 + k]), to_tf32(cls_w[n * 128 + k + 4]));
        }
        Wf[i] = v;
    }
    if (tid < 64) Cb[tid] = cls_b[tid];
    if (tid < 128) Gb[tid] = gat_b[tid];
    __syncthreads();

    const int warp = tid >> 5, lane = tid & 31;
    const int grp = lane >> 2, tg = lane & 3;
    const int nwarps = gridDim.x * 16;

    for (int rg = blockIdx.x * 16 + warp; rg < N_NODES / 16; rg += nwarps) {
        const int node0 = rg * 16 + grp, node1 = node0 + 8;
        const float* r0 = g_z + (long)node0 * 128;
        const float* r1 = g_z + (long)node1 * 128;

        unsigned a[16][4];
#pragma unroll
        for (int k8 = 0; k8 < 16; k8++) {
            int c0 = k8 * 8 + tg, c1 = c0 + 4;
            float b0 = Gb[c0], b1 = Gb[c1];
            float v;
            v = __ldg(r0 + c0) + b0; a[k8][0] = to_tf32(v > 0.f ? v : 0.f);
            v = __ldg(r1 + c0) + b0; a[k8][1] = to_tf32(v > 0.f ? v : 0.f);
            v = __ldg(r0 + c1) + b1; a[k8][2] = to_tf32(v > 0.f ? v : 0.f);
            v = __ldg(r1 + c1) + b1; a[k8][3] = to_tf32(v > 0.f ? v : 0.f);
        }

        float acc[8][4];
#pragma unroll
        for (int q = 0; q < 8; q++)
#pragma unroll
            for (int i = 0; i < 4; i++) acc[q][i] = 0.f;

#pragma unroll
        for (int k8 = 0; k8 < 16; k8++) {
            const uint4* wp = (const uint4*)(Wf + (k8 * 32 + lane) * 10);
            uint4 wa = wp[0], wb = wp[1], wc = wp[2], wd = wp[3];
            mma8(acc[0], a[k8][0], a[k8][1], a[k8][2], a[k8][3], wa.x, wa.y);
            mma8(acc[1], a[k8][0], a[k8][1], a[k8][2], a[k8][3], wa.z, wa.w);
            mma8(acc[2], a[k8][0], a[k8][1], a[k8][2], a[k8][3], wb.x, wb.y);
            mma8(acc[3], a[k8][0], a[k8][1], a[k8][2], a[k8][3], wb.z, wb.w);
            mma8(acc[4], a[k8][0], a[k8][1], a[k8][2], a[k8][3], wc.x, wc.y);
            mma8(acc[5], a[k8][0], a[k8][1], a[k8][2], a[k8][3], wc.z, wc.w);
            mma8(acc[6], a[k8][0], a[k8][1], a[k8][2], a[k8][3], wd.x, wd.y);
            mma8(acc[7], a[k8][0], a[k8][1], a[k8][2], a[k8][3], wd.z, wd.w);
        }
#pragma unroll
        for (int n8 = 0; n8 < 8; n8++) {
            int col = n8 * 8 + 2 * tg;
            float b0 = Cb[col], b1 = Cb[col + 1];
            *(float2*)&out[(long)node0 * 64 + col] =
                make_float2(acc[n8][0] + b0, acc[n8][1] + b1);
            *(float2*)&out[(long)node1 * 64 + col] =
                make_float2(acc[n8][2] + b0, acc[n8][3] + b1);
        }
    }
}

/* ---------------- launch ----------------
 * Fork-join: CSR build (cnt/count/scan/fill) runs on a side stream, overlapped
 * with the GEMM chain; joined via event before k_agg. One-time stream/event
 * creation (host resources only; identical device work every call).
 * Host issue order keeps k_gru as the 4th kernel for the ncu window.
 */
extern "C" void kernel_launch(void* const* d_in, const int* in_sizes, int n_in,
                              void* d_out, int out_size) {
    const int*   src    = (const int*)  d_in[0];
    const int*   dst    = (const int*)  d_in[1];
    const int*   t      = (const int*)  d_in[2];
    const float* msg    = (const float*)d_in[3];
    const int*   sei    = (const int*)  d_in[4];
    const float* time_w = (const float*)d_in[5];
    const float* time_b = (const float*)d_in[6];
    const float* w_ih   = (const float*)d_in[7];
    /* d_in[8] = gru_w_hh: unused (memory == 0 at update time) */
    const float* b_ih   = (const float*)d_in[9];
    const float* b_hh   = (const float*)d_in[10];
    const float* gat_w  = (const float*)d_in[11];
    const float* att_s  = (const float*)d_in[12];
    const float* att_d  = (const float*)d_in[13];
    const float* gat_b  = (const float*)d_in[14];
    const float* cls_w  = (const float*)d_in[15];
    const float* cls_b  = (const float*)d_in[16];
    float* out = (float*)d_out;
    const int* es = sei;
    const int* ed = sei + N_SEDGE;
    (void)in_sizes; (void)n_in; (void)out_size;

    static cudaStream_t s1 = 0;
    static cudaEvent_t evRoot = 0, evSide = 0;
    static int ok = -1;
    if (ok < 0) {
        ok = 1;
        if (cudaStreamCreateWithFlags(&s1, cudaStreamNonBlocking) != cudaSuccess) ok = 0;
        if (ok && cudaEventCreateWithFlags(&evRoot, cudaEventDisableTiming) != cudaSuccess) ok = 0;
        if (ok && cudaEventCreateWithFlags(&evSide, cudaEventDisableTiming) != cudaSuccess) ok = 0;
    }
    cudaStream_t sC = ok ? s1 : 0;   /* side chain stream (fallback: serial) */

    if (ok) { cudaEventRecord(evRoot, 0); cudaStreamWaitEvent(s1, evRoot, 0); }

    k_init_last<<<(N_NODES + 255) / 256, 256>>>();
    k_last     <<<(N_EV + 255) / 256, 256>>>(src, dst);
    k_init_cnt <<<(N_NODES + 255) / 256, 256, 0, sC>>>();

    {
        size_t smb = (size_t)GRU_WENT * 8 + (512 + 64) * 4;
        cudaFuncSetAttribute(k_gru, cudaFuncAttributeMaxDynamicSharedMemorySize, (int)smb);
        k_gru<<<148, 512, smb>>>(t, msg, w_ih, b_ih, b_hh, time_w, time_b);
    }

    k_count<<<(N_SEDGE + 255) / 256, 256, 0, sC>>>(ed);
    k_scanA<<<SNBLK, 256, 0, sC>>>();
    k_scanB<<<1, 128, 0, sC>>>();
    k_scanC<<<SNBLK, 256, 0, sC>>>();
    k_fill <<<(N_SEDGE + 255) / 256, 256, 0, sC>>>(es, ed);
    if (ok) cudaEventRecord(evSide, s1);

    {
        size_t smb = (size_t)XW_ENT * 8 + 256 * 4;
        cudaFuncSetAttribute(k_gatx, cudaFuncAttributeMaxDynamicSharedMemorySize, (int)smb);
        k_gatx<<<148, 512, smb>>>(gat_w, att_s, att_d);
    }

    if (ok) cudaStreamWaitEvent(0, evSide, 0);
    k_agg<<<(N_NODES * 32 + 255) / 256, 256>>>();
    {
        size_t smb = (size_t)CW_ENT * 8 + 192 * 4;
        cudaFuncSetAttribute(k_cls, cudaFuncAttributeMaxDynamicSharedMemorySize, (int)smb);
        k_cls<<<148, 512, smb>>>(cls_w, cls_b, gat_b, out);
    }
}

// round 14
// speedup vs baseline: 5.2558x; 1.0207x over previous
#include <cuda_runtime.h>
#include <cuda_fp16.h>
#include <math.h>

#define N_NODES 100000
#define N_EV    200000
#define N_SEDGE 1600000
#define SCHUNK  1024
#define SNBLK   ((N_NODES + SCHUNK - 1) / SCHUNK)

/* ---------------- device scratch (no allocations allowed) ---------------- */
__device__ __align__(16) int    g_last[N_NODES];
__device__ __align__(16) float  g_mem [N_NODES * 128];
__device__ __align__(16) __half g_xh  [N_NODES * 128];
__device__ __align__(16) float  g_as  [N_NODES];
__device__ __align__(16) float  g_ad  [N_NODES];
__device__ __align__(16) float  g_z   [N_NODES * 128];
__device__ __align__(16) int    g_cnt [N_NODES];
__device__ __align__(16) int    g_off [N_NODES];
__device__ __align__(16) int    g_pos [N_NODES];
__device__               int    g_part[SNBLK];
__device__ __align__(16) int    g_csrs[N_SEDGE];

/* ---------------- tf32 MMA helpers ---------------- */
__device__ __forceinline__ unsigned to_tf32(float f) {
    unsigned r; asm("cvt.rna.tf32.f32 %0,%1;" : "=r"(r) : "f"(f)); return r;
}
__device__ __forceinline__ void mma8(float (&c)[4], unsigned a0, unsigned a1,
                                     unsigned a2, unsigned a3,
                                     unsigned b0, unsigned b1) {
    asm("mma.sync.aligned.m16n8k8.row.col.f32.tf32.tf32.f32 "
        "{%0,%1,%2,%3},{%4,%5,%6,%7},{%8,%9},{%0,%1,%2,%3};"
        : "+f"(c[0]), "+f"(c[1]), "+f"(c[2]), "+f"(c[3])
        : "r"(a0), "r"(a1), "r"(a2), "r"(a3), "r"(b0), "r"(b1));
}
/* exact-ish fast sigmoid/tanh (rel err ~1e-6): used for z and n gates */
__device__ __forceinline__ float fsig(float x) {
    return __fdividef(1.f, 1.f + __expf(-x));
}
__device__ __forceinline__ float ftanh_(float x) {
    return 1.f - __fdividef(2.f, __expf(2.f * x) + 1.f);
}
/* r-gate sigmoid via single-MUFU tanh.approx: abs err ~6e-4, attenuated by
 * d n/d r = (1-n^2)*b_hn (~0.09) to ~5e-5 on h — invisible under tf32 noise. */
__device__ __forceinline__ float fsig_r(float x) {
    float y; asm("tanh.approx.f32 %0,%1;" : "=f"(y) : "f"(x * 0.5f));
    return fmaf(0.5f, y, 0.5f);
}

/* ---------------- init ---------------- */
__global__ void k_init_last() {
    int i = blockIdx.x * blockDim.x + threadIdx.x;
    if (i < N_NODES) g_last[i] = -1;
}
__global__ void k_init_cnt() {
    int i = blockIdx.x * blockDim.x + threadIdx.x;
    if (i < N_NODES) g_cnt[i] = 0;
}

/* ---------------- last event per node ---------------- */
__global__ void k_last(const int* __restrict__ src, const int* __restrict__ dst) {
    int i = blockIdx.x * blockDim.x + threadIdx.x;
    if (i >= N_EV) return;
    atomicMax(&g_last[src[i]], i);
    atomicMax(&g_last[dst[i]], i);
}

/* ---------------- CSR build: count / scan / fill ---------------- */
__global__ void k_count(const int* __restrict__ ed) {
    int i = blockIdx.x * blockDim.x + threadIdx.x;
    if (i < N_SEDGE) atomicAdd(&g_cnt[ed[i]], 1);
}

__global__ void k_scanA() {
    int b = blockIdx.x, t = threadIdx.x;
    int base = b * SCHUNK + t * 4;
    int s = 0;
#pragma unroll
    for (int u = 0; u < 4; u++) { int i = base + u; if (i < N_NODES) s += g_cnt[i]; }
#pragma unroll
    for (int o = 16; o; o >>= 1) s += __shfl_xor_sync(0xFFFFFFFFu, s, o);
    __shared__ int ws[8];
    if ((t & 31) == 0) ws[t >> 5] = s;
    __syncthreads();
    if (t == 0) { int tot = 0; for (int w = 0; w < 8; w++) tot += ws[w]; g_part[b] = tot; }
}

__global__ void k_scanB() {
    int t = threadIdx.x;
    int v = (t < SNBLK) ? g_part[t] : 0;
    int lane = t & 31, wid = t >> 5;
    int inc = v;
#pragma unroll
    for (int o = 1; o < 32; o <<= 1) { int n = __shfl_up_sync(0xFFFFFFFFu, inc, o); if (lane >= o) inc += n; }
    __shared__ int ws[4];
    if (lane == 31) ws[wid] = inc;
    __syncthreads();
    if (t == 0) { int r = 0; for (int i = 0; i < 4; i++) { int x = ws[i]; ws[i] = r; r += x; } }
    __syncthreads();
    if (t < SNBLK) g_part[t] = inc - v + ws[wid];
}

__global__ void k_scanC() {
    int b = blockIdx.x, t = threadIdx.x;
    int base = b * SCHUNK + t * 4;
    int c[4]; int s = 0;
#pragma unroll
    for (int u = 0; u < 4; u++) { int i = base + u; c[u] = (i < N_NODES) ? g_cnt[i] : 0; s += c[u]; }
    int lane = t & 31, wid = t >> 5;
    int inc = s;
#pragma unroll
    for (int o = 1; o < 32; o <<= 1) { int n = __shfl_up_sync(0xFFFFFFFFu, inc, o); if (lane >= o) inc += n; }
    __shared__ int ws[8];
    if (lane == 31) ws[wid] = inc;
    __syncthreads();
    if (t == 0) { int r = 0; for (int i = 0; i < 8; i++) { int x = ws[i]; ws[i] = r; r += x; } }
    __syncthreads();
    int off = g_part[b] + ws[wid] + inc - s;
#pragma unroll
    for (int u = 0; u < 4; u++) {
        int i = base + u;
        if (i < N_NODES) { g_off[i] = off; g_pos[i] = off; }
        off += c[u];
    }
}

__global__ void k_fill(const int* __restrict__ es, const int* __restrict__ ed) {
    int i = blockIdx.x * blockDim.x + threadIdx.x;
    if (i >= N_SEDGE) return;
    int pos = atomicAdd(&g_pos[ed[i]], 1);
    g_csrs[pos] = es[i];
}

/* ---------------- fused GRU memory update (tf32 MMA, reg-resident A) ---------
 * A-fill is UNPREDICATED: for no-message nodes the fragments hold garbage
 * (msg[0] / cos(t[0])) that the epilogue discards via has-flag — removes all
 * per-element SELs from the hot path.
 */
#define GRU_WENT (8 * 12 * 32 * 6)   /* uint2 entries = 147456 B */
__global__ void __launch_bounds__(512, 1)
k_gru(const int* __restrict__ t, const float* __restrict__ msg,
      const float* __restrict__ w_ih, const float* __restrict__ b_ih,
      const float* __restrict__ b_hh,
      const float* __restrict__ time_w, const float* __restrict__ time_b) {
    extern __shared__ unsigned smu[];
    uint2* Wf  = (uint2*)smu;                 /* [p][k8][lane][t6] */
    float* Bsm = (float*)(Wf + GRU_WENT);
    float* Tw  = Bsm + 512;
    float* Tb  = Tw + 32;
    const int tid = threadIdx.x;

    for (int i = tid; i < GRU_WENT; i += 512) {
        int t6 = i % 6;
        int lane = (i / 6) & 31;
        int k8 = (i / 192) % 12;
        int p  = i / 2304;
        int g = t6 >> 1, jj = t6 & 1;
        int n8 = g * 16 + p * 2 + jj;
        int n = n8 * 8 + (lane >> 2);
        int k = k8 * 8 + (lane & 3);
        const float* wr = w_ih + n * 352 + 256 + k;
        Wf[i] = make_uint2(to_tf32(wr[0]), to_tf32(wr[4]));
    }
    for (int k = tid; k < 128; k += 512) {
        Bsm[k]       = b_ih[k]       + b_hh[k];
        Bsm[128 + k] = b_ih[128 + k] + b_hh[128 + k];
        Bsm[256 + k] = b_ih[256 + k];
        Bsm[384 + k] = b_hh[256 + k];
    }
    if (tid < 32) { Tw[tid] = time_w[tid]; Tb[tid] = time_b[tid]; }
    __syncthreads();

    const int warp = tid >> 5, lane = tid & 31;
    const int grp = lane >> 2, tg = lane & 3;
    const int nwarps = gridDim.x * 16;

    for (int rg = blockIdx.x * 16 + warp; rg < N_NODES / 16; rg += nwarps) {
        const int node0 = rg * 16 + grp, node1 = node0 + 8;
        const int le0 = g_last[node0], le1 = g_last[node1];
        const bool h0 = le0 >= 0, h1 = le1 >= 0;
        const int e0 = h0 ? le0 : 0, e1 = h1 ? le1 : 0;
        const float tf0 = (float)t[e0];
        const float tf1 = (float)t[e1];
        const float* m0 = msg + (long)e0 * 64;
        const float* m1 = msg + (long)e1 * 64;

        unsigned a[12][4];
#pragma unroll
        for (int k8 = 0; k8 < 8; k8++) {
            int c0 = k8 * 8 + tg, c1 = c0 + 4;
            a[k8][0] = to_tf32(__ldg(&m0[c0]));
            a[k8][1] = to_tf32(__ldg(&m1[c0]));
            a[k8][2] = to_tf32(__ldg(&m0[c1]));
            a[k8][3] = to_tf32(__ldg(&m1[c1]));
        }
#pragma unroll
        for (int k8 = 8; k8 < 12; k8++) {
            int j0 = k8 * 8 + tg - 64, j1 = j0 + 4;
            float w0 = Tw[j0], bb0 = Tb[j0], w1 = Tw[j1], bb1 = Tb[j1];
            a[k8][0] = to_tf32(cosf(__fadd_rn(__fmul_rn(tf0, w0), bb0)));
            a[k8][1] = to_tf32(cosf(__fadd_rn(__fmul_rn(tf1, w0), bb0)));
            a[k8][2] = to_tf32(cosf(__fadd_rn(__fmul_rn(tf0, w1), bb1)));
            a[k8][3] = to_tf32(cosf(__fadd_rn(__fmul_rn(tf1, w1), bb1)));
        }

#pragma unroll 1
        for (int p = 0; p < 8; p++) {
            float acc[6][4];
#pragma unroll
            for (int q = 0; q < 6; q++)
#pragma unroll
                for (int i = 0; i < 4; i++) acc[q][i] = 0.f;

#pragma unroll
            for (int k8 = 0; k8 < 12; k8++) {
                const uint4* wp = (const uint4*)(Wf + ((p * 12 + k8) * 32 + lane) * 6);
                uint4 w0 = wp[0], w1 = wp[1], w2 = wp[2];
                mma8(acc[0], a[k8][0], a[k8][1], a[k8][2], a[k8][3], w0.x, w0.y);
                mma8(acc[1], a[k8][0], a[k8][1], a[k8][2], a[k8][3], w0.z, w0.w);
                mma8(acc[2], a[k8][0], a[k8][1], a[k8][2], a[k8][3], w1.x, w1.y);
                mma8(acc[3], a[k8][0], a[k8][1], a[k8][2], a[k8][3], w1.z, w1.w);
                mma8(acc[4], a[k8][0], a[k8][1], a[k8][2], a[k8][3], w2.x, w2.y);
                mma8(acc[5], a[k8][0], a[k8][1], a[k8][2], a[k8][3], w2.z, w2.w);
            }
#pragma unroll
            for (int jj = 0; jj < 2; jj++) {
                int kbase = (p * 2 + jj) * 8 + 2 * tg;
                float o0[2], o1[2];
#pragma unroll
                for (int ii = 0; ii < 2; ii++) {
                    int kk = kbase + ii;
                    float br = Bsm[kk], bz = Bsm[128 + kk];
                    float bin = Bsm[256 + kk], bhn = Bsm[384 + kk];
                    {
                        float r = fsig_r(acc[jj][ii] + br);
                        float z = fsig(acc[2 + jj][ii] + bz);
                        float nn = ftanh_(acc[4 + jj][ii] + bin + r * bhn);
                        o0[ii] = h0 ? (1.f - z) * nn : 0.f;
                    }
                    {
                        float r = fsig_r(acc[jj][2 + ii] + br);
                        float z = fsig(acc[2 + jj][2 + ii] + bz);
                        float nn = ftanh_(acc[4 + jj][2 + ii] + bin + r * bhn);
                        o1[ii] = h1 ? (1.f - z) * nn : 0.f;
                    }
                }
                *(float2*)&g_mem[(long)node0 * 128 + kbase] = make_float2(o0[0], o0[1]);
                *(float2*)&g_mem[(long)node1 * 128 + kbase] = make_float2(o1[0], o1[1]);
            }
        }
    }
}

/* ---------------- GAT projection + attention scores (reg-resident A) --------- */
#define XW_ENT (16 * 2 * 32 * 10)   /* uint2 = 81920 B */
__global__ void __launch_bounds__(512, 1)
k_gatx(const float* __restrict__ gat_w, const float* __restrict__ att_src,
       const float* __restrict__ att_dst) {
    extern __shared__ unsigned smu[];
    uint2* Wf  = (uint2*)smu;              /* [k8][h][lane][n8(+pad)] */
    float* Asm = (float*)(Wf + XW_ENT);
    const int tid = threadIdx.x;

    for (int i = tid; i < XW_ENT; i += 512) {
        int n8 = i % 10;
        int lane = (i / 10) & 31;
        int h = (i / 320) & 1;
        int k8 = i / 640;
        uint2 v = make_uint2(0u, 0u);
        if (n8 < 8) {
            int n = (h * 8 + n8) * 8 + (lane >> 2);
            int k = k8 * 8 + (lane & 3);
            v = make_uint2(to_tf32(gat_w[n * 128 + k]), to_tf32(gat_w[n * 128 + k + 4]));
        }
        Wf[i] = v;
    }
    if (tid < 256) Asm[tid] = (tid < 128) ? att_src[tid] : att_dst[tid - 128];
    __syncthreads();

    const int warp = tid >> 5, lane = tid & 31;
    const int grp = lane >> 2, tg = lane & 3;
    const int nwarps = gridDim.x * 16;

    for (int rg = blockIdx.x * 16 + warp; rg < N_NODES / 16; rg += nwarps) {
        const int node0 = rg * 16 + grp, node1 = node0 + 8;
        const float* r0 = g_mem + (long)node0 * 128;
        const float* r1 = g_mem + (long)node1 * 128;

        unsigned a[16][4];
#pragma unroll
        for (int k8 = 0; k8 < 16; k8++) {
            int c0 = k8 * 8 + tg;
            a[k8][0] = to_tf32(__ldg(r0 + c0));
            a[k8][1] = to_tf32(__ldg(r1 + c0));
            a[k8][2] = to_tf32(__ldg(r0 + c0 + 4));
            a[k8][3] = to_tf32(__ldg(r1 + c0 + 4));
        }

        float ps0 = 0.f, pd0 = 0.f, ps1 = 0.f, pd1 = 0.f;
#pragma unroll 1
        for (int h = 0; h < 2; h++) {
            float acc[8][4];
#pragma unroll
            for (int q = 0; q < 8; q++)
#pragma unroll
                for (int i = 0; i < 4; i++) acc[q][i] = 0.f;

#pragma unroll
            for (int k8 = 0; k8 < 16; k8++) {
                const uint4* wp = (const uint4*)(Wf + ((k8 * 2 + h) * 32 + lane) * 10);
                uint4 wa = wp[0], wb = wp[1], wc = wp[2], wd = wp[3];
                mma8(acc[0], a[k8][0], a[k8][1], a[k8][2], a[k8][3], wa.x, wa.y);
                mma8(acc[1], a[k8][0], a[k8][1], a[k8][2], a[k8][3], wa.z, wa.w);
                mma8(acc[2], a[k8][0], a[k8][1], a[k8][2], a[k8][3], wb.x, wb.y);
                mma8(acc[3], a[k8][0], a[k8][1], a[k8][2], a[k8][3], wb.z, wb.w);
                mma8(acc[4], a[k8][0], a[k8][1], a[k8][2], a[k8][3], wc.x, wc.y);
                mma8(acc[5], a[k8][0], a[k8][1], a[k8][2], a[k8][3], wc.z, wc.w);
                mma8(acc[6], a[k8][0], a[k8][1], a[k8][2], a[k8][3], wd.x, wd.y);
                mma8(acc[7], a[k8][0], a[k8][1], a[k8][2], a[k8][3], wd.z, wd.w);
            }
#pragma unroll
            for (int n8 = 0; n8 < 8; n8++) {
                int col = (h * 8 + n8) * 8 + 2 * tg;
                float s0 = Asm[col], s1 = Asm[col + 1];
                float d0 = Asm[128 + col], d1 = Asm[128 + col + 1];
                ps0 += acc[n8][0] * s0 + acc[n8][1] * s1;
                pd0 += acc[n8][0] * d0 + acc[n8][1] * d1;
                ps1 += acc[n8][2] * s0 + acc[n8][3] * s1;
                pd1 += acc[n8][2] * d0 + acc[n8][3] * d1;
                *(__half2*)&g_xh[(long)node0 * 128 + col] =
                    __floats2half2_rn(acc[n8][0], acc[n8][1]);
                *(__half2*)&g_xh[(long)node1 * 128 + col] =
                    __floats2half2_rn(acc[n8][2], acc[n8][3]);
            }
        }
#pragma unroll
        for (int o = 1; o <= 2; o <<= 1) {
            ps0 += __shfl_xor_sync(0xFFFFFFFFu, ps0, o);
            pd0 += __shfl_xor_sync(0xFFFFFFFFu, pd0, o);
            ps1 += __shfl_xor_sync(0xFFFFFFFFu, ps1, o);
            pd1 += __shfl_xor_sync(0xFFFFFFFFu, pd1, o);
        }
        if (tg == 0) {
            g_as[node0] = ps0; g_ad[node0] = pd0;
            g_as[node1] = ps1; g_ad[node1] = pd1;
        }
    }
}

/* ---------------- fused GAT softmax + aggregation: warp per node ------------- */
__global__ void __launch_bounds__(256)
k_agg() {
    int gt = blockIdx.x * blockDim.x + threadIdx.x;
    int node = gt >> 5, lane = gt & 31;
    if (node >= N_NODES) return;
    const int start = g_off[node], end = g_pos[node];
    const float ad = g_ad[node];
    float e_self = g_as[node] + ad;
    e_self = (e_self > 0.f) ? e_self : 0.2f * e_self;

    const float w0 = __expf(e_self);
    uint2 raw = __ldg((const uint2*)(g_xh + (long)node * 128) + lane);
    float2 lo = __half22float2(*(__half2*)&raw.x);
    float2 hi = __half22float2(*(__half2*)&raw.y);
    float4 acc = make_float4(w0 * lo.x, w0 * lo.y, w0 * hi.x, w0 * hi.y);
    float den_l = 0.f;

    for (int b = start; b < end; b += 32) {
        int rem = end - b;
        int n = rem < 32 ? rem : 32;
        int  s_l = 0;
        float w_l = 0.f;
        if (lane < n) {
            s_l = __ldg(&g_csrs[b + lane]);
            float e = __ldg(&g_as[s_l]) + ad;
            e = (e > 0.f) ? e : 0.2f * e;
            w_l = __expf(e);
            den_l += w_l;
        }
#pragma unroll 4
        for (int j = 0; j < n; j++) {
            int   s = __shfl_sync(0xFFFFFFFFu, s_l, j);
            float w = __shfl_sync(0xFFFFFFFFu, w_l, j);
            uint2 r = __ldg((const uint2*)(g_xh + (long)s * 128) + lane);
            float2 l2 = __half22float2(*(__half2*)&r.x);
            float2 h2 = __half22float2(*(__half2*)&r.y);
            acc.x += w * l2.x; acc.y += w * l2.y;
            acc.z += w * h2.x; acc.w += w * h2.y;
        }
    }
#pragma unroll
    for (int o = 16; o; o >>= 1) den_l += __shfl_xor_sync(0xFFFFFFFFu, den_l, o);
    float inv = 1.f / (den_l + w0);
    acc.x *= inv; acc.y *= inv; acc.z *= inv; acc.w *= inv;
    ((float4*)(g_z + (long)node * 128))[lane] = acc;
}

/* ---------------- fused ReLU + classifier (reg-resident A) ---------------- */
#define CW_ENT (16 * 32 * 10)   /* uint2 = 40960 B */
__global__ void __launch_bounds__(512, 1)
k_cls(const float* __restrict__ cls_w, const float* __restrict__ cls_b,
      const float* __restrict__ gat_b, float* __restrict__ out) {
    extern __shared__ unsigned smu[];
    uint2* Wf = (uint2*)smu;              /* [k8][lane][n8(+pad)] */
    float* Cb = (float*)(Wf + CW_ENT);
    float* Gb = Cb + 64;
    const int tid = threadIdx.x;

    for (int i = tid; i < CW_ENT; i += 512) {
        int n8 = i % 10;
        int lane = (i / 10) & 31;
        int k8 = i / 320;
        uint2 v = make_uint2(0u, 0u);
        if (n8 < 8) {
            int n = n8 * 8 + (lane >> 2);
            int k = k8 * 8 + (lane & 3);
            v = make_uint2(to_tf32(cls_w[n * 128 + k]), to_tf32(cls_w[n * 128 + k + 4]));
        }
        Wf[i] = v;
    }
    if (tid < 64) Cb[tid] = cls_b[tid];
    if (tid < 128) Gb[tid] = gat_b[tid];
    __syncthreads();

    const int warp = tid >> 5, lane = tid & 31;
    const int grp = lane >> 2, tg = lane & 3;
    const int nwarps = gridDim.x * 16;

    for (int rg = blockIdx.x * 16 + warp; rg < N_NODES / 16; rg += nwarps) {
        const int node0 = rg * 16 + grp, node1 = node0 + 8;
        const float* r0 = g_z + (long)node0 * 128;
        const float* r1 = g_z + (long)node1 * 128;

        unsigned a[16][4];
#pragma unroll
        for (int k8 = 0; k8 < 16; k8++) {
            int c0 = k8 * 8 + tg, c1 = c0 + 4;
            float b0 = Gb[c0], b1 = Gb[c1];
            float v;
            v = __ldg(r0 + c0) + b0; a[k8][0] = to_tf32(v > 0.f ? v : 0.f);
            v = __ldg(r1 + c0) + b0; a[k8][1] = to_tf32(v > 0.f ? v : 0.f);
            v = __ldg(r0 + c1) + b1; a[k8][2] = to_tf32(v > 0.f ? v : 0.f);
            v = __ldg(r1 + c1) + b1; a[k8][3] = to_tf32(v > 0.f ? v : 0.f);
        }

        float acc[8][4];
#pragma unroll
        for (int q = 0; q < 8; q++)
#pragma unroll
            for (int i = 0; i < 4; i++) acc[q][i] = 0.f;

#pragma unroll
        for (int k8 = 0; k8 < 16; k8++) {
            const uint4* wp = (const uint4*)(Wf + (k8 * 32 + lane) * 10);
            uint4 wa = wp[0], wb = wp[1], wc = wp[2], wd = wp[3];
            mma8(acc[0], a[k8][0], a[k8][1], a[k8][2], a[k8][3], wa.x, wa.y);
            mma8(acc[1], a[k8][0], a[k8][1], a[k8][2], a[k8][3], wa.z, wa.w);
            mma8(acc[2], a[k8][0], a[k8][1], a[k8][2], a[k8][3], wb.x, wb.y);
            mma8(acc[3], a[k8][0], a[k8][1], a[k8][2], a[k8][3], wb.z, wb.w);
            mma8(acc[4], a[k8][0], a[k8][1], a[k8][2], a[k8][3], wc.x, wc.y);
            mma8(acc[5], a[k8][0], a[k8][1], a[k8][2], a[k8][3], wc.z, wc.w);
            mma8(acc[6], a[k8][0], a[k8][1], a[k8][2], a[k8][3], wd.x, wd.y);
            mma8(acc[7], a[k8][0], a[k8][1], a[k8][2], a[k8][3], wd.z, wd.w);
        }
#pragma unroll
        for (int n8 = 0; n8 < 8; n8++) {
            int col = n8 * 8 + 2 * tg;
            float b0 = Cb[col], b1 = Cb[col + 1];
            *(float2*)&out[(long)node0 * 64 + col] =
                make_float2(acc[n8][0] + b0, acc[n8][1] + b1);
            *(float2*)&out[(long)node1 * 64 + col] =
                make_float2(acc[n8][2] + b0, acc[n8][3] + b1);
        }
    }
}

/* ---------------- launch ----------------
 * Fork-join: CSR build overlapped on a side stream; joined before k_agg.
 * Host issue order keeps k_gru as the 4th kernel for the ncu window.
 */
extern "C" void kernel_launch(void* const* d_in, const int* in_sizes, int n_in,
                              void* d_out, int out_size) {
    const int*   src    = (const int*)  d_in[0];
    const int*   dst    = (const int*)  d_in[1];
    const int*   t      = (const int*)  d_in[2];
    const float* msg    = (const float*)d_in[3];
    const int*   sei    = (const int*)  d_in[4];
    const float* time_w = (const float*)d_in[5];
    const float* time_b = (const float*)d_in[6];
    const float* w_ih   = (const float*)d_in[7];
    /* d_in[8] = gru_w_hh: unused (memory == 0 at update time) */
    const float* b_ih   = (const float*)d_in[9];
    const float* b_hh   = (const float*)d_in[10];
    const float* gat_w  = (const float*)d_in[11];
    const float* att_s  = (const float*)d_in[12];
    const float* att_d  = (const float*)d_in[13];
    const float* gat_b  = (const float*)d_in[14];
    const float* cls_w  = (const float*)d_in[15];
    const float* cls_b  = (const float*)d_in[16];
    float* out = (float*)d_out;
    const int* es = sei;
    const int* ed = sei + N_SEDGE;
    (void)in_sizes; (void)n_in; (void)out_size;

    static cudaStream_t s1 = 0;
    static cudaEvent_t evRoot = 0, evSide = 0;
    static int ok = -1;
    if (ok < 0) {
        ok = 1;
        if (cudaStreamCreateWithFlags(&s1, cudaStreamNonBlocking) != cudaSuccess) ok = 0;
        if (ok && cudaEventCreateWithFlags(&evRoot, cudaEventDisableTiming) != cudaSuccess) ok = 0;
        if (ok && cudaEventCreateWithFlags(&evSide, cudaEventDisableTiming) != cudaSuccess) ok = 0;
    }
    cudaStream_t sC = ok ? s1 : 0;

    if (ok) { cudaEventRecord(evRoot, 0); cudaStreamWaitEvent(s1, evRoot, 0); }

    k_init_last<<<(N_NODES + 255) / 256, 256>>>();
    k_last     <<<(N_EV + 255) / 256, 256>>>(src, dst);
    k_init_cnt <<<(N_NODES + 255) / 256, 256, 0, sC>>>();

    {
        size_t smb = (size_t)GRU_WENT * 8 + (512 + 64) * 4;
        cudaFuncSetAttribute(k_gru, cudaFuncAttributeMaxDynamicSharedMemorySize, (int)smb);
        k_gru<<<148, 512, smb>>>(t, msg, w_ih, b_ih, b_hh, time_w, time_b);
    }

    k_count<<<(N_SEDGE + 255) / 256, 256, 0, sC>>>(ed);
    k_scanA<<<SNBLK, 256, 0, sC>>>();
    k_scanB<<<1, 128, 0, sC>>>();
    k_scanC<<<SNBLK, 256, 0, sC>>>();
    k_fill <<<(N_SEDGE + 255) / 256, 256, 0, sC>>>(es, ed);
    if (ok) cudaEventRecord(evSide, s1);

    {
        size_t smb = (size_t)XW_ENT * 8 + 256 * 4;
        cudaFuncSetAttribute(k_gatx, cudaFuncAttributeMaxDynamicSharedMemorySize, (int)smb);
        k_gatx<<<148, 512, smb>>>(gat_w, att_s, att_d);
    }

    if (ok) cudaStreamWaitEvent(0, evSide, 0);
    k_agg<<<(N_NODES * 32 + 255) / 256, 256>>>();
    {
        size_t smb = (size_t)CW_ENT * 8 + 192 * 4;
        cudaFuncSetAttribute(k_cls, cudaFuncAttributeMaxDynamicSharedMemorySize, (int)smb);
        k_cls<<<148, 512, smb>>>(cls_w, cls_b, gat_b, out);
    }
}

// round 15
// speedup vs baseline: 6.0515x; 1.1514x over previous
#include <cuda_runtime.h>
#include <cuda_fp16.h>
#include <math.h>

#define N_NODES 100000
#define N_EV    200000
#define N_SEDGE 1600000
#define SCHUNK  1024
#define SNBLK   ((N_NODES + SCHUNK - 1) / SCHUNK)

/* ---------------- device scratch (no allocations allowed) ---------------- */
__device__ __align__(16) int    g_last[N_NODES];
__device__ __align__(16) float  g_mem [N_NODES * 128];
__device__ __align__(16) __half g_xh  [N_NODES * 128];
__device__ __align__(16) float  g_as  [N_NODES];
__device__ __align__(16) float  g_ad  [N_NODES];
__device__ __align__(16) float  g_z   [N_NODES * 128];
__device__ __align__(16) int    g_cnt [N_NODES];
__device__ __align__(16) int    g_off [N_NODES];
__device__ __align__(16) int    g_pos [N_NODES];
__device__               int    g_part[SNBLK];
__device__ __align__(16) int    g_csrs[N_SEDGE];

/* ---------------- fp16 MMA helpers (m16n8k16, f32 accum) ----------------
 * fp16 mantissa (10 bits) == tf32 mantissa; all operands here are range-safe
 * for fp16's exponent, so precision matches the previous tf32 kernels.
 */
__device__ __forceinline__ unsigned h2pk(float a, float b) {
    __half2 h = __floats2half2_rn(a, b);
    return *(unsigned*)&h;
}
__device__ __forceinline__ void mma16(float (&c)[4], unsigned a0, unsigned a1,
                                      unsigned a2, unsigned a3,
                                      unsigned b0, unsigned b1) {
    asm("mma.sync.aligned.m16n8k16.row.col.f32.f16.f16.f32 "
        "{%0,%1,%2,%3},{%4,%5,%6,%7},{%8,%9},{%0,%1,%2,%3};"
        : "+f"(c[0]), "+f"(c[1]), "+f"(c[2]), "+f"(c[3])
        : "r"(a0), "r"(a1), "r"(a2), "r"(a3), "r"(b0), "r"(b1));
}
/* exact-ish fast sigmoid/tanh (rel err ~1e-6): used for z and n gates */
__device__ __forceinline__ float fsig(float x) {
    return __fdividef(1.f, 1.f + __expf(-x));
}
__device__ __forceinline__ float ftanh_(float x) {
    return 1.f - __fdividef(2.f, __expf(2.f * x) + 1.f);
}
/* r-gate sigmoid via single-MUFU tanh.approx: error attenuated through n */
__device__ __forceinline__ float fsig_r(float x) {
    float y; asm("tanh.approx.f32 %0,%1;" : "=f"(y) : "f"(x * 0.5f));
    return fmaf(0.5f, y, 0.5f);
}

/* ---------------- init ---------------- */
__global__ void k_init_last() {
    int i = blockIdx.x * blockDim.x + threadIdx.x;
    if (i < N_NODES) g_last[i] = -1;
}
__global__ void k_init_cnt() {
    int i = blockIdx.x * blockDim.x + threadIdx.x;
    if (i < N_NODES) g_cnt[i] = 0;
}

/* ---------------- last event per node ---------------- */
__global__ void k_last(const int* __restrict__ src, const int* __restrict__ dst) {
    int i = blockIdx.x * blockDim.x + threadIdx.x;
    if (i >= N_EV) return;
    atomicMax(&g_last[src[i]], i);
    atomicMax(&g_last[dst[i]], i);
}

/* ---------------- CSR build: count / scan / fill ---------------- */
__global__ void k_count(const int* __restrict__ ed) {
    int i = blockIdx.x * blockDim.x + threadIdx.x;
    if (i < N_SEDGE) atomicAdd(&g_cnt[ed[i]], 1);
}

__global__ void k_scanA() {
    int b = blockIdx.x, t = threadIdx.x;
    int base = b * SCHUNK + t * 4;
    int s = 0;
#pragma unroll
    for (int u = 0; u < 4; u++) { int i = base + u; if (i < N_NODES) s += g_cnt[i]; }
#pragma unroll
    for (int o = 16; o; o >>= 1) s += __shfl_xor_sync(0xFFFFFFFFu, s, o);
    __shared__ int ws[8];
    if ((t & 31) == 0) ws[t >> 5] = s;
    __syncthreads();
    if (t == 0) { int tot = 0; for (int w = 0; w < 8; w++) tot += ws[w]; g_part[b] = tot; }
}

__global__ void k_scanB() {
    int t = threadIdx.x;
    int v = (t < SNBLK) ? g_part[t] : 0;
    int lane = t & 31, wid = t >> 5;
    int inc = v;
#pragma unroll
    for (int o = 1; o < 32; o <<= 1) { int n = __shfl_up_sync(0xFFFFFFFFu, inc, o); if (lane >= o) inc += n; }
    __shared__ int ws[4];
    if (lane == 31) ws[wid] = inc;
    __syncthreads();
    if (t == 0) { int r = 0; for (int i = 0; i < 4; i++) { int x = ws[i]; ws[i] = r; r += x; } }
    __syncthreads();
    if (t < SNBLK) g_part[t] = inc - v + ws[wid];
}

__global__ void k_scanC() {
    int b = blockIdx.x, t = threadIdx.x;
    int base = b * SCHUNK + t * 4;
    int c[4]; int s = 0;
#pragma unroll
    for (int u = 0; u < 4; u++) { int i = base + u; c[u] = (i < N_NODES) ? g_cnt[i] : 0; s += c[u]; }
    int lane = t & 31, wid = t >> 5;
    int inc = s;
#pragma unroll
    for (int o = 1; o < 32; o <<= 1) { int n = __shfl_up_sync(0xFFFFFFFFu, inc, o); if (lane >= o) inc += n; }
    __shared__ int ws[8];
    if (lane == 31) ws[wid] = inc;
    __syncthreads();
    if (t == 0) { int r = 0; for (int i = 0; i < 8; i++) { int x = ws[i]; ws[i] = r; r += x; } }
    __syncthreads();
    int off = g_part[b] + ws[wid] + inc - s;
#pragma unroll
    for (int u = 0; u < 4; u++) {
        int i = base + u;
        if (i < N_NODES) { g_off[i] = off; g_pos[i] = off; }
        off += c[u];
    }
}

__global__ void k_fill(const int* __restrict__ es, const int* __restrict__ ed) {
    int i = blockIdx.x * blockDim.x + threadIdx.x;
    if (i >= N_SEDGE) return;
    int pos = atomicAdd(&g_pos[ed[i]], 1);
    g_csrs[pos] = es[i];
}

/* ---------------- fused GRU memory update (fp16 MMA, reg-resident A) ---------
 * K=96 -> 6 k16 steps; N=384 -> 8 passes x 6 tiles (r/z/n x2 per pass).
 * W fragments per-lane-contiguous: 48 B/lane per (p,k16) -> 3x LDS.128.
 */
#define GRU_WENT (8 * 6 * 32 * 6)   /* uint2 entries = 73728 B */
__global__ void __launch_bounds__(512, 1)
k_gru(const int* __restrict__ t, const float* __restrict__ msg,
      const float* __restrict__ w_ih, const float* __restrict__ b_ih,
      const float* __restrict__ b_hh,
      const float* __restrict__ time_w, const float* __restrict__ time_b) {
    extern __shared__ unsigned smu[];
    uint2* Wf  = (uint2*)smu;                 /* [p][k16][lane][t6] */
    float* Bsm = (float*)(Wf + GRU_WENT);
    float* Tw  = Bsm + 512;
    float* Tb  = Tw + 32;
    const int tid = threadIdx.x;

    for (int i = tid; i < GRU_WENT; i += 512) {
        int t6 = i % 6;
        int lane = (i / 6) & 31;
        int k16 = (i / 192) % 6;
        int p  = i / 1152;
        int g = t6 >> 1, jj = t6 & 1;
        int n8 = g * 16 + p * 2 + jj;
        int n = n8 * 8 + (lane >> 2);
        int k0 = k16 * 16 + 2 * (lane & 3);
        const float* wr = w_ih + n * 352 + 256;
        Wf[i] = make_uint2(h2pk(wr[k0], wr[k0 + 1]), h2pk(wr[k0 + 8], wr[k0 + 9]));
    }
    for (int k = tid; k < 128; k += 512) {
        Bsm[k]       = b_ih[k]       + b_hh[k];
        Bsm[128 + k] = b_ih[128 + k] + b_hh[128 + k];
        Bsm[256 + k] = b_ih[256 + k];
        Bsm[384 + k] = b_hh[256 + k];
    }
    if (tid < 32) { Tw[tid] = time_w[tid]; Tb[tid] = time_b[tid]; }
    __syncthreads();

    const int warp = tid >> 5, lane = tid & 31;
    const int grp = lane >> 2, tg = lane & 3;
    const int nwarps = gridDim.x * 16;

    for (int rg = blockIdx.x * 16 + warp; rg < N_NODES / 16; rg += nwarps) {
        const int node0 = rg * 16 + grp, node1 = node0 + 8;
        const int le0 = g_last[node0], le1 = g_last[node1];
        const bool h0 = le0 >= 0, h1 = le1 >= 0;
        const int e0 = h0 ? le0 : 0, e1 = h1 ? le1 : 0;
        const float tf0 = (float)t[e0];
        const float tf1 = (float)t[e1];
        const float* m0 = msg + (long)e0 * 64;
        const float* m1 = msg + (long)e1 * 64;

        unsigned a[6][4];
#pragma unroll
        for (int s = 0; s < 4; s++) {
            int k0 = s * 16 + 2 * tg;
            float2 v;
            v = __ldg((const float2*)(m0 + k0));     a[s][0] = h2pk(v.x, v.y);
            v = __ldg((const float2*)(m1 + k0));     a[s][1] = h2pk(v.x, v.y);
            v = __ldg((const float2*)(m0 + k0 + 8)); a[s][2] = h2pk(v.x, v.y);
            v = __ldg((const float2*)(m1 + k0 + 8)); a[s][3] = h2pk(v.x, v.y);
        }
#pragma unroll
        for (int s = 4; s < 6; s++) {
            int j0 = (s - 4) * 16 + 2 * tg;
            float wA = Tw[j0], bA = Tb[j0], wB = Tw[j0 + 1], bB = Tb[j0 + 1];
            float wC = Tw[j0 + 8], bC = Tb[j0 + 8], wD = Tw[j0 + 9], bD = Tb[j0 + 9];
            a[s][0] = h2pk(cosf(__fadd_rn(__fmul_rn(tf0, wA), bA)),
                           cosf(__fadd_rn(__fmul_rn(tf0, wB), bB)));
            a[s][1] = h2pk(cosf(__fadd_rn(__fmul_rn(tf1, wA), bA)),
                           cosf(__fadd_rn(__fmul_rn(tf1, wB), bB)));
            a[s][2] = h2pk(cosf(__fadd_rn(__fmul_rn(tf0, wC), bC)),
                           cosf(__fadd_rn(__fmul_rn(tf0, wD), bD)));
            a[s][3] = h2pk(cosf(__fadd_rn(__fmul_rn(tf1, wC), bC)),
                           cosf(__fadd_rn(__fmul_rn(tf1, wD), bD)));
        }

#pragma unroll 1
        for (int p = 0; p < 8; p++) {
            float acc[6][4];
#pragma unroll
            for (int q = 0; q < 6; q++)
#pragma unroll
                for (int i = 0; i < 4; i++) acc[q][i] = 0.f;

#pragma unroll
            for (int k16 = 0; k16 < 6; k16++) {
                const uint4* wp = (const uint4*)(Wf + ((p * 6 + k16) * 32 + lane) * 6);
                uint4 w0 = wp[0], w1 = wp[1], w2 = wp[2];
                mma16(acc[0], a[k16][0], a[k16][1], a[k16][2], a[k16][3], w0.x, w0.y);
                mma16(acc[1], a[k16][0], a[k16][1], a[k16][2], a[k16][3], w0.z, w0.w);
                mma16(acc[2], a[k16][0], a[k16][1], a[k16][2], a[k16][3], w1.x, w1.y);
                mma16(acc[3], a[k16][0], a[k16][1], a[k16][2], a[k16][3], w1.z, w1.w);
                mma16(acc[4], a[k16][0], a[k16][1], a[k16][2], a[k16][3], w2.x, w2.y);
                mma16(acc[5], a[k16][0], a[k16][1], a[k16][2], a[k16][3], w2.z, w2.w);
            }
#pragma unroll
            for (int jj = 0; jj < 2; jj++) {
                int kbase = (p * 2 + jj) * 8 + 2 * tg;
                float o0[2], o1[2];
#pragma unroll
                for (int ii = 0; ii < 2; ii++) {
                    int kk = kbase + ii;
                    float br = Bsm[kk], bz = Bsm[128 + kk];
                    float bin = Bsm[256 + kk], bhn = Bsm[384 + kk];
                    {
                        float r = fsig_r(acc[jj][ii] + br);
                        float z = fsig(acc[2 + jj][ii] + bz);
                        float nn = ftanh_(acc[4 + jj][ii] + bin + r * bhn);
                        o0[ii] = h0 ? (1.f - z) * nn : 0.f;
                    }
                    {
                        float r = fsig_r(acc[jj][2 + ii] + br);
                        float z = fsig(acc[2 + jj][2 + ii] + bz);
                        float nn = ftanh_(acc[4 + jj][2 + ii] + bin + r * bhn);
                        o1[ii] = h1 ? (1.f - z) * nn : 0.f;
                    }
                }
                *(float2*)&g_mem[(long)node0 * 128 + kbase] = make_float2(o0[0], o0[1]);
                *(float2*)&g_mem[(long)node1 * 128 + kbase] = make_float2(o1[0], o1[1]);
            }
        }
    }
}

/* ---------------- GAT projection + attention scores (fp16 MMA) ---------------
 * K=128 -> 8 k16 steps; N=128 -> 2 halves x 8 tiles. 64 B/lane -> pad to 80 B.
 */
#define XW_ENT (8 * 2 * 32 * 10)   /* uint2 = 40960 B */
__global__ void __launch_bounds__(512, 1)
k_gatx(const float* __restrict__ gat_w, const float* __restrict__ att_src,
       const float* __restrict__ att_dst) {
    extern __shared__ unsigned smu[];
    uint2* Wf  = (uint2*)smu;              /* [k16][h][lane][n8(+pad)] */
    float* Asm = (float*)(Wf + XW_ENT);
    const int tid = threadIdx.x;

    for (int i = tid; i < XW_ENT; i += 512) {
        int n8 = i % 10;
        int lane = (i / 10) & 31;
        int h = (i / 320) & 1;
        int k16 = i / 640;
        uint2 v = make_uint2(0u, 0u);
        if (n8 < 8) {
            int n = (h * 8 + n8) * 8 + (lane >> 2);
            int k0 = k16 * 16 + 2 * (lane & 3);
            const float* wr = gat_w + n * 128;
            v = make_uint2(h2pk(wr[k0], wr[k0 + 1]), h2pk(wr[k0 + 8], wr[k0 + 9]));
        }
        Wf[i] = v;
    }
    if (tid < 256) Asm[tid] = (tid < 128) ? att_src[tid] : att_dst[tid - 128];
    __syncthreads();

    const int warp = tid >> 5, lane = tid & 31;
    const int grp = lane >> 2, tg = lane & 3;
    const int nwarps = gridDim.x * 16;

    for (int rg = blockIdx.x * 16 + warp; rg < N_NODES / 16; rg += nwarps) {
        const int node0 = rg * 16 + grp, node1 = node0 + 8;
        const float* r0 = g_mem + (long)node0 * 128;
        const float* r1 = g_mem + (long)node1 * 128;

        unsigned a[8][4];
#pragma unroll
        for (int s = 0; s < 8; s++) {
            int k0 = s * 16 + 2 * tg;
            float2 v;
            v = __ldg((const float2*)(r0 + k0));     a[s][0] = h2pk(v.x, v.y);
            v = __ldg((const float2*)(r1 + k0));     a[s][1] = h2pk(v.x, v.y);
            v = __ldg((const float2*)(r0 + k0 + 8)); a[s][2] = h2pk(v.x, v.y);
            v = __ldg((const float2*)(r1 + k0 + 8)); a[s][3] = h2pk(v.x, v.y);
        }

        float ps0 = 0.f, pd0 = 0.f, ps1 = 0.f, pd1 = 0.f;
#pragma unroll 1
        for (int h = 0; h < 2; h++) {
            float acc[8][4];
#pragma unroll
            for (int q = 0; q < 8; q++)
#pragma unroll
                for (int i = 0; i < 4; i++) acc[q][i] = 0.f;

#pragma unroll
            for (int k16 = 0; k16 < 8; k16++) {
                const uint4* wp = (const uint4*)(Wf + ((k16 * 2 + h) * 32 + lane) * 10);
                uint4 wa = wp[0], wb = wp[1], wc = wp[2], wd = wp[3];
                mma16(acc[0], a[k16][0], a[k16][1], a[k16][2], a[k16][3], wa.x, wa.y);
                mma16(acc[1], a[k16][0], a[k16][1], a[k16][2], a[k16][3], wa.z, wa.w);
                mma16(acc[2], a[k16][0], a[k16][1], a[k16][2], a[k16][3], wb.x, wb.y);
                mma16(acc[3], a[k16][0], a[k16][1], a[k16][2], a[k16][3], wb.z, wb.w);
                mma16(acc[4], a[k16][0], a[k16][1], a[k16][2], a[k16][3], wc.x, wc.y);
                mma16(acc[5], a[k16][0], a[k16][1], a[k16][2], a[k16][3], wc.z, wc.w);
                mma16(acc[6], a[k16][0], a[k16][1], a[k16][2], a[k16][3], wd.x, wd.y);
                mma16(acc[7], a[k16][0], a[k16][1], a[k16][2], a[k16][3], wd.z, wd.w);
            }
#pragma unroll
            for (int n8 = 0; n8 < 8; n8++) {
                int col = (h * 8 + n8) * 8 + 2 * tg;
                float s0 = Asm[col], s1 = Asm[col + 1];
                float d0 = Asm[128 + col], d1 = Asm[128 + col + 1];
                ps0 += acc[n8][0] * s0 + acc[n8][1] * s1;
                pd0 += acc[n8][0] * d0 + acc[n8][1] * d1;
                ps1 += acc[n8][2] * s0 + acc[n8][3] * s1;
                pd1 += acc[n8][2] * d0 + acc[n8][3] * d1;
                *(__half2*)&g_xh[(long)node0 * 128 + col] =
                    __floats2half2_rn(acc[n8][0], acc[n8][1]);
                *(__half2*)&g_xh[(long)node1 * 128 + col] =
                    __floats2half2_rn(acc[n8][2], acc[n8][3]);
            }
        }
#pragma unroll
        for (int o = 1; o <= 2; o <<= 1) {
            ps0 += __shfl_xor_sync(0xFFFFFFFFu, ps0, o);
            pd0 += __shfl_xor_sync(0xFFFFFFFFu, pd0, o);
            ps1 += __shfl_xor_sync(0xFFFFFFFFu, ps1, o);
            pd1 += __shfl_xor_sync(0xFFFFFFFFu, pd1, o);
        }
        if (tg == 0) {
            g_as[node0] = ps0; g_ad[node0] = pd0;
            g_as[node1] = ps1; g_ad[node1] = pd1;
        }
    }
}

/* ---------------- fused GAT softmax + aggregation: warp per node ------------- */
__global__ void __launch_bounds__(256)
k_agg() {
    int gt = blockIdx.x * blockDim.x + threadIdx.x;
    int node = gt >> 5, lane = gt & 31;
    if (node >= N_NODES) return;
    const int start = g_off[node], end = g_pos[node];
    const float ad = g_ad[node];
    float e_self = g_as[node] + ad;
    e_self = (e_self > 0.f) ? e_self : 0.2f * e_self;

    const float w0 = __expf(e_self);
    uint2 raw = __ldg((const uint2*)(g_xh + (long)node * 128) + lane);
    float2 lo = __half22float2(*(__half2*)&raw.x);
    float2 hi = __half22float2(*(__half2*)&raw.y);
    float4 acc = make_float4(w0 * lo.x, w0 * lo.y, w0 * hi.x, w0 * hi.y);
    float den_l = 0.f;

    for (int b = start; b < end; b += 32) {
        int rem = end - b;
        int n = rem < 32 ? rem : 32;
        int  s_l = 0;
        float w_l = 0.f;
        if (lane < n) {
            s_l = __ldg(&g_csrs[b + lane]);
            float e = __ldg(&g_as[s_l]) + ad;
            e = (e > 0.f) ? e : 0.2f * e;
            w_l = __expf(e);
            den_l += w_l;
        }
#pragma unroll 4
        for (int j = 0; j < n; j++) {
            int   s = __shfl_sync(0xFFFFFFFFu, s_l, j);
            float w = __shfl_sync(0xFFFFFFFFu, w_l, j);
            uint2 r = __ldg((const uint2*)(g_xh + (long)s * 128) + lane);
            float2 l2 = __half22float2(*(__half2*)&r.x);
            float2 h2 = __half22float2(*(__half2*)&r.y);
            acc.x += w * l2.x; acc.y += w * l2.y;
            acc.z += w * h2.x; acc.w += w * h2.y;
        }
    }
#pragma unroll
    for (int o = 16; o; o >>= 1) den_l += __shfl_xor_sync(0xFFFFFFFFu, den_l, o);
    float inv = 1.f / (den_l + w0);
    acc.x *= inv; acc.y *= inv; acc.z *= inv; acc.w *= inv;
    ((float4*)(g_z + (long)node * 128))[lane] = acc;
}

/* ---------------- fused ReLU + classifier (fp16 MMA) ---------------- */
#define CW_ENT (8 * 32 * 10)   /* uint2 = 20480 B */
__global__ void __launch_bounds__(512, 1)
k_cls(const float* __restrict__ cls_w, const float* __restrict__ cls_b,
      const float* __restrict__ gat_b, float* __restrict__ out) {
    extern __shared__ unsigned smu[];
    uint2* Wf = (uint2*)smu;              /* [k16][lane][n8(+pad)] */
    float* Cb = (float*)(Wf + CW_ENT);
    float* Gb = Cb + 64;
    const int tid = threadIdx.x;

    for (int i = tid; i < CW_ENT; i += 512) {
        int n8 = i % 10;
        int lane = (i / 10) & 31;
        int k16 = i / 320;
        uint2 v = make_uint2(0u, 0u);
        if (n8 < 8) {
            int n = n8 * 8 + (lane >> 2);
            int k0 = k16 * 16 + 2 * (lane & 3);
            const float* wr = cls_w + n * 128;
            v = make_uint2(h2pk(wr[k0], wr[k0 + 1]), h2pk(wr[k0 + 8], wr[k0 + 9]));
        }
        Wf[i] = v;
    }
    if (tid < 64) Cb[tid] = cls_b[tid];
    if (tid < 128) Gb[tid] = gat_b[tid];
    __syncthreads();

    const int warp = tid >> 5, lane = tid & 31;
    const int grp = lane >> 2, tg = lane & 3;
    const int nwarps = gridDim.x * 16;

    for (int rg = blockIdx.x * 16 + warp; rg < N_NODES / 16; rg += nwarps) {
        const int node0 = rg * 16 + grp, node1 = node0 + 8;
        const float* r0 = g_z + (long)node0 * 128;
        const float* r1 = g_z + (long)node1 * 128;

        unsigned a[8][4];
#pragma unroll
        for (int s = 0; s < 8; s++) {
            int k0 = s * 16 + 2 * tg;
            float2 gb0 = *(float2*)&Gb[k0];
            float2 gb1 = *(float2*)&Gb[k0 + 8];
            float2 v;
            v = __ldg((const float2*)(r0 + k0));
            a[s][0] = h2pk(fmaxf(v.x + gb0.x, 0.f), fmaxf(v.y + gb0.y, 0.f));
            v = __ldg((const float2*)(r1 + k0));
            a[s][1] = h2pk(fmaxf(v.x + gb0.x, 0.f), fmaxf(v.y + gb0.y, 0.f));
            v = __ldg((const float2*)(r0 + k0 + 8));
            a[s][2] = h2pk(fmaxf(v.x + gb1.x, 0.f), fmaxf(v.y + gb1.y, 0.f));
            v = __ldg((const float2*)(r1 + k0 + 8));
            a[s][3] = h2pk(fmaxf(v.x + gb1.x, 0.f), fmaxf(v.y + gb1.y, 0.f));
        }

        float acc[8][4];
#pragma unroll
        for (int q = 0; q < 8; q++)
#pragma unroll
            for (int i = 0; i < 4; i++) acc[q][i] = 0.f;

#pragma unroll
        for (int k16 = 0; k16 < 8; k16++) {
            const uint4* wp = (const uint4*)(Wf + (k16 * 32 + lane) * 10);
            uint4 wa = wp[0], wb = wp[1], wc = wp[2], wd = wp[3];
            mma16(acc[0], a[k16][0], a[k16][1], a[k16][2], a[k16][3], wa.x, wa.y);
            mma16(acc[1], a[k16][0], a[k16][1], a[k16][2], a[k16][3], wa.z, wa.w);
            mma16(acc[2], a[k16][0], a[k16][1], a[k16][2], a[k16][3], wb.x, wb.y);
            mma16(acc[3], a[k16][0], a[k16][1], a[k16][2], a[k16][3], wb.z, wb.w);
            mma16(acc[4], a[k16][0], a[k16][1], a[k16][2], a[k16][3], wc.x, wc.y);
            mma16(acc[5], a[k16][0], a[k16][1], a[k16][2], a[k16][3], wc.z, wc.w);
            mma16(acc[6], a[k16][0], a[k16][1], a[k16][2], a[k16][3], wd.x, wd.y);
            mma16(acc[7], a[k16][0], a[k16][1], a[k16][2], a[k16][3], wd.z, wd.w);
        }
#pragma unroll
        for (int n8 = 0; n8 < 8; n8++) {
            int col = n8 * 8 + 2 * tg;
            float b0 = Cb[col], b1 = Cb[col + 1];
            *(float2*)&out[(long)node0 * 64 + col] =
                make_float2(acc[n8][0] + b0, acc[n8][1] + b1);
            *(float2*)&out[(long)node1 * 64 + col] =
                make_float2(acc[n8][2] + b0, acc[n8][3] + b1);
        }
    }
}

/* ---------------- launch ----------------
 * Fork-join: CSR build overlapped on a side stream; joined before k_agg.
 * Host issue order keeps k_gru as the 4th kernel for the ncu window.
 */
extern "C" void kernel_launch(void* const* d_in, const int* in_sizes, int n_in,
                              void* d_out, int out_size) {
    const int*   src    = (const int*)  d_in[0];
    const int*   dst    = (const int*)  d_in[1];
    const int*   t      = (const int*)  d_in[2];
    const float* msg    = (const float*)d_in[3];
    const int*   sei    = (const int*)  d_in[4];
    const float* time_w = (const float*)d_in[5];
    const float* time_b = (const float*)d_in[6];
    const float* w_ih   = (const float*)d_in[7];
    /* d_in[8] = gru_w_hh: unused (memory == 0 at update time) */
    const float* b_ih   = (const float*)d_in[9];
    const float* b_hh   = (const float*)d_in[10];
    const float* gat_w  = (const float*)d_in[11];
    const float* att_s  = (const float*)d_in[12];
    const float* att_d  = (const float*)d_in[13];
    const float* gat_b  = (const float*)d_in[14];
    const float* cls_w  = (const float*)d_in[15];
    const float* cls_b  = (const float*)d_in[16];
    float* out = (float*)d_out;
    const int* es = sei;
    const int* ed = sei + N_SEDGE;
    (void)in_sizes; (void)n_in; (void)out_size;

    static cudaStream_t s1 = 0;
    static cudaEvent_t evRoot = 0, evSide = 0;
    static int ok = -1;
    if (ok < 0) {
        ok = 1;
        if (cudaStreamCreateWithFlags(&s1, cudaStreamNonBlocking) != cudaSuccess) ok = 0;
        if (ok && cudaEventCreateWithFlags(&evRoot, cudaEventDisableTiming) != cudaSuccess) ok = 0;
        if (ok && cudaEventCreateWithFlags(&evSide, cudaEventDisableTiming) != cudaSuccess) ok = 0;
    }
    cudaStream_t sC = ok ? s1 : 0;

    if (ok) { cudaEventRecord(evRoot, 0); cudaStreamWaitEvent(s1, evRoot, 0); }

    k_init_last<<<(N_NODES + 255) / 256, 256>>>();
    k_last     <<<(N_EV + 255) / 256, 256>>>(src, dst);
    k_init_cnt <<<(N_NODES + 255) / 256, 256, 0, sC>>>();

    {
        size_t smb = (size_t)GRU_WENT * 8 + (512 + 64) * 4;
        cudaFuncSetAttribute(k_gru, cudaFuncAttributeMaxDynamicSharedMemorySize, (int)smb);
        k_gru<<<148, 512, smb>>>(t, msg, w_ih, b_ih, b_hh, time_w, time_b);
    }

    k_count<<<(N_SEDGE + 255) / 256, 256, 0, sC>>>(ed);
    k_scanA<<<SNBLK, 256, 0, sC>>>();
    k_scanB<<<1, 128, 0, sC>>>();
    k_scanC<<<SNBLK, 256, 0, sC>>>();
    k_fill <<<(N_SEDGE + 255) / 256, 256, 0, sC>>>(es, ed);
    if (ok) cudaEventRecord(evSide, s1);

    {
        size_t smb = (size_t)XW_ENT * 8 + 256 * 4;
        cudaFuncSetAttribute(k_gatx, cudaFuncAttributeMaxDynamicSharedMemorySize, (int)smb);
        k_gatx<<<148, 512, smb>>>(gat_w, att_s, att_d);
    }

    if (ok) cudaStreamWaitEvent(0, evSide, 0);
    k_agg<<<(N_NODES * 32 + 255) / 256, 256>>>();
    {
        size_t smb = (size_t)CW_ENT * 8 + 192 * 4;
        cudaFuncSetAttribute(k_cls, cudaFuncAttributeMaxDynamicSharedMemorySize, (int)smb);
        k_cls<<<148, 512, smb>>>(cls_w, cls_b, gat_b, out);
    }
}

// round 16
// speedup vs baseline: 6.6921x; 1.1059x over previous
#include <cuda_runtime.h>
#include <cuda_fp16.h>
#include <math.h>

#define N_NODES 100000
#define N_EV    200000
#define N_SEDGE 1600000
#define SCHUNK  1024
#define SNBLK   ((N_NODES + SCHUNK - 1) / SCHUNK)

/* ---------------- device scratch (no allocations allowed) ---------------- */
__device__ __align__(16) int    g_last[N_NODES];
__device__ __align__(16) __half g_xh  [N_NODES * 128];
__device__ __align__(16) float  g_as  [N_NODES];
__device__ __align__(16) float  g_ad  [N_NODES];
__device__ __align__(16) float  g_z   [N_NODES * 128];
__device__ __align__(16) int    g_cnt [N_NODES];
__device__ __align__(16) int    g_off [N_NODES];
__device__ __align__(16) int    g_pos [N_NODES];
__device__               int    g_part[SNBLK];
__device__ __align__(16) int    g_csrs[N_SEDGE];

/* ---------------- fp16 MMA helpers (m16n8k16, f32 accum) ---------------- */
__device__ __forceinline__ unsigned h2pk(float a, float b) {
    __half2 h = __floats2half2_rn(a, b);
    return *(unsigned*)&h;
}
__device__ __forceinline__ void mma16(float (&c)[4], unsigned a0, unsigned a1,
                                      unsigned a2, unsigned a3,
                                      unsigned b0, unsigned b1) {
    asm("mma.sync.aligned.m16n8k16.row.col.f32.f16.f16.f32 "
        "{%0,%1,%2,%3},{%4,%5,%6,%7},{%8,%9},{%0,%1,%2,%3};"
        : "+f"(c[0]), "+f"(c[1]), "+f"(c[2]), "+f"(c[3])
        : "r"(a0), "r"(a1), "r"(a2), "r"(a3), "r"(b0), "r"(b1));
}
__device__ __forceinline__ float fsig(float x) {
    return __fdividef(1.f, 1.f + __expf(-x));
}
__device__ __forceinline__ float ftanh_(float x) {
    return 1.f - __fdividef(2.f, __expf(2.f * x) + 1.f);
}
__device__ __forceinline__ float fsig_r(float x) {
    float y; asm("tanh.approx.f32 %0,%1;" : "=f"(y) : "f"(x * 0.5f));
    return fmaf(0.5f, y, 0.5f);
}

/* ---------------- init ---------------- */
__global__ void k_init_last() {
    int i = blockIdx.x * blockDim.x + threadIdx.x;
    if (i < N_NODES) g_last[i] = -1;
}
__global__ void k_init_cnt() {
    int i = blockIdx.x * blockDim.x + threadIdx.x;
    if (i < N_NODES) g_cnt[i] = 0;
}

/* ---------------- last event per node ---------------- */
__global__ void k_last(const int* __restrict__ src, const int* __restrict__ dst) {
    int i = blockIdx.x * blockDim.x + threadIdx.x;
    if (i >= N_EV) return;
    atomicMax(&g_last[src[i]], i);
    atomicMax(&g_last[dst[i]], i);
}

/* ---------------- CSR build: count / scan / fill ---------------- */
__global__ void k_count(const int* __restrict__ ed) {
    int i = blockIdx.x * blockDim.x + threadIdx.x;
    if (i < N_SEDGE) atomicAdd(&g_cnt[ed[i]], 1);
}

__global__ void k_scanA() {
    int b = blockIdx.x, t = threadIdx.x;
    int base = b * SCHUNK + t * 4;
    int s = 0;
#pragma unroll
    for (int u = 0; u < 4; u++) { int i = base + u; if (i < N_NODES) s += g_cnt[i]; }
#pragma unroll
    for (int o = 16; o; o >>= 1) s += __shfl_xor_sync(0xFFFFFFFFu, s, o);
    __shared__ int ws[8];
    if ((t & 31) == 0) ws[t >> 5] = s;
    __syncthreads();
    if (t == 0) { int tot = 0; for (int w = 0; w < 8; w++) tot += ws[w]; g_part[b] = tot; }
}

__global__ void k_scanB() {
    int t = threadIdx.x;
    int v = (t < SNBLK) ? g_part[t] : 0;
    int lane = t & 31, wid = t >> 5;
    int inc = v;
#pragma unroll
    for (int o = 1; o < 32; o <<= 1) { int n = __shfl_up_sync(0xFFFFFFFFu, inc, o); if (lane >= o) inc += n; }
    __shared__ int ws[4];
    if (lane == 31) ws[wid] = inc;
    __syncthreads();
    if (t == 0) { int r = 0; for (int i = 0; i < 4; i++) { int x = ws[i]; ws[i] = r; r += x; } }
    __syncthreads();
    if (t < SNBLK) g_part[t] = inc - v + ws[wid];
}

__global__ void k_scanC() {
    int b = blockIdx.x, t = threadIdx.x;
    int base = b * SCHUNK + t * 4;
    int c[4]; int s = 0;
#pragma unroll
    for (int u = 0; u < 4; u++) { int i = base + u; c[u] = (i < N_NODES) ? g_cnt[i] : 0; s += c[u]; }
    int lane = t & 31, wid = t >> 5;
    int inc = s;
#pragma unroll
    for (int o = 1; o < 32; o <<= 1) { int n = __shfl_up_sync(0xFFFFFFFFu, inc, o); if (lane >= o) inc += n; }
    __shared__ int ws[8];
    if (lane == 31) ws[wid] = inc;
    __syncthreads();
    if (t == 0) { int r = 0; for (int i = 0; i < 8; i++) { int x = ws[i]; ws[i] = r; r += x; } }
    __syncthreads();
    int off = g_part[b] + ws[wid] + inc - s;
#pragma unroll
    for (int u = 0; u < 4; u++) {
        int i = base + u;
        if (i < N_NODES) { g_off[i] = off; g_pos[i] = off; }
        off += c[u];
    }
}

__global__ void k_fill(const int* __restrict__ es, const int* __restrict__ ed) {
    int i = blockIdx.x * blockDim.x + threadIdx.x;
    if (i >= N_SEDGE) return;
    int pos = atomicAdd(&g_pos[ed[i]], 1);
    g_csrs[pos] = es[i];
}

/* ---------------- FUSED GRU + GAT projection + attention scores --------------
 * The warp computing mem rows [rg*16, rg*16+16) feeds them straight into the
 * gatx GEMM: gru epilogue output (cols (2p+jj)*8+2tg+{0,1}, rows grp/grp+8)
 * IS the m16n8k16 A-fragment layout (a2[p][jj*2 + node]) — no g_mem roundtrip.
 * Outputs: g_xh (fp16 x for k_agg), g_as/g_ad (attention scores).
 */
#define GRU_WENT (8 * 6 * 32 * 6)    /* uint2 = 73728 B */
#define XW_ENT   (8 * 2 * 32 * 10)   /* uint2 = 40960 B */
__global__ void __launch_bounds__(512, 1)
k_grux(const int* __restrict__ t, const float* __restrict__ msg,
       const float* __restrict__ w_ih, const float* __restrict__ b_ih,
       const float* __restrict__ b_hh,
       const float* __restrict__ time_w, const float* __restrict__ time_b,
       const float* __restrict__ gat_w, const float* __restrict__ att_src,
       const float* __restrict__ att_dst) {
    extern __shared__ unsigned smu[];
    uint2* GWf = (uint2*)smu;                  /* [p][k16][lane][t6] */
    uint2* XWf = GWf + GRU_WENT;               /* [k16][h][lane][n8(+pad)] */
    float* Bsm = (float*)(XWf + XW_ENT);       /* gate biases 4*128 */
    float* Tw  = Bsm + 512;
    float* Tb  = Tw + 32;
    float* Asm = Tb + 32;                      /* att_src[128], att_dst[128] */
    const int tid = threadIdx.x;

    for (int i = tid; i < GRU_WENT; i += 512) {
        int t6 = i % 6;
        int lane = (i / 6) & 31;
        int k16 = (i / 192) % 6;
        int p  = i / 1152;
        int g = t6 >> 1, jj = t6 & 1;
        int n8 = g * 16 + p * 2 + jj;
        int n = n8 * 8 + (lane >> 2);
        int k0 = k16 * 16 + 2 * (lane & 3);
        const float* wr = w_ih + n * 352 + 256;
        GWf[i] = make_uint2(h2pk(wr[k0], wr[k0 + 1]), h2pk(wr[k0 + 8], wr[k0 + 9]));
    }
    for (int i = tid; i < XW_ENT; i += 512) {
        int n8 = i % 10;
        int lane = (i / 10) & 31;
        int h = (i / 320) & 1;
        int k16 = i / 640;
        uint2 v = make_uint2(0u, 0u);
        if (n8 < 8) {
            int n = (h * 8 + n8) * 8 + (lane >> 2);
            int k0 = k16 * 16 + 2 * (lane & 3);
            const float* wr = gat_w + n * 128;
            v = make_uint2(h2pk(wr[k0], wr[k0 + 1]), h2pk(wr[k0 + 8], wr[k0 + 9]));
        }
        XWf[i] = v;
    }
    for (int k = tid; k < 128; k += 512) {
        Bsm[k]       = b_ih[k]       + b_hh[k];
        Bsm[128 + k] = b_ih[128 + k] + b_hh[128 + k];
        Bsm[256 + k] = b_ih[256 + k];
        Bsm[384 + k] = b_hh[256 + k];
    }
    if (tid < 32) { Tw[tid] = time_w[tid]; Tb[tid] = time_b[tid]; }
    if (tid < 256) Asm[tid] = (tid < 128) ? att_src[tid] : att_dst[tid - 128];
    __syncthreads();

    const int warp = tid >> 5, lane = tid & 31;
    const int grp = lane >> 2, tg = lane & 3;
    const int nwarps = gridDim.x * 16;

    for (int rg = blockIdx.x * 16 + warp; rg < N_NODES / 16; rg += nwarps) {
        const int node0 = rg * 16 + grp, node1 = node0 + 8;
        const int le0 = g_last[node0], le1 = g_last[node1];
        const bool h0 = le0 >= 0, h1 = le1 >= 0;
        const int e0 = h0 ? le0 : 0, e1 = h1 ? le1 : 0;
        const float tf0 = (float)t[e0];
        const float tf1 = (float)t[e1];
        const float* m0 = msg + (long)e0 * 64;
        const float* m1 = msg + (long)e1 * 64;

        /* ---- GRU A fragments (reg-resident) ---- */
        unsigned a[6][4];
#pragma unroll
        for (int s = 0; s < 4; s++) {
            int k0 = s * 16 + 2 * tg;
            float2 v;
            v = __ldg((const float2*)(m0 + k0));     a[s][0] = h2pk(v.x, v.y);
            v = __ldg((const float2*)(m1 + k0));     a[s][1] = h2pk(v.x, v.y);
            v = __ldg((const float2*)(m0 + k0 + 8)); a[s][2] = h2pk(v.x, v.y);
            v = __ldg((const float2*)(m1 + k0 + 8)); a[s][3] = h2pk(v.x, v.y);
        }
#pragma unroll
        for (int s = 4; s < 6; s++) {
            int j0 = (s - 4) * 16 + 2 * tg;
            float wA = Tw[j0], bA = Tb[j0], wB = Tw[j0 + 1], bB = Tb[j0 + 1];
            float wC = Tw[j0 + 8], bC = Tb[j0 + 8], wD = Tw[j0 + 9], bD = Tb[j0 + 9];
            a[s][0] = h2pk(cosf(__fadd_rn(__fmul_rn(tf0, wA), bA)),
                           cosf(__fadd_rn(__fmul_rn(tf0, wB), bB)));
            a[s][1] = h2pk(cosf(__fadd_rn(__fmul_rn(tf1, wA), bA)),
                           cosf(__fadd_rn(__fmul_rn(tf1, wB), bB)));
            a[s][2] = h2pk(cosf(__fadd_rn(__fmul_rn(tf0, wC), bC)),
                           cosf(__fadd_rn(__fmul_rn(tf0, wD), bD)));
            a[s][3] = h2pk(cosf(__fadd_rn(__fmul_rn(tf1, wC), bC)),
                           cosf(__fadd_rn(__fmul_rn(tf1, wD), bD)));
        }

        /* ---- GRU passes: h straight into gatx A fragments a2 ---- */
        unsigned a2[8][4];
#pragma unroll 1
        for (int p = 0; p < 8; p++) {
            float acc[6][4];
#pragma unroll
            for (int q = 0; q < 6; q++)
#pragma unroll
                for (int i = 0; i < 4; i++) acc[q][i] = 0.f;

#pragma unroll
            for (int k16 = 0; k16 < 6; k16++) {
                const uint4* wp = (const uint4*)(GWf + ((p * 6 + k16) * 32 + lane) * 6);
                uint4 w0 = wp[0], w1 = wp[1], w2 = wp[2];
                mma16(acc[0], a[k16][0], a[k16][1], a[k16][2], a[k16][3], w0.x, w0.y);
                mma16(acc[1], a[k16][0], a[k16][1], a[k16][2], a[k16][3], w0.z, w0.w);
                mma16(acc[2], a[k16][0], a[k16][1], a[k16][2], a[k16][3], w1.x, w1.y);
                mma16(acc[3], a[k16][0], a[k16][1], a[k16][2], a[k16][3], w1.z, w1.w);
                mma16(acc[4], a[k16][0], a[k16][1], a[k16][2], a[k16][3], w2.x, w2.y);
                mma16(acc[5], a[k16][0], a[k16][1], a[k16][2], a[k16][3], w2.z, w2.w);
            }
#pragma unroll
            for (int jj = 0; jj < 2; jj++) {
                int kbase = (p * 2 + jj) * 8 + 2 * tg;
                float o0[2], o1[2];
#pragma unroll
                for (int ii = 0; ii < 2; ii++) {
                    int kk = kbase + ii;
                    float br = Bsm[kk], bz = Bsm[128 + kk];
                    float bin = Bsm[256 + kk], bhn = Bsm[384 + kk];
                    {
                        float r = fsig_r(acc[jj][ii] + br);
                        float z = fsig(acc[2 + jj][ii] + bz);
                        float nn = ftanh_(acc[4 + jj][ii] + bin + r * bhn);
                        o0[ii] = h0 ? (1.f - z) * nn : 0.f;
                    }
                    {
                        float r = fsig_r(acc[jj][2 + ii] + br);
                        float z = fsig(acc[2 + jj][2 + ii] + bz);
                        float nn = ftanh_(acc[4 + jj][2 + ii] + bin + r * bhn);
                        o1[ii] = h1 ? (1.f - z) * nn : 0.f;
                    }
                }
                /* jj=0 -> k16-lo half (slots 0,1); jj=1 -> k16-hi (slots 2,3) */
                a2[p][jj * 2]     = h2pk(o0[0], o0[1]);
                a2[p][jj * 2 + 1] = h2pk(o1[0], o1[1]);
            }
        }

        /* ---- GAT projection + fused attention scores ---- */
        float ps0 = 0.f, pd0 = 0.f, ps1 = 0.f, pd1 = 0.f;
#pragma unroll 1
        for (int h = 0; h < 2; h++) {
            float acc[8][4];
#pragma unroll
            for (int q = 0; q < 8; q++)
#pragma unroll
                for (int i = 0; i < 4; i++) acc[q][i] = 0.f;

#pragma unroll
            for (int k16 = 0; k16 < 8; k16++) {
                const uint4* wp = (const uint4*)(XWf + ((k16 * 2 + h) * 32 + lane) * 10);
                uint4 wa = wp[0], wb = wp[1], wc = wp[2], wd = wp[3];
                mma16(acc[0], a2[k16][0], a2[k16][1], a2[k16][2], a2[k16][3], wa.x, wa.y);
                mma16(acc[1], a2[k16][0], a2[k16][1], a2[k16][2], a2[k16][3], wa.z, wa.w);
                mma16(acc[2], a2[k16][0], a2[k16][1], a2[k16][2], a2[k16][3], wb.x, wb.y);
                mma16(acc[3], a2[k16][0], a2[k16][1], a2[k16][2], a2[k16][3], wb.z, wb.w);
                mma16(acc[4], a2[k16][0], a2[k16][1], a2[k16][2], a2[k16][3], wc.x, wc.y);
                mma16(acc[5], a2[k16][0], a2[k16][1], a2[k16][2], a2[k16][3], wc.z, wc.w);
                mma16(acc[6], a2[k16][0], a2[k16][1], a2[k16][2], a2[k16][3], wd.x, wd.y);
                mma16(acc[7], a2[k16][0], a2[k16][1], a2[k16][2], a2[k16][3], wd.z, wd.w);
            }
#pragma unroll
            for (int n8 = 0; n8 < 8; n8++) {
                int col = (h * 8 + n8) * 8 + 2 * tg;
                float s0 = Asm[col], s1 = Asm[col + 1];
                float d0 = Asm[128 + col], d1 = Asm[128 + col + 1];
                ps0 += acc[n8][0] * s0 + acc[n8][1] * s1;
                pd0 += acc[n8][0] * d0 + acc[n8][1] * d1;
                ps1 += acc[n8][2] * s0 + acc[n8][3] * s1;
                pd1 += acc[n8][2] * d0 + acc[n8][3] * d1;
                *(__half2*)&g_xh[(long)node0 * 128 + col] =
                    __floats2half2_rn(acc[n8][0], acc[n8][1]);
                *(__half2*)&g_xh[(long)node1 * 128 + col] =
                    __floats2half2_rn(acc[n8][2], acc[n8][3]);
            }
        }
#pragma unroll
        for (int o = 1; o <= 2; o <<= 1) {
            ps0 += __shfl_xor_sync(0xFFFFFFFFu, ps0, o);
            pd0 += __shfl_xor_sync(0xFFFFFFFFu, pd0, o);
            ps1 += __shfl_xor_sync(0xFFFFFFFFu, ps1, o);
            pd1 += __shfl_xor_sync(0xFFFFFFFFu, pd1, o);
        }
        if (tg == 0) {
            g_as[node0] = ps0; g_ad[node0] = pd0;
            g_as[node1] = ps1; g_ad[node1] = pd1;
        }
    }
}

/* ---------------- fused GAT softmax + aggregation: warp per node ------------- */
__global__ void __launch_bounds__(256)
k_agg() {
    int gt = blockIdx.x * blockDim.x + threadIdx.x;
    int node = gt >> 5, lane = gt & 31;
    if (node >= N_NODES) return;
    const int start = g_off[node], end = g_pos[node];
    const float ad = g_ad[node];
    float e_self = g_as[node] + ad;
    e_self = (e_self > 0.f) ? e_self : 0.2f * e_self;

    const float w0 = __expf(e_self);
    uint2 raw = __ldg((const uint2*)(g_xh + (long)node * 128) + lane);
    float2 lo = __half22float2(*(__half2*)&raw.x);
    float2 hi = __half22float2(*(__half2*)&raw.y);
    float4 acc = make_float4(w0 * lo.x, w0 * lo.y, w0 * hi.x, w0 * hi.y);
    float den_l = 0.f;

    for (int b = start; b < end; b += 32) {
        int rem = end - b;
        int n = rem < 32 ? rem : 32;
        int  s_l = 0;
        float w_l = 0.f;
        if (lane < n) {
            s_l = __ldg(&g_csrs[b + lane]);
            float e = __ldg(&g_as[s_l]) + ad;
            e = (e > 0.f) ? e : 0.2f * e;
            w_l = __expf(e);
            den_l += w_l;
        }
#pragma unroll 4
        for (int j = 0; j < n; j++) {
            int   s = __shfl_sync(0xFFFFFFFFu, s_l, j);
            float w = __shfl_sync(0xFFFFFFFFu, w_l, j);
            uint2 r = __ldg((const uint2*)(g_xh + (long)s * 128) + lane);
            float2 l2 = __half22float2(*(__half2*)&r.x);
            float2 h2 = __half22float2(*(__half2*)&r.y);
            acc.x += w * l2.x; acc.y += w * l2.y;
            acc.z += w * h2.x; acc.w += w * h2.y;
        }
    }
#pragma unroll
    for (int o = 16; o; o >>= 1) den_l += __shfl_xor_sync(0xFFFFFFFFu, den_l, o);
    float inv = 1.f / (den_l + w0);
    acc.x *= inv; acc.y *= inv; acc.z *= inv; acc.w *= inv;
    ((float4*)(g_z + (long)node * 128))[lane] = acc;
}

/* ---------------- fused ReLU + classifier (fp16 MMA) ---------------- */
#define CW_ENT (8 * 32 * 10)   /* uint2 = 20480 B */
__global__ void __launch_bounds__(512, 1)
k_cls(const float* __restrict__ cls_w, const float* __restrict__ cls_b,
      const float* __restrict__ gat_b, float* __restrict__ out) {
    extern __shared__ unsigned smu[];
    uint2* Wf = (uint2*)smu;              /* [k16][lane][n8(+pad)] */
    float* Cb = (float*)(Wf + CW_ENT);
    float* Gb = Cb + 64;
    const int tid = threadIdx.x;

    for (int i = tid; i < CW_ENT; i += 512) {
        int n8 = i % 10;
        int lane = (i / 10) & 31;
        int k16 = i / 320;
        uint2 v = make_uint2(0u, 0u);
        if (n8 < 8) {
            int n = n8 * 8 + (lane >> 2);
            int k0 = k16 * 16 + 2 * (lane & 3);
            const float* wr = cls_w + n * 128;
            v = make_uint2(h2pk(wr[k0], wr[k0 + 1]), h2pk(wr[k0 + 8], wr[k0 + 9]));
        }
        Wf[i] = v;
    }
    if (tid < 64) Cb[tid] = cls_b[tid];
    if (tid < 128) Gb[tid] = gat_b[tid];
    __syncthreads();

    const int warp = tid >> 5, lane = tid & 31;
    const int grp = lane >> 2, tg = lane & 3;
    const int nwarps = gridDim.x * 16;

    for (int rg = blockIdx.x * 16 + warp; rg < N_NODES / 16; rg += nwarps) {
        const int node0 = rg * 16 + grp, node1 = node0 + 8;
        const float* r0 = g_z + (long)node0 * 128;
        const float* r1 = g_z + (long)node1 * 128;

        unsigned a[8][4];
#pragma unroll
        for (int s = 0; s < 8; s++) {
            int k0 = s * 16 + 2 * tg;
            float2 gb0 = *(float2*)&Gb[k0];
            float2 gb1 = *(float2*)&Gb[k0 + 8];
            float2 v;
            v = __ldg((const float2*)(r0 + k0));
            a[s][0] = h2pk(fmaxf(v.x + gb0.x, 0.f), fmaxf(v.y + gb0.y, 0.f));
            v = __ldg((const float2*)(r1 + k0));
            a[s][1] = h2pk(fmaxf(v.x + gb0.x, 0.f), fmaxf(v.y + gb0.y, 0.f));
            v = __ldg((const float2*)(r0 + k0 + 8));
            a[s][2] = h2pk(fmaxf(v.x + gb1.x, 0.f), fmaxf(v.y + gb1.y, 0.f));
            v = __ldg((const float2*)(r1 + k0 + 8));
            a[s][3] = h2pk(fmaxf(v.x + gb1.x, 0.f), fmaxf(v.y + gb1.y, 0.f));
        }

        float acc[8][4];
#pragma unroll
        for (int q = 0; q < 8; q++)
#pragma unroll
            for (int i = 0; i < 4; i++) acc[q][i] = 0.f;

#pragma unroll
        for (int k16 = 0; k16 < 8; k16++) {
            const uint4* wp = (const uint4*)(Wf + (k16 * 32 + lane) * 10);
            uint4 wa = wp[0], wb = wp[1], wc = wp[2], wd = wp[3];
            mma16(acc[0], a[k16][0], a[k16][1], a[k16][2], a[k16][3], wa.x, wa.y);
            mma16(acc[1], a[k16][0], a[k16][1], a[k16][2], a[k16][3], wa.z, wa.w);
            mma16(acc[2], a[k16][0], a[k16][1], a[k16][2], a[k16][3], wb.x, wb.y);
            mma16(acc[3], a[k16][0], a[k16][1], a[k16][2], a[k16][3], wb.z, wb.w);
            mma16(acc[4], a[k16][0], a[k16][1], a[k16][2], a[k16][3], wc.x, wc.y);
            mma16(acc[5], a[k16][0], a[k16][1], a[k16][2], a[k16][3], wc.z, wc.w);
            mma16(acc[6], a[k16][0], a[k16][1], a[k16][2], a[k16][3], wd.x, wd.y);
            mma16(acc[7], a[k16][0], a[k16][1], a[k16][2], a[k16][3], wd.z, wd.w);
        }
#pragma unroll
        for (int n8 = 0; n8 < 8; n8++) {
            int col = n8 * 8 + 2 * tg;
            float b0 = Cb[col], b1 = Cb[col + 1];
            *(float2*)&out[(long)node0 * 64 + col] =
                make_float2(acc[n8][0] + b0, acc[n8][1] + b1);
            *(float2*)&out[(long)node1 * 64 + col] =
                make_float2(acc[n8][2] + b0, acc[n8][3] + b1);
        }
    }
}

/* ---------------- launch ----------------
 * Fork-join: CSR build overlapped on a side stream; joined before k_agg.
 * Host issue order keeps k_grux as the 4th kernel for the ncu window.
 */
extern "C" void kernel_launch(void* const* d_in, const int* in_sizes, int n_in,
                              void* d_out, int out_size) {
    const int*   src    = (const int*)  d_in[0];
    const int*   dst    = (const int*)  d_in[1];
    const int*   t      = (const int*)  d_in[2];
    const float* msg    = (const float*)d_in[3];
    const int*   sei    = (const int*)  d_in[4];
    const float* time_w = (const float*)d_in[5];
    const float* time_b = (const float*)d_in[6];
    const float* w_ih   = (const float*)d_in[7];
    /* d_in[8] = gru_w_hh: unused (memory == 0 at update time) */
    const float* b_ih   = (const float*)d_in[9];
    const float* b_hh   = (const float*)d_in[10];
    const float* gat_w  = (const float*)d_in[11];
    const float* att_s  = (const float*)d_in[12];
    const float* att_d  = (const float*)d_in[13];
    const float* gat_b  = (const float*)d_in[14];
    const float* cls_w  = (const float*)d_in[15];
    const float* cls_b  = (const float*)d_in[16];
    float* out = (float*)d_out;
    const int* es = sei;
    const int* ed = sei + N_SEDGE;
    (void)in_sizes; (void)n_in; (void)out_size;

    static cudaStream_t s1 = 0;
    static cudaEvent_t evRoot = 0, evSide = 0;
    static int ok = -1;
    if (ok < 0) {
        ok = 1;
        if (cudaStreamCreateWithFlags(&s1, cudaStreamNonBlocking) != cudaSuccess) ok = 0;
        if (ok && cudaEventCreateWithFlags(&evRoot, cudaEventDisableTiming) != cudaSuccess) ok = 0;
        if (ok && cudaEventCreateWithFlags(&evSide, cudaEventDisableTiming) != cudaSuccess) ok = 0;
    }
    cudaStream_t sC = ok ? s1 : 0;

    if (ok) { cudaEventRecord(evRoot, 0); cudaStreamWaitEvent(s1, evRoot, 0); }

    k_init_last<<<(N_NODES + 255) / 256, 256>>>();
    k_last     <<<(N_EV + 255) / 256, 256>>>(src, dst);
    k_init_cnt <<<(N_NODES + 255) / 256, 256, 0, sC>>>();

    {
        size_t smb = (size_t)(GRU_WENT + XW_ENT) * 8 + (512 + 64 + 256) * 4;
        cudaFuncSetAttribute(k_grux, cudaFuncAttributeMaxDynamicSharedMemorySize, (int)smb);
        k_grux<<<148, 512, smb>>>(t, msg, w_ih, b_ih, b_hh, time_w, time_b,
                                  gat_w, att_s, att_d);
    }

    k_count<<<(N_SEDGE + 255) / 256, 256, 0, sC>>>(ed);
    k_scanA<<<SNBLK, 256, 0, sC>>>();
    k_scanB<<<1, 128, 0, sC>>>();
    k_scanC<<<SNBLK, 256, 0, sC>>>();
    k_fill <<<(N_SEDGE + 255) / 256, 256, 0, sC>>>(es, ed);
    if (ok) cudaEventRecord(evSide, s1);

    if (ok) cudaStreamWaitEvent(0, evSide, 0);
    k_agg<<<(N_NODES * 32 + 255) / 256, 256>>>();
    {
        size_t smb = (size_t)CW_ENT * 8 + 192 * 4;
        cudaFuncSetAttribute(k_cls, cudaFuncAttributeMaxDynamicSharedMemorySize, (int)smb);
        k_cls<<<148, 512, smb>>>(cls_w, cls_b, gat_b, out);
    }
}